// round 12
// baseline (speedup 1.0000x reference)
#include <cuda_runtime.h>
#include <cuda_fp16.h>
#include <cstdint>

#define T_STEPS 2048
#define OBS 512
#define MLPD 1024
#define HD 1024
#define ACTD 16
#define SCAN_BLOCKS 128

// ---------------- device scratch (no allocations allowed) ----------------
__device__ float g_preB[MLPD];
__device__ float g_p1B[MLPD];
__device__ float g_p2B[MLPD];
__device__ float g_p3W[ACTD * MLPD];
__device__ float g_p3B[ACTD];
__device__ float g_ig[(size_t)T_STEPS * 3 * HD];
__device__ float g_states[(size_t)T_STEPS * HD];
__device__ float g_y2[T_STEPS * MLPD];
__device__ __half g_xh[T_STEPS * OBS],  g_xl[T_STEPS * OBS];
__device__ __half g_preWh[MLPD * OBS],  g_preWl[MLPD * OBS];
__device__ __half g_wihh[3 * HD * MLPD], g_wihl[3 * HD * MLPD];
__device__ __half g_p1Wh[MLPD * HD],    g_p1Wl[MLPD * HD];
__device__ __half g_p2Wh[MLPD * MLPD],  g_p2Wl[MLPD * MLPD];
__device__ __half g_zh[T_STEPS * MLPD], g_zl[T_STEPS * MLPD];
__device__ __half g_sth[(size_t)T_STEPS * HD], g_stl[(size_t)T_STEPS * HD];
__device__ __half g_y1h[T_STEPS * MLPD], g_y1l[T_STEPS * MLPD];
__device__ unsigned g_bar;
__device__ int g_order[T_STEPS];
__device__ int g_off[T_STEPS + 1];
__device__ int g_kmax;

// ---------------- threefry2x32 (matches JAX) ----------------
#define TF_ROUND(x0, x1, R) { x0 += x1; x1 = (x1 << R) | (x1 >> (32 - R)); x1 ^= x0; }

__host__ __device__ inline void tf_block(unsigned k0, unsigned k1, unsigned &x0, unsigned &x1) {
    unsigned ks2 = k0 ^ k1 ^ 0x1BD11BDAu;
    x0 += k0; x1 += k1;
    TF_ROUND(x0, x1, 13) TF_ROUND(x0, x1, 15) TF_ROUND(x0, x1, 26) TF_ROUND(x0, x1, 6)
    x0 += k1; x1 += ks2 + 1u;
    TF_ROUND(x0, x1, 17) TF_ROUND(x0, x1, 29) TF_ROUND(x0, x1, 16) TF_ROUND(x0, x1, 24)
    x0 += ks2; x1 += k0 + 2u;
    TF_ROUND(x0, x1, 13) TF_ROUND(x0, x1, 15) TF_ROUND(x0, x1, 26) TF_ROUND(x0, x1, 6)
    x0 += k0; x1 += k1 + 3u;
    TF_ROUND(x0, x1, 17) TF_ROUND(x0, x1, 29) TF_ROUND(x0, x1, 16) TF_ROUND(x0, x1, 24)
    x0 += k1; x1 += ks2 + 4u;
    TF_ROUND(x0, x1, 13) TF_ROUND(x0, x1, 15) TF_ROUND(x0, x1, 26) TF_ROUND(x0, x1, 6)
    x0 += ks2; x1 += k0 + 5u;
}

// XLA f32 erf_inv (Giles)
__device__ inline float xla_erfinv(float x) {
    float w = -log1pf(-x * x);
    float p;
    if (w < 5.0f) {
        w -= 2.5f;
        p = 2.81022636e-08f;
        p = fmaf(p, w, 3.43273939e-07f);
        p = fmaf(p, w, -3.5233877e-06f);
        p = fmaf(p, w, -4.39150654e-06f);
        p = fmaf(p, w, 0.00021858087f);
        p = fmaf(p, w, -0.00125372503f);
        p = fmaf(p, w, -0.00417768164f);
        p = fmaf(p, w, 0.246640727f);
        p = fmaf(p, w, 1.50140941f);
    } else {
        w = sqrtf(w) - 3.0f;
        p = -0.000200214257f;
        p = fmaf(p, w, 0.000100950558f);
        p = fmaf(p, w, 0.00134934322f);
        p = fmaf(p, w, -0.00367342844f);
        p = fmaf(p, w, 0.00573950773f);
        p = fmaf(p, w, -0.0076224613f);
        p = fmaf(p, w, 0.00943887047f);
        p = fmaf(p, w, 1.00167406f);
        p = fmaf(p, w, 2.83297682f);
    }
    return p * x;
}

__device__ inline float bits_to_normal(unsigned b) {
    float u1 = __uint_as_float((b >> 9) | 0x3f800000u) - 1.0f;
    float v = fmaf(u1, 1.99999994f, -0.99999994f);
    v = fmaxf(v, -0.99999994f);
    return 1.41421356f * xla_erfinv(v);
}

// Partitionable threefry: bits[i] = x0^x1 of block with counter (0, i)
__global__ void gen_noisy_kernel(const float* __restrict__ wm, const float* __restrict__ ws,
                                 float* __restrict__ dst, int n, unsigned k0, unsigned k1) {
    int i = blockIdx.x * blockDim.x + threadIdx.x;
    if (i >= n) return;
    unsigned x0 = 0u, x1 = (unsigned)i;
    tf_block(k0, k1, x0, x1);
    dst[i] = fmaf(ws[i], bits_to_normal(x0 ^ x1), wm[i]);
}

// noisy weights straight to fp16 hi/lo
__global__ void gen_noisy_w_kernel(const float* __restrict__ wm, const float* __restrict__ ws,
                                   __half* __restrict__ hi, __half* __restrict__ lo,
                                   int n, unsigned k0, unsigned k1) {
    int i = blockIdx.x * blockDim.x + threadIdx.x;
    if (i >= n) return;
    unsigned x0 = 0u, x1 = (unsigned)i;
    tf_block(k0, k1, x0, x1);
    float v = fmaf(ws[i], bits_to_normal(x0 ^ x1), wm[i]);
    __half h = __float2half_rn(v);
    hi[i] = h;
    lo[i] = __float2half_rn(v - __half2float(h));
}

// ---------------- activations ----------------
__device__ inline float mishf(float x) {
    float sp = fmaxf(x, 0.0f) + log1pf(expf(-fabsf(x)));
    return x * tanhf(sp);
}
__device__ inline float sigmoidf_(float x) { return 1.0f / (1.0f + expf(-x)); }

__device__ __forceinline__ uint32_t h2u(__half2 v) {
    return *reinterpret_cast<uint32_t*>(&v);
}

// ---------------- fp32 -> fp16 hi/lo split (n4 = n/4) ----------------
__global__ void conv_split_kernel(const float* __restrict__ src,
                                  __half* __restrict__ hi,
                                  __half* __restrict__ lo, int n4) {
    int i = blockIdx.x * blockDim.x + threadIdx.x;
    if (i >= n4) return;
    float4 v = ((const float4*)src)[i];
    __half2 h0, h1, l0, l1;
    h0.x = __float2half_rn(v.x); h0.y = __float2half_rn(v.y);
    h1.x = __float2half_rn(v.z); h1.y = __float2half_rn(v.w);
    l0.x = __float2half_rn(v.x - __half2float(h0.x));
    l0.y = __float2half_rn(v.y - __half2float(h0.y));
    l1.x = __float2half_rn(v.z - __half2float(h1.x));
    l1.y = __float2half_rn(v.w - __half2float(h1.y));
    ((uint2*)hi)[i] = make_uint2(h2u(h0), h2u(h1));
    ((uint2*)lo)[i] = make_uint2(h2u(l0), h2u(l1));
}

// ---------------- mma / ldmatrix / cp.async wrappers ----------------
__device__ __forceinline__ void mma16816(float* c, const uint32_t* a, const uint32_t* b) {
    asm volatile(
        "mma.sync.aligned.m16n8k16.row.col.f32.f16.f16.f32 "
        "{%0,%1,%2,%3}, {%4,%5,%6,%7}, {%8,%9}, {%0,%1,%2,%3};\n"
        : "+f"(c[0]), "+f"(c[1]), "+f"(c[2]), "+f"(c[3])
        : "r"(a[0]), "r"(a[1]), "r"(a[2]), "r"(a[3]), "r"(b[0]), "r"(b[1]));
}
__device__ __forceinline__ void mma16816h(uint32_t* c, const uint32_t* a, const uint32_t* b) {
    asm volatile(
        "mma.sync.aligned.m16n8k16.row.col.f16.f16.f16.f16 "
        "{%0,%1}, {%2,%3,%4,%5}, {%6,%7}, {%0,%1};\n"
        : "+r"(c[0]), "+r"(c[1])
        : "r"(a[0]), "r"(a[1]), "r"(a[2]), "r"(a[3]), "r"(b[0]), "r"(b[1]));
}
__device__ __forceinline__ void ldsm4(uint32_t& r0, uint32_t& r1, uint32_t& r2, uint32_t& r3,
                                      uint32_t addr) {
    asm volatile("ldmatrix.sync.aligned.m8n8.x4.shared.b16 {%0,%1,%2,%3}, [%4];"
                 : "=r"(r0), "=r"(r1), "=r"(r2), "=r"(r3) : "r"(addr));
}
__device__ __forceinline__ uint32_t smem_u32(const void* p) {
    uint32_t a;
    asm("{ .reg .u64 t; cvta.to.shared.u64 t, %1; cvt.u32.u64 %0, t; }" : "=r"(a) : "l"(p));
    return a;
}
__device__ __forceinline__ void cp16(uint32_t saddr, const void* gptr) {
    asm volatile("cp.async.cg.shared.global [%0], [%1], 16;" :: "r"(saddr), "l"(gptr));
}
__device__ __forceinline__ void cp_commit() {
    asm volatile("cp.async.commit_group;" ::: "memory");
}
__device__ __forceinline__ void cp_wait1() {
    asm volatile("cp.async.wait_group 1;" ::: "memory");
}
__device__ __forceinline__ void cp_wait0() {
    asm volatile("cp.async.wait_group 0;" ::: "memory");
}

// ============ split-fp16 tensor-core GEMM: C[M,N] = A[M,K] @ B[N,K]^T + bias ============
// CTA tile 64(M)x128(N), 8 warps (2m x 4n), warp tile 32x32, k-chunk 32,
// cp.async 2-stage double buffer, 2 CTAs/SM. Row pitch 40 halves (80B).
// Main term f32-accum; corrections (Al*Bh + Ah*Bl) in f16-accum (2x rate).
#define PADE 40
#define OFF_AH 0
#define OFF_AL (64 * PADE)
#define OFF_BH (2 * 64 * PADE)
#define OFF_BL (2 * 64 * PADE + 128 * PADE)
#define BUFE (2 * 64 * PADE + 2 * 128 * PADE)
#define MMA_SMEM_BYTES (2 * BUFE * 2)

__global__ __launch_bounds__(256, 2) void mma_gemm_kernel(
    const __half* __restrict__ Ah, const __half* __restrict__ Al,
    const __half* __restrict__ Bh, const __half* __restrict__ Bl,
    const float* __restrict__ bias, float* __restrict__ C,
    __half* __restrict__ Ch, __half* __restrict__ Cl,
    int M, int N, int K, int act, int osplit) {
    extern __shared__ __half smb[];
    const uint32_t sbase = smem_u32(smb);
    const int tid = threadIdx.x;
    const int wid = tid >> 5, lane = tid & 31;
    const int r4 = lane >> 2, lq = lane & 3;
    const int m0 = blockIdx.y * 64, n0 = blockIdx.x * 128;
    const int wm = (wid & 1) * 32, wn = (wid >> 1) * 32;

    const int aro = lane & 15, ako = (lane >> 4) << 3;
    const int bro = (lane & 7) + ((lane >> 4) << 3), bko = ((lane >> 3) & 1) << 3;

    float acc[2][4][4] = {};
    uint32_t corr[2][4][2] = {};
    const int nch = K >> 5;

    const int ld_r = tid >> 2, ld_q = tid & 3;
    const uint32_t ld_e = (uint32_t)(ld_r * PADE + ld_q * 8) * 2;

    {
#pragma unroll
        for (int c = 0; c < 2; c++) {
            if (c >= nch) break;
            const int k0 = c << 5;
            const uint32_t bb = sbase + (uint32_t)((c & 1) * BUFE * 2);
            // A: 64 rows, one 16B per thread per tensor
            {
                size_t goA = (size_t)(m0 + ld_r) * K + k0 + ld_q * 8;
                cp16(bb + OFF_AH * 2 + ld_e, Ah + goA);
                cp16(bb + OFF_AL * 2 + ld_e, Al + goA);
            }
            // B: 128 rows, two 16B per thread per tensor
#pragma unroll
            for (int q = 0; q < 2; q++) {
                int r = ld_r + 64 * q;
                uint32_t e = ld_e + (uint32_t)(64 * q * PADE) * 2;
                size_t goB = (size_t)(n0 + r) * K + k0 + ld_q * 8;
                cp16(bb + OFF_BH * 2 + e, Bh + goB);
                cp16(bb + OFF_BL * 2 + e, Bl + goB);
            }
            cp_commit();
        }
    }

    for (int c = 0; c < nch; c++) {
        if (c + 1 < nch) cp_wait1(); else cp_wait0();
        __syncthreads();

        const uint32_t bb = sbase + (uint32_t)((c & 1) * BUFE * 2);
#pragma unroll
        for (int ks = 0; ks < 2; ks++) {
            uint32_t ahf[2][4], alf[2][4], bhf[4][2], blf[4][2];
#pragma unroll
            for (int am = 0; am < 2; am++) {
                uint32_t ar = (uint32_t)((wm + am * 16 + aro) * PADE + ks * 16 + ako) * 2;
                ldsm4(ahf[am][0], ahf[am][1], ahf[am][2], ahf[am][3], bb + OFF_AH * 2 + ar);
                ldsm4(alf[am][0], alf[am][1], alf[am][2], alf[am][3], bb + OFF_AL * 2 + ar);
            }
#pragma unroll
            for (int nb = 0; nb < 2; nb++) {
                uint32_t br = (uint32_t)((wn + nb * 16 + bro) * PADE + ks * 16 + bko) * 2;
                ldsm4(bhf[nb * 2][0], bhf[nb * 2][1], bhf[nb * 2 + 1][0], bhf[nb * 2 + 1][1],
                      bb + OFF_BH * 2 + br);
                ldsm4(blf[nb * 2][0], blf[nb * 2][1], blf[nb * 2 + 1][0], blf[nb * 2 + 1][1],
                      bb + OFF_BL * 2 + br);
            }
#pragma unroll
            for (int am = 0; am < 2; am++)
#pragma unroll
                for (int bn = 0; bn < 4; bn++) {
                    mma16816(acc[am][bn], ahf[am], bhf[bn]);
                    mma16816h(corr[am][bn], alf[am], bhf[bn]);
                    mma16816h(corr[am][bn], ahf[am], blf[bn]);
                }
        }
        __syncthreads();

        if (c + 2 < nch) {
            const int k0 = (c + 2) << 5;
            const uint32_t nb = sbase + (uint32_t)(((c + 2) & 1) * BUFE * 2);
            {
                size_t goA = (size_t)(m0 + ld_r) * K + k0 + ld_q * 8;
                cp16(nb + OFF_AH * 2 + ld_e, Ah + goA);
                cp16(nb + OFF_AL * 2 + ld_e, Al + goA);
            }
#pragma unroll
            for (int q = 0; q < 2; q++) {
                int r = ld_r + 64 * q;
                uint32_t e = ld_e + (uint32_t)(64 * q * PADE) * 2;
                size_t goB = (size_t)(n0 + r) * K + k0 + ld_q * 8;
                cp16(nb + OFF_BH * 2 + e, Bh + goB);
                cp16(nb + OFF_BL * 2 + e, Bl + goB);
            }
            cp_commit();
        }
    }

#pragma unroll
    for (int am = 0; am < 2; am++) {
        const int row = m0 + wm + am * 16 + r4;
#pragma unroll
        for (int bn = 0; bn < 4; bn++) {
            const int col = n0 + wn + bn * 8 + 2 * lq;
            const float b0 = bias[col], b1 = bias[col + 1];
            float2 c01 = __half22float2(*reinterpret_cast<__half2*>(&corr[am][bn][0]));
            float2 c23 = __half22float2(*reinterpret_cast<__half2*>(&corr[am][bn][1]));
            float v0 = acc[am][bn][0] + c01.x + b0, v1 = acc[am][bn][1] + c01.y + b1;
            float v2 = acc[am][bn][2] + c23.x + b0, v3 = acc[am][bn][3] + c23.y + b1;
            if (act) { v0 = mishf(v0); v1 = mishf(v1); v2 = mishf(v2); v3 = mishf(v3); }
            if (osplit) {
                __half2 h01, h23, l01, l23;
                h01.x = __float2half_rn(v0); h01.y = __float2half_rn(v1);
                h23.x = __float2half_rn(v2); h23.y = __float2half_rn(v3);
                l01.x = __float2half_rn(v0 - __half2float(h01.x));
                l01.y = __float2half_rn(v1 - __half2float(h01.y));
                l23.x = __float2half_rn(v2 - __half2float(h23.x));
                l23.y = __float2half_rn(v3 - __half2float(h23.y));
                *(uint32_t*)(Ch + (size_t)row * N + col) = h2u(h01);
                *(uint32_t*)(Cl + (size_t)row * N + col) = h2u(l01);
                *(uint32_t*)(Ch + (size_t)(row + 8) * N + col) = h2u(h23);
                *(uint32_t*)(Cl + (size_t)(row + 8) * N + col) = h2u(l23);
            } else {
                *(float2*)(C + (size_t)row * N + col) = make_float2(v0, v1);
                *(float2*)(C + (size_t)(row + 8) * N + col) = make_float2(v2, v3);
            }
        }
    }
}

// ---------------- small SGEMM (p3, N=16) ----------------
__global__ __launch_bounds__(256) void sgemm64_kernel(
    const float* __restrict__ A, const float* __restrict__ B,
    const float* __restrict__ bias, float* __restrict__ C,
    int M, int N, int K) {
    __shared__ float As[16][64];
    __shared__ float Bs[16][64];
    const int m0 = blockIdx.y * 64;
    const int n0 = blockIdx.x * 64;
    const int tid = threadIdx.x;
    const int tx = tid & 15, ty = tid >> 4;
    const int lr = tid >> 2, lq = tid & 3;
    float acc[4][4] = {};
    for (int k0 = 0; k0 < K; k0 += 16) {
        float4 a4 = *(const float4*)(A + (size_t)(m0 + lr) * K + k0 + lq * 4);
        As[lq * 4 + 0][lr] = a4.x; As[lq * 4 + 1][lr] = a4.y;
        As[lq * 4 + 2][lr] = a4.z; As[lq * 4 + 3][lr] = a4.w;
        float4 b4 = make_float4(0.f, 0.f, 0.f, 0.f);
        if (n0 + lr < N) b4 = *(const float4*)(B + (size_t)(n0 + lr) * K + k0 + lq * 4);
        Bs[lq * 4 + 0][lr] = b4.x; Bs[lq * 4 + 1][lr] = b4.y;
        Bs[lq * 4 + 2][lr] = b4.z; Bs[lq * 4 + 3][lr] = b4.w;
        __syncthreads();
#pragma unroll
        for (int k = 0; k < 16; k++) {
            float4 av = *(const float4*)(&As[k][ty * 4]);
            float4 bv = *(const float4*)(&Bs[k][tx * 4]);
            float avs[4] = {av.x, av.y, av.z, av.w};
            float bvs[4] = {bv.x, bv.y, bv.z, bv.w};
#pragma unroll
            for (int i = 0; i < 4; i++)
#pragma unroll
                for (int jj = 0; jj < 4; jj++)
                    acc[i][jj] = fmaf(avs[i], bvs[jj], acc[i][jj]);
        }
        __syncthreads();
    }
#pragma unroll
    for (int i = 0; i < 4; i++) {
        int m = m0 + ty * 4 + i;
#pragma unroll
        for (int jj = 0; jj < 4; jj++) {
            int n = n0 + tx * 4 + jj;
            if (n < N) C[(size_t)m * N + n] = acc[i][jj] + (bias ? bias[n] : 0.0f);
        }
    }
}

// ---------------- prep: bucket timesteps by age within reset-segment ----------------
__global__ __launch_bounds__(1024) void prep_kernel(const int* __restrict__ start) {
    __shared__ int sa[2048], sb_[2048], sc[2048];
    __shared__ int skmax;
    const int tid = threadIdx.x;
    const int t0 = tid, t1 = tid + 1024;
    if (tid == 0) { g_bar = 0u; skmax = 0; }
    sa[t0] = start[t0] ? t0 : -1;
    sa[t1] = start[t1] ? t1 : -1;
    __syncthreads();
    int* src = sa; int* dst = sb_;
    for (int d = 1; d < 2048; d <<= 1) {
        int v0 = src[t0]; if (t0 >= d) v0 = max(v0, src[t0 - d]);
        int v1 = src[t1]; if (t1 >= d) v1 = max(v1, src[t1 - d]);
        dst[t0] = v0; dst[t1] = v1;
        __syncthreads();
        int* tmp = src; src = dst; dst = tmp;
    }
    int r0v = src[t0], r1v = src[t1];
    int age0 = (r0v < 0) ? t0 : t0 - r0v;
    int age1 = (r1v < 0) ? t1 : t1 - r1v;
    __syncthreads();
    sc[t0] = 0; sc[t1] = 0;
    __syncthreads();
    atomicAdd(&sc[age0], 1);
    atomicAdd(&sc[age1], 1);
    atomicMax(&skmax, max(age0, age1) + 1);
    __syncthreads();
    sa[t0] = sc[t0]; sa[t1] = sc[t1];
    __syncthreads();
    src = sa; dst = sb_;
    for (int d = 1; d < 2048; d <<= 1) {
        int v0 = src[t0]; if (t0 >= d) v0 += src[t0 - d];
        int v1 = src[t1]; if (t1 >= d) v1 += src[t1 - d];
        dst[t0] = v0; dst[t1] = v1;
        __syncthreads();
        int* tmp = src; src = dst; dst = tmp;
    }
    if (tid == 0) { g_off[0] = 0; g_kmax = skmax; }
    g_off[t0 + 1] = src[t0];
    g_off[t1 + 1] = src[t1];
    sc[t0] = 0; sc[t1] = 0;
    __syncthreads();
    int base0 = (age0 == 0) ? 0 : src[age0 - 1];
    g_order[base0 + atomicAdd(&sc[age0], 1)] = t0;
    int base1 = (age1 == 0) ? 0 : src[age1 - 1];
    g_order[base1 + atomicAdd(&sc[age1], 1)] = t1;
}

// ---------------- grid barrier ----------------
__device__ inline void grid_bar(unsigned* barp, unsigned target) {
    __syncthreads();
    if (threadIdx.x == 0) {
        asm volatile("red.release.gpu.global.add.u32 [%0], %1;" :: "l"(barp), "r"(1u) : "memory");
        unsigned v;
        do {
            asm volatile("ld.acquire.gpu.global.u32 %0, [%1];" : "=r"(v) : "l"(barp) : "memory");
        } while (v < target);
    }
    __syncthreads();
}

__device__ __forceinline__ void store_state(int t, int j, float hnew, float* out) {
    g_states[(size_t)t * HD + j] = hnew;
    __half h = __float2half_rn(hnew);
    g_sth[(size_t)t * HD + j] = h;
    g_stl[(size_t)t * HD + j] = __float2half_rn(hnew - __half2float(h));
    if (t == T_STEPS - 1) out[(size_t)T_STEPS * ACTD + j] = hnew;
}

// ---------------- segment-parallel GRU scan, register-resident whh, 2 rows/iter ----------------
__global__ __launch_bounds__(256, 1) void scan_kernel(
    const float* __restrict__ whh, const float* __restrict__ gbn,
    const int* __restrict__ start, const float* __restrict__ state,
    float* __restrict__ out) {
    __shared__ float sH[2][HD];
    const int tid = threadIdx.x;
    const int w = tid >> 5, lane = tid & 31;
    const int j = blockIdx.x * 8 + w;

    const float4* w4 = (const float4*)whh;
    float4 wr[8], wz[8], wn[8];
#pragma unroll
    for (int q = 0; q < 8; q++) {
        wr[q] = w4[(size_t)(0 * HD + j) * 256 + lane + 32 * q];
        wz[q] = w4[(size_t)(1 * HD + j) * 256 + lane + 32 * q];
        wn[q] = w4[(size_t)(2 * HD + j) * 256 + lane + 32 * q];
    }
    const float bnj = gbn[j];
    float4* sH0s = (float4*)sH[0];
    float4* sH1s = (float4*)sH[1];
    const float4* sH0 = (const float4*)sH[0];
    const float4* sH1 = (const float4*)sH[1];
    unsigned* barp = &g_bar;
    const int kmax = g_kmax;
    const int s0 = start[0];
    unsigned epoch = 0;

    if (s0 == 0) {
        sH0s[tid] = ((const float4*)state)[tid];
        __syncthreads();
        float ir = 0.f, iz = 0.f, inn = 0.f;
        if (lane == 0) { ir = g_ig[j]; iz = g_ig[HD + j]; inn = g_ig[2 * HD + j]; }
        float aR = 0.f, aZ = 0.f, aN = 0.f;
#pragma unroll
        for (int q = 0; q < 8; q++) {
            float4 h4 = sH0[lane + 32 * q];
            aR = fmaf(h4.x, wr[q].x, fmaf(h4.y, wr[q].y, fmaf(h4.z, wr[q].z, fmaf(h4.w, wr[q].w, aR))));
            aZ = fmaf(h4.x, wz[q].x, fmaf(h4.y, wz[q].y, fmaf(h4.z, wz[q].z, fmaf(h4.w, wz[q].w, aZ))));
            aN = fmaf(h4.x, wn[q].x, fmaf(h4.y, wn[q].y, fmaf(h4.z, wn[q].z, fmaf(h4.w, wn[q].w, aN))));
        }
#pragma unroll
        for (int off = 16; off; off >>= 1) {
            aR += __shfl_xor_sync(0xffffffffu, aR, off);
            aZ += __shfl_xor_sync(0xffffffffu, aZ, off);
            aN += __shfl_xor_sync(0xffffffffu, aN, off);
        }
        if (lane == 0) {
            float rv = sigmoidf_(ir + aR);
            float uv = sigmoidf_(iz + aZ);
            float nv = tanhf(inn + rv * (aN + bnj));
            float hin = sH[0][j];
            store_state(0, j, nv + uv * (hin - nv), out);
        }
        __syncthreads();
    }
    {
        const int beg = g_off[0], end = g_off[1];
        for (int r = beg + lane; r < end; r += 32) {
            const int t = g_order[r];
            if (t == 0 && s0 == 0) continue;
            const float* igt = g_ig + (size_t)t * (3 * HD);
            float rv = sigmoidf_(igt[j]);
            float uv = sigmoidf_(igt[HD + j]);
            float nv = tanhf(igt[2 * HD + j] + rv * bnj);
            store_state(t, j, nv - uv * nv, out);
        }
    }
    grid_bar(barp, (++epoch) * SCAN_BLOCKS);

    for (int k = 1; k < kmax; k++) {
        const int beg = g_off[k], end = g_off[k + 1];
        int r = beg;
        int tA = g_order[r];
        float4 nxtA = __ldcg((const float4*)(g_states + (size_t)(tA - 1) * HD) + tid);
        int tB = (r + 1 < end) ? g_order[r + 1] : -1;
        float4 nxtB = make_float4(0.f, 0.f, 0.f, 0.f);
        if (tB >= 0) nxtB = __ldcg((const float4*)(g_states + (size_t)(tB - 1) * HD) + tid);

        while (r < end) {
            const int curA = tA, curB = tB;
            sH0s[tid] = nxtA;
            if (curB >= 0) sH1s[tid] = nxtB;
            __syncthreads();

            const int rn = r + 2;
            if (rn < end) {
                tA = g_order[rn];
                nxtA = __ldcg((const float4*)(g_states + (size_t)(tA - 1) * HD) + tid);
            }
            if (rn + 1 < end) {
                tB = g_order[rn + 1];
                nxtB = __ldcg((const float4*)(g_states + (size_t)(tB - 1) * HD) + tid);
            } else {
                tB = -1;
            }

            float irA = 0.f, izA = 0.f, inA = 0.f, irB = 0.f, izB = 0.f, inB = 0.f;
            if (lane == 0) {
                const float* iga = g_ig + (size_t)curA * (3 * HD);
                irA = iga[j]; izA = iga[HD + j]; inA = iga[2 * HD + j];
                if (curB >= 0) {
                    const float* igb = g_ig + (size_t)curB * (3 * HD);
                    irB = igb[j]; izB = igb[HD + j]; inB = igb[2 * HD + j];
                }
            }

            float aR = 0.f, aZ = 0.f, aN = 0.f, bR = 0.f, bZ = 0.f, bN = 0.f;
#pragma unroll
            for (int q = 0; q < 8; q++) {
                const int c = lane + 32 * q;
                float4 hA = sH0[c];
                float4 hB = sH1[c];
                float4 r4v = wr[q], z4v = wz[q], n4v = wn[q];
                aR = fmaf(hA.x, r4v.x, fmaf(hA.y, r4v.y, fmaf(hA.z, r4v.z, fmaf(hA.w, r4v.w, aR))));
                bR = fmaf(hB.x, r4v.x, fmaf(hB.y, r4v.y, fmaf(hB.z, r4v.z, fmaf(hB.w, r4v.w, bR))));
                aZ = fmaf(hA.x, z4v.x, fmaf(hA.y, z4v.y, fmaf(hA.z, z4v.z, fmaf(hA.w, z4v.w, aZ))));
                bZ = fmaf(hB.x, z4v.x, fmaf(hB.y, z4v.y, fmaf(hB.z, z4v.z, fmaf(hB.w, z4v.w, bZ))));
                aN = fmaf(hA.x, n4v.x, fmaf(hA.y, n4v.y, fmaf(hA.z, n4v.z, fmaf(hA.w, n4v.w, aN))));
                bN = fmaf(hB.x, n4v.x, fmaf(hB.y, n4v.y, fmaf(hB.z, n4v.z, fmaf(hB.w, n4v.w, bN))));
            }
#pragma unroll
            for (int off = 16; off; off >>= 1) {
                aR += __shfl_xor_sync(0xffffffffu, aR, off);
                aZ += __shfl_xor_sync(0xffffffffu, aZ, off);
                aN += __shfl_xor_sync(0xffffffffu, aN, off);
                bR += __shfl_xor_sync(0xffffffffu, bR, off);
                bZ += __shfl_xor_sync(0xffffffffu, bZ, off);
                bN += __shfl_xor_sync(0xffffffffu, bN, off);
            }
            if (lane == 0) {
                {
                    float rv = sigmoidf_(irA + aR);
                    float uv = sigmoidf_(izA + aZ);
                    float nv = tanhf(inA + rv * (aN + bnj));
                    float hin = sH[0][j];
                    store_state(curA, j, nv + uv * (hin - nv), out);
                }
                if (curB >= 0) {
                    float rv = sigmoidf_(irB + bR);
                    float uv = sigmoidf_(izB + bZ);
                    float nv = tanhf(inB + rv * (bN + bnj));
                    float hin = sH[1][j];
                    store_state(curB, j, nv + uv * (hin - nv), out);
                }
            }
            __syncthreads();
            r = rn;
        }
        grid_bar(barp, (++epoch) * SCAN_BLOCKS);
    }
}

// ---------------- launch ----------------
extern "C" void kernel_launch(void* const* d_in, const int* in_sizes, int n_in,
                              void* d_out, int out_size) {
    (void)in_sizes; (void)n_in;
    const float* x      = (const float*)d_in[0];
    const float* state  = (const float*)d_in[1];
    const int*   start  = (const int*)d_in[2];
    const float* pre_wm = (const float*)d_in[4];
    const float* pre_ws = (const float*)d_in[5];
    const float* pre_bm = (const float*)d_in[6];
    const float* pre_bs = (const float*)d_in[7];
    const float* wih    = (const float*)d_in[8];
    const float* whh    = (const float*)d_in[9];
    const float* gru_b  = (const float*)d_in[10];
    const float* gru_bn = (const float*)d_in[11];
    const float* p1_wm  = (const float*)d_in[12];
    const float* p1_ws  = (const float*)d_in[13];
    const float* p1_bm  = (const float*)d_in[14];
    const float* p1_bs  = (const float*)d_in[15];
    const float* p2_wm  = (const float*)d_in[16];
    const float* p2_ws  = (const float*)d_in[17];
    const float* p2_bm  = (const float*)d_in[18];
    const float* p2_bs  = (const float*)d_in[19];
    const float* p3_wm  = (const float*)d_in[20];
    const float* p3_ws  = (const float*)d_in[21];
    const float* p3_bm  = (const float*)d_in[22];
    const float* p3_bs  = (const float*)d_in[23];
    float* out = (float*)d_out;
    (void)out_size;

    unsigned nk[8][2];
    for (int i = 0; i < 8; i++) {
        unsigned a = 0u, b = (unsigned)i;
        tf_block(0u, 7u, a, b);
        nk[i][0] = a; nk[i][1] = b;
    }

    float *preB, *p1B, *p2B, *p3W, *p3B, *ig, *states, *y2;
    __half *xh, *xl, *preWh, *preWl, *wihh, *wihl, *p1Wh, *p1Wl, *p2Wh, *p2Wl;
    __half *zh, *zl, *sth, *stl, *y1h, *y1l;
    cudaGetSymbolAddress((void**)&preB, g_preB);
    cudaGetSymbolAddress((void**)&p1B, g_p1B);
    cudaGetSymbolAddress((void**)&p2B, g_p2B);
    cudaGetSymbolAddress((void**)&p3W, g_p3W);
    cudaGetSymbolAddress((void**)&p3B, g_p3B);
    cudaGetSymbolAddress((void**)&ig, g_ig);
    cudaGetSymbolAddress((void**)&states, g_states);
    cudaGetSymbolAddress((void**)&y2, g_y2);
    cudaGetSymbolAddress((void**)&xh, g_xh);
    cudaGetSymbolAddress((void**)&xl, g_xl);
    cudaGetSymbolAddress((void**)&preWh, g_preWh);
    cudaGetSymbolAddress((void**)&preWl, g_preWl);
    cudaGetSymbolAddress((void**)&wihh, g_wihh);
    cudaGetSymbolAddress((void**)&wihl, g_wihl);
    cudaGetSymbolAddress((void**)&p1Wh, g_p1Wh);
    cudaGetSymbolAddress((void**)&p1Wl, g_p1Wl);
    cudaGetSymbolAddress((void**)&p2Wh, g_p2Wh);
    cudaGetSymbolAddress((void**)&p2Wl, g_p2Wl);
    cudaGetSymbolAddress((void**)&zh, g_zh);
    cudaGetSymbolAddress((void**)&zl, g_zl);
    cudaGetSymbolAddress((void**)&sth, g_sth);
    cudaGetSymbolAddress((void**)&stl, g_stl);
    cudaGetSymbolAddress((void**)&y1h, g_y1h);
    cudaGetSymbolAddress((void**)&y1l, g_y1l);

    cudaFuncSetAttribute(mma_gemm_kernel, cudaFuncAttributeMaxDynamicSharedMemorySize,
                         MMA_SMEM_BYTES);

    static cudaStream_t sB = nullptr;
    static cudaEvent_t evFork, evPre, evWih, evPrep, evP1, evP2, evP3;
    if (sB == nullptr) {
        cudaStreamCreateWithFlags(&sB, cudaStreamNonBlocking);
        cudaEventCreateWithFlags(&evFork, cudaEventDisableTiming);
        cudaEventCreateWithFlags(&evPre, cudaEventDisableTiming);
        cudaEventCreateWithFlags(&evWih, cudaEventDisableTiming);
        cudaEventCreateWithFlags(&evPrep, cudaEventDisableTiming);
        cudaEventCreateWithFlags(&evP1, cudaEventDisableTiming);
        cudaEventCreateWithFlags(&evP2, cudaEventDisableTiming);
        cudaEventCreateWithFlags(&evP3, cudaEventDisableTiming);
    }

    cudaEventRecord(evFork, 0);
    cudaStreamWaitEvent(sB, evFork, 0);

    // main #1: x split
    conv_split_kernel<<<(T_STEPS * OBS / 4 + 255) / 256, 256>>>(x, xh, xl, T_STEPS * OBS / 4);
    // side: pre noise
    { int n = MLPD * OBS; gen_noisy_w_kernel<<<(n + 255) / 256, 256, 0, sB>>>(pre_wm, pre_ws, preWh, preWl, n, nk[0][0], nk[0][1]); }
    { int n = MLPD;       gen_noisy_kernel<<<(n + 255) / 256, 256, 0, sB>>>(pre_bm, pre_bs, preB, n, nk[1][0], nk[1][1]); }
    cudaEventRecord(evPre, sB);

    // main: GEMM1 (launch #4 -> profiled)
    cudaStreamWaitEvent(0, evPre, 0);
    mma_gemm_kernel<<<dim3(MLPD / 128, T_STEPS / 64), 256, MMA_SMEM_BYTES>>>(
        xh, xl, preWh, preWl, preB, nullptr, zh, zl, T_STEPS, MLPD, OBS, 1, 1);

    // side: wih split (overlaps GEMM1)
    conv_split_kernel<<<(3 * HD * MLPD / 4 + 255) / 256, 256, 0, sB>>>(wih, wihh, wihl, 3 * HD * MLPD / 4);
    cudaEventRecord(evWih, sB);
    // side: prep
    prep_kernel<<<1, 1024, 0, sB>>>(start);
    cudaEventRecord(evPrep, sB);

    // main: GEMM2
    cudaStreamWaitEvent(0, evWih, 0);
    mma_gemm_kernel<<<dim3(3 * HD / 128, T_STEPS / 64), 256, MMA_SMEM_BYTES>>>(
        zh, zl, wihh, wihl, gru_b, ig, nullptr, nullptr, T_STEPS, 3 * HD, MLPD, 0, 0);

    // side: p1/p2/p3 noise (overlaps GEMM2 + scan)
    { int n = MLPD * HD;   gen_noisy_w_kernel<<<(n + 255) / 256, 256, 0, sB>>>(p1_wm, p1_ws, p1Wh, p1Wl, n, nk[2][0], nk[2][1]); }
    { int n = MLPD;        gen_noisy_kernel<<<(n + 255) / 256, 256, 0, sB>>>(p1_bm, p1_bs, p1B, n, nk[3][0], nk[3][1]); }
    cudaEventRecord(evP1, sB);
    { int n = MLPD * MLPD; gen_noisy_w_kernel<<<(n + 255) / 256, 256, 0, sB>>>(p2_wm, p2_ws, p2Wh, p2Wl, n, nk[4][0], nk[4][1]); }
    { int n = MLPD;        gen_noisy_kernel<<<(n + 255) / 256, 256, 0, sB>>>(p2_bm, p2_bs, p2B, n, nk[5][0], nk[5][1]); }
    cudaEventRecord(evP2, sB);
    { int n = ACTD * MLPD; gen_noisy_kernel<<<(n + 255) / 256, 256, 0, sB>>>(p3_wm, p3_ws, p3W, n, nk[6][0], nk[6][1]); }
    { int n = ACTD;        gen_noisy_kernel<<<(n + 255) / 256, 256, 0, sB>>>(p3_bm, p3_bs, p3B, n, nk[7][0], nk[7][1]); }
    cudaEventRecord(evP3, sB);

    // main: scan
    cudaStreamWaitEvent(0, evPrep, 0);
    scan_kernel<<<SCAN_BLOCKS, 256>>>(whh, gru_bn, start, state, out);

    // main: GEMM3
    cudaStreamWaitEvent(0, evP1, 0);
    mma_gemm_kernel<<<dim3(MLPD / 128, T_STEPS / 64), 256, MMA_SMEM_BYTES>>>(
        sth, stl, p1Wh, p1Wl, p1B, nullptr, y1h, y1l, T_STEPS, MLPD, HD, 1, 1);

    // main: GEMM4
    cudaStreamWaitEvent(0, evP2, 0);
    mma_gemm_kernel<<<dim3(MLPD / 128, T_STEPS / 64), 256, MMA_SMEM_BYTES>>>(
        y1h, y1l, p2Wh, p2Wl, p2B, y2, nullptr, nullptr, T_STEPS, MLPD, MLPD, 1, 0);

    // main: final layer -> d_out[0 : 2048*16]
    cudaStreamWaitEvent(0, evP3, 0);
    sgemm64_kernel<<<dim3(1, T_STEPS / 64), 256>>>(y2, p3W, p3B, out, T_STEPS, ACTD, MLPD);
}

// round 13
// speedup vs baseline: 1.2279x; 1.2279x over previous
#include <cuda_runtime.h>
#include <cuda_fp16.h>
#include <cstdint>

#define T_STEPS 2048
#define OBS 512
#define MLPD 1024
#define HD 1024
#define ACTD 16
#define SCAN_BLOCKS 128

// ---------------- device scratch (no allocations allowed) ----------------
__device__ float g_preB[MLPD];
__device__ float g_p1B[MLPD];
__device__ float g_p2B[MLPD];
__device__ float g_p3W[ACTD * MLPD];
__device__ float g_p3B[ACTD];
__device__ float g_ig[(size_t)T_STEPS * 3 * HD];
__device__ float g_states[(size_t)T_STEPS * HD];
__device__ float g_y2[T_STEPS * MLPD];
__device__ __half g_xh[T_STEPS * OBS],  g_xl[T_STEPS * OBS];
__device__ __half g_preWh[MLPD * OBS],  g_preWl[MLPD * OBS];
__device__ __half g_wihh[3 * HD * MLPD], g_wihl[3 * HD * MLPD];
__device__ __half g_p1Wh[MLPD * HD],    g_p1Wl[MLPD * HD];
__device__ __half g_p2Wh[MLPD * MLPD],  g_p2Wl[MLPD * MLPD];
__device__ __half g_zh[T_STEPS * MLPD], g_zl[T_STEPS * MLPD];
__device__ __half g_sth[(size_t)T_STEPS * HD], g_stl[(size_t)T_STEPS * HD];
__device__ __half g_y1h[T_STEPS * MLPD], g_y1l[T_STEPS * MLPD];
__device__ unsigned g_bar;
__device__ int g_order[T_STEPS];
__device__ int g_off[T_STEPS + 1];
__device__ int g_kmax;

// ---------------- threefry2x32 (matches JAX) ----------------
#define TF_ROUND(x0, x1, R) { x0 += x1; x1 = (x1 << R) | (x1 >> (32 - R)); x1 ^= x0; }

__host__ __device__ inline void tf_block(unsigned k0, unsigned k1, unsigned &x0, unsigned &x1) {
    unsigned ks2 = k0 ^ k1 ^ 0x1BD11BDAu;
    x0 += k0; x1 += k1;
    TF_ROUND(x0, x1, 13) TF_ROUND(x0, x1, 15) TF_ROUND(x0, x1, 26) TF_ROUND(x0, x1, 6)
    x0 += k1; x1 += ks2 + 1u;
    TF_ROUND(x0, x1, 17) TF_ROUND(x0, x1, 29) TF_ROUND(x0, x1, 16) TF_ROUND(x0, x1, 24)
    x0 += ks2; x1 += k0 + 2u;
    TF_ROUND(x0, x1, 13) TF_ROUND(x0, x1, 15) TF_ROUND(x0, x1, 26) TF_ROUND(x0, x1, 6)
    x0 += k0; x1 += k1 + 3u;
    TF_ROUND(x0, x1, 17) TF_ROUND(x0, x1, 29) TF_ROUND(x0, x1, 16) TF_ROUND(x0, x1, 24)
    x0 += k1; x1 += ks2 + 4u;
    TF_ROUND(x0, x1, 13) TF_ROUND(x0, x1, 15) TF_ROUND(x0, x1, 26) TF_ROUND(x0, x1, 6)
    x0 += ks2; x1 += k0 + 5u;
}

// XLA f32 erf_inv (Giles)
__device__ inline float xla_erfinv(float x) {
    float w = -log1pf(-x * x);
    float p;
    if (w < 5.0f) {
        w -= 2.5f;
        p = 2.81022636e-08f;
        p = fmaf(p, w, 3.43273939e-07f);
        p = fmaf(p, w, -3.5233877e-06f);
        p = fmaf(p, w, -4.39150654e-06f);
        p = fmaf(p, w, 0.00021858087f);
        p = fmaf(p, w, -0.00125372503f);
        p = fmaf(p, w, -0.00417768164f);
        p = fmaf(p, w, 0.246640727f);
        p = fmaf(p, w, 1.50140941f);
    } else {
        w = sqrtf(w) - 3.0f;
        p = -0.000200214257f;
        p = fmaf(p, w, 0.000100950558f);
        p = fmaf(p, w, 0.00134934322f);
        p = fmaf(p, w, -0.00367342844f);
        p = fmaf(p, w, 0.00573950773f);
        p = fmaf(p, w, -0.0076224613f);
        p = fmaf(p, w, 0.00943887047f);
        p = fmaf(p, w, 1.00167406f);
        p = fmaf(p, w, 2.83297682f);
    }
    return p * x;
}

__device__ inline float bits_to_normal(unsigned b) {
    float u1 = __uint_as_float((b >> 9) | 0x3f800000u) - 1.0f;
    float v = fmaf(u1, 1.99999994f, -0.99999994f);
    v = fmaxf(v, -0.99999994f);
    return 1.41421356f * xla_erfinv(v);
}

__device__ inline float tf_normal(unsigned k0, unsigned k1, unsigned i) {
    unsigned x0 = 0u, x1 = i;
    tf_block(k0, k1, x0, x1);
    return bits_to_normal(x0 ^ x1);
}

// noisy weights straight to fp16 hi/lo
__global__ void gen_noisy_w_kernel(const float* __restrict__ wm, const float* __restrict__ ws,
                                   __half* __restrict__ hi, __half* __restrict__ lo,
                                   int n, unsigned k0, unsigned k1) {
    int i = blockIdx.x * blockDim.x + threadIdx.x;
    if (i >= n) return;
    float v = fmaf(ws[i], tf_normal(k0, k1, (unsigned)i), wm[i]);
    __half h = __float2half_rn(v);
    hi[i] = h;
    lo[i] = __float2half_rn(v - __half2float(h));
}

// all small noisy tensors in one launch: p3W(16384), preB/p1B/p2B(1024 each), p3B(16)
__global__ void gen_small_kernel(
    const float* p3wm, const float* p3ws, float* p3w, unsigned kw0, unsigned kw1,
    const float* prebm, const float* prebs, float* preb, unsigned ka0, unsigned ka1,
    const float* p1bm, const float* p1bs, float* p1b, unsigned kb0, unsigned kb1,
    const float* p2bm, const float* p2bs, float* p2b, unsigned kc0, unsigned kc1,
    const float* p3bm, const float* p3bs, float* p3b, unsigned kd0, unsigned kd1) {
    int i = blockIdx.x * blockDim.x + threadIdx.x;
    if (i < 16384) {
        p3w[i] = fmaf(p3ws[i], tf_normal(kw0, kw1, (unsigned)i), p3wm[i]);
    } else if (i < 17408) {
        int l = i - 16384;
        preb[l] = fmaf(prebs[l], tf_normal(ka0, ka1, (unsigned)l), prebm[l]);
    } else if (i < 18432) {
        int l = i - 17408;
        p1b[l] = fmaf(p1bs[l], tf_normal(kb0, kb1, (unsigned)l), p1bm[l]);
    } else if (i < 19456) {
        int l = i - 18432;
        p2b[l] = fmaf(p2bs[l], tf_normal(kc0, kc1, (unsigned)l), p2bm[l]);
    } else if (i < 19472) {
        int l = i - 19456;
        p3b[l] = fmaf(p3bs[l], tf_normal(kd0, kd1, (unsigned)l), p3bm[l]);
    }
}

// ---------------- activations ----------------
__device__ inline float mishf(float x) {
    float sp = fmaxf(x, 0.0f) + log1pf(expf(-fabsf(x)));
    return x * tanhf(sp);
}
__device__ inline float sigmoidf_(float x) { return 1.0f / (1.0f + expf(-x)); }

__device__ __forceinline__ uint32_t h2u(__half2 v) {
    return *reinterpret_cast<uint32_t*>(&v);
}

// ---------------- fp32 -> fp16 hi/lo split (n4 = n/4) ----------------
__global__ void conv_split_kernel(const float* __restrict__ src,
                                  __half* __restrict__ hi,
                                  __half* __restrict__ lo, int n4) {
    int i = blockIdx.x * blockDim.x + threadIdx.x;
    if (i >= n4) return;
    float4 v = ((const float4*)src)[i];
    __half2 h0, h1, l0, l1;
    h0.x = __float2half_rn(v.x); h0.y = __float2half_rn(v.y);
    h1.x = __float2half_rn(v.z); h1.y = __float2half_rn(v.w);
    l0.x = __float2half_rn(v.x - __half2float(h0.x));
    l0.y = __float2half_rn(v.y - __half2float(h0.y));
    l1.x = __float2half_rn(v.z - __half2float(h1.x));
    l1.y = __float2half_rn(v.w - __half2float(h1.y));
    ((uint2*)hi)[i] = make_uint2(h2u(h0), h2u(h1));
    ((uint2*)lo)[i] = make_uint2(h2u(l0), h2u(l1));
}

// ---------------- mma / ldmatrix / cp.async wrappers ----------------
__device__ __forceinline__ void mma16816(float* c, const uint32_t* a, const uint32_t* b) {
    asm volatile(
        "mma.sync.aligned.m16n8k16.row.col.f32.f16.f16.f32 "
        "{%0,%1,%2,%3}, {%4,%5,%6,%7}, {%8,%9}, {%0,%1,%2,%3};\n"
        : "+f"(c[0]), "+f"(c[1]), "+f"(c[2]), "+f"(c[3])
        : "r"(a[0]), "r"(a[1]), "r"(a[2]), "r"(a[3]), "r"(b[0]), "r"(b[1]));
}
__device__ __forceinline__ void mma16816h(uint32_t* c, const uint32_t* a, const uint32_t* b) {
    asm volatile(
        "mma.sync.aligned.m16n8k16.row.col.f16.f16.f16.f16 "
        "{%0,%1}, {%2,%3,%4,%5}, {%6,%7}, {%0,%1};\n"
        : "+r"(c[0]), "+r"(c[1])
        : "r"(a[0]), "r"(a[1]), "r"(a[2]), "r"(a[3]), "r"(b[0]), "r"(b[1]));
}
__device__ __forceinline__ void ldsm4(uint32_t& r0, uint32_t& r1, uint32_t& r2, uint32_t& r3,
                                      uint32_t addr) {
    asm volatile("ldmatrix.sync.aligned.m8n8.x4.shared.b16 {%0,%1,%2,%3}, [%4];"
                 : "=r"(r0), "=r"(r1), "=r"(r2), "=r"(r3) : "r"(addr));
}
__device__ __forceinline__ uint32_t smem_u32(const void* p) {
    uint32_t a;
    asm("{ .reg .u64 t; cvta.to.shared.u64 t, %1; cvt.u32.u64 %0, t; }" : "=r"(a) : "l"(p));
    return a;
}
__device__ __forceinline__ void cp16(uint32_t saddr, const void* gptr) {
    asm volatile("cp.async.cg.shared.global [%0], [%1], 16;" :: "r"(saddr), "l"(gptr));
}
__device__ __forceinline__ void cp_commit() {
    asm volatile("cp.async.commit_group;" ::: "memory");
}
__device__ __forceinline__ void cp_wait1() {
    asm volatile("cp.async.wait_group 1;" ::: "memory");
}
__device__ __forceinline__ void cp_wait0() {
    asm volatile("cp.async.wait_group 0;" ::: "memory");
}

// ============ split-fp16 tensor-core GEMM (as R12): CTA 64x128, 8 warps 32x32 ============
#define PADE 40
#define OFF_AH 0
#define OFF_AL (64 * PADE)
#define OFF_BH (2 * 64 * PADE)
#define OFF_BL (2 * 64 * PADE + 128 * PADE)
#define BUFE (2 * 64 * PADE + 2 * 128 * PADE)
#define MMA_SMEM_BYTES (2 * BUFE * 2)

__global__ __launch_bounds__(256, 2) void mma_gemm_kernel(
    const __half* __restrict__ Ah, const __half* __restrict__ Al,
    const __half* __restrict__ Bh, const __half* __restrict__ Bl,
    const float* __restrict__ bias, float* __restrict__ C,
    __half* __restrict__ Ch, __half* __restrict__ Cl,
    int M, int N, int K, int act, int osplit) {
    extern __shared__ __half smb[];
    const uint32_t sbase = smem_u32(smb);
    const int tid = threadIdx.x;
    const int wid = tid >> 5, lane = tid & 31;
    const int r4 = lane >> 2, lq = lane & 3;
    const int m0 = blockIdx.y * 64, n0 = blockIdx.x * 128;
    const int wm = (wid & 1) * 32, wn = (wid >> 1) * 32;

    const int aro = lane & 15, ako = (lane >> 4) << 3;
    const int bro = (lane & 7) + ((lane >> 4) << 3), bko = ((lane >> 3) & 1) << 3;

    float acc[2][4][4] = {};
    uint32_t corr[2][4][2] = {};
    const int nch = K >> 5;

    const int ld_r = tid >> 2, ld_q = tid & 3;
    const uint32_t ld_e = (uint32_t)(ld_r * PADE + ld_q * 8) * 2;

    {
#pragma unroll
        for (int c = 0; c < 2; c++) {
            if (c >= nch) break;
            const int k0 = c << 5;
            const uint32_t bb = sbase + (uint32_t)((c & 1) * BUFE * 2);
            {
                size_t goA = (size_t)(m0 + ld_r) * K + k0 + ld_q * 8;
                cp16(bb + OFF_AH * 2 + ld_e, Ah + goA);
                cp16(bb + OFF_AL * 2 + ld_e, Al + goA);
            }
#pragma unroll
            for (int q = 0; q < 2; q++) {
                int r = ld_r + 64 * q;
                uint32_t e = ld_e + (uint32_t)(64 * q * PADE) * 2;
                size_t goB = (size_t)(n0 + r) * K + k0 + ld_q * 8;
                cp16(bb + OFF_BH * 2 + e, Bh + goB);
                cp16(bb + OFF_BL * 2 + e, Bl + goB);
            }
            cp_commit();
        }
    }

    for (int c = 0; c < nch; c++) {
        if (c + 1 < nch) cp_wait1(); else cp_wait0();
        __syncthreads();

        const uint32_t bb = sbase + (uint32_t)((c & 1) * BUFE * 2);
#pragma unroll
        for (int ks = 0; ks < 2; ks++) {
            uint32_t ahf[2][4], alf[2][4], bhf[4][2], blf[4][2];
#pragma unroll
            for (int am = 0; am < 2; am++) {
                uint32_t ar = (uint32_t)((wm + am * 16 + aro) * PADE + ks * 16 + ako) * 2;
                ldsm4(ahf[am][0], ahf[am][1], ahf[am][2], ahf[am][3], bb + OFF_AH * 2 + ar);
                ldsm4(alf[am][0], alf[am][1], alf[am][2], alf[am][3], bb + OFF_AL * 2 + ar);
            }
#pragma unroll
            for (int nb = 0; nb < 2; nb++) {
                uint32_t br = (uint32_t)((wn + nb * 16 + bro) * PADE + ks * 16 + bko) * 2;
                ldsm4(bhf[nb * 2][0], bhf[nb * 2][1], bhf[nb * 2 + 1][0], bhf[nb * 2 + 1][1],
                      bb + OFF_BH * 2 + br);
                ldsm4(blf[nb * 2][0], blf[nb * 2][1], blf[nb * 2 + 1][0], blf[nb * 2 + 1][1],
                      bb + OFF_BL * 2 + br);
            }
#pragma unroll
            for (int am = 0; am < 2; am++)
#pragma unroll
                for (int bn = 0; bn < 4; bn++) {
                    mma16816(acc[am][bn], ahf[am], bhf[bn]);
                    mma16816h(corr[am][bn], alf[am], bhf[bn]);
                    mma16816h(corr[am][bn], ahf[am], blf[bn]);
                }
        }
        __syncthreads();

        if (c + 2 < nch) {
            const int k0 = (c + 2) << 5;
            const uint32_t nb = sbase + (uint32_t)(((c + 2) & 1) * BUFE * 2);
            {
                size_t goA = (size_t)(m0 + ld_r) * K + k0 + ld_q * 8;
                cp16(nb + OFF_AH * 2 + ld_e, Ah + goA);
                cp16(nb + OFF_AL * 2 + ld_e, Al + goA);
            }
#pragma unroll
            for (int q = 0; q < 2; q++) {
                int r = ld_r + 64 * q;
                uint32_t e = ld_e + (uint32_t)(64 * q * PADE) * 2;
                size_t goB = (size_t)(n0 + r) * K + k0 + ld_q * 8;
                cp16(nb + OFF_BH * 2 + e, Bh + goB);
                cp16(nb + OFF_BL * 2 + e, Bl + goB);
            }
            cp_commit();
        }
    }

#pragma unroll
    for (int am = 0; am < 2; am++) {
        const int row = m0 + wm + am * 16 + r4;
#pragma unroll
        for (int bn = 0; bn < 4; bn++) {
            const int col = n0 + wn + bn * 8 + 2 * lq;
            const float b0 = bias[col], b1 = bias[col + 1];
            float2 c01 = __half22float2(*reinterpret_cast<__half2*>(&corr[am][bn][0]));
            float2 c23 = __half22float2(*reinterpret_cast<__half2*>(&corr[am][bn][1]));
            float v0 = acc[am][bn][0] + c01.x + b0, v1 = acc[am][bn][1] + c01.y + b1;
            float v2 = acc[am][bn][2] + c23.x + b0, v3 = acc[am][bn][3] + c23.y + b1;
            if (act) { v0 = mishf(v0); v1 = mishf(v1); v2 = mishf(v2); v3 = mishf(v3); }
            if (osplit) {
                __half2 h01, h23, l01, l23;
                h01.x = __float2half_rn(v0); h01.y = __float2half_rn(v1);
                h23.x = __float2half_rn(v2); h23.y = __float2half_rn(v3);
                l01.x = __float2half_rn(v0 - __half2float(h01.x));
                l01.y = __float2half_rn(v1 - __half2float(h01.y));
                l23.x = __float2half_rn(v2 - __half2float(h23.x));
                l23.y = __float2half_rn(v3 - __half2float(h23.y));
                *(uint32_t*)(Ch + (size_t)row * N + col) = h2u(h01);
                *(uint32_t*)(Cl + (size_t)row * N + col) = h2u(l01);
                *(uint32_t*)(Ch + (size_t)(row + 8) * N + col) = h2u(h23);
                *(uint32_t*)(Cl + (size_t)(row + 8) * N + col) = h2u(l23);
            } else {
                *(float2*)(C + (size_t)row * N + col) = make_float2(v0, v1);
                *(float2*)(C + (size_t)(row + 8) * N + col) = make_float2(v2, v3);
            }
        }
    }
}

// ---------------- small SGEMM (p3, N=16) ----------------
__global__ __launch_bounds__(256) void sgemm64_kernel(
    const float* __restrict__ A, const float* __restrict__ B,
    const float* __restrict__ bias, float* __restrict__ C,
    int M, int N, int K) {
    __shared__ float As[16][64];
    __shared__ float Bs[16][64];
    const int m0 = blockIdx.y * 64;
    const int n0 = blockIdx.x * 64;
    const int tid = threadIdx.x;
    const int tx = tid & 15, ty = tid >> 4;
    const int lr = tid >> 2, lq = tid & 3;
    float acc[4][4] = {};
    for (int k0 = 0; k0 < K; k0 += 16) {
        float4 a4 = *(const float4*)(A + (size_t)(m0 + lr) * K + k0 + lq * 4);
        As[lq * 4 + 0][lr] = a4.x; As[lq * 4 + 1][lr] = a4.y;
        As[lq * 4 + 2][lr] = a4.z; As[lq * 4 + 3][lr] = a4.w;
        float4 b4 = make_float4(0.f, 0.f, 0.f, 0.f);
        if (n0 + lr < N) b4 = *(const float4*)(B + (size_t)(n0 + lr) * K + k0 + lq * 4);
        Bs[lq * 4 + 0][lr] = b4.x; Bs[lq * 4 + 1][lr] = b4.y;
        Bs[lq * 4 + 2][lr] = b4.z; Bs[lq * 4 + 3][lr] = b4.w;
        __syncthreads();
#pragma unroll
        for (int k = 0; k < 16; k++) {
            float4 av = *(const float4*)(&As[k][ty * 4]);
            float4 bv = *(const float4*)(&Bs[k][tx * 4]);
            float avs[4] = {av.x, av.y, av.z, av.w};
            float bvs[4] = {bv.x, bv.y, bv.z, bv.w};
#pragma unroll
            for (int i = 0; i < 4; i++)
#pragma unroll
                for (int jj = 0; jj < 4; jj++)
                    acc[i][jj] = fmaf(avs[i], bvs[jj], acc[i][jj]);
        }
        __syncthreads();
    }
#pragma unroll
    for (int i = 0; i < 4; i++) {
        int m = m0 + ty * 4 + i;
#pragma unroll
        for (int jj = 0; jj < 4; jj++) {
            int n = n0 + tx * 4 + jj;
            if (n < N) C[(size_t)m * N + n] = acc[i][jj] + (bias ? bias[n] : 0.0f);
        }
    }
}

// ---------------- prep: bucket timesteps by age within reset-segment ----------------
__global__ __launch_bounds__(1024) void prep_kernel(const int* __restrict__ start) {
    __shared__ int sa[2048], sb_[2048], sc[2048];
    __shared__ int skmax;
    const int tid = threadIdx.x;
    const int t0 = tid, t1 = tid + 1024;
    if (tid == 0) { g_bar = 0u; skmax = 0; }
    sa[t0] = start[t0] ? t0 : -1;
    sa[t1] = start[t1] ? t1 : -1;
    __syncthreads();
    int* src = sa; int* dst = sb_;
    for (int d = 1; d < 2048; d <<= 1) {
        int v0 = src[t0]; if (t0 >= d) v0 = max(v0, src[t0 - d]);
        int v1 = src[t1]; if (t1 >= d) v1 = max(v1, src[t1 - d]);
        dst[t0] = v0; dst[t1] = v1;
        __syncthreads();
        int* tmp = src; src = dst; dst = tmp;
    }
    int r0v = src[t0], r1v = src[t1];
    int age0 = (r0v < 0) ? t0 : t0 - r0v;
    int age1 = (r1v < 0) ? t1 : t1 - r1v;
    __syncthreads();
    sc[t0] = 0; sc[t1] = 0;
    __syncthreads();
    atomicAdd(&sc[age0], 1);
    atomicAdd(&sc[age1], 1);
    atomicMax(&skmax, max(age0, age1) + 1);
    __syncthreads();
    sa[t0] = sc[t0]; sa[t1] = sc[t1];
    __syncthreads();
    src = sa; dst = sb_;
    for (int d = 1; d < 2048; d <<= 1) {
        int v0 = src[t0]; if (t0 >= d) v0 += src[t0 - d];
        int v1 = src[t1]; if (t1 >= d) v1 += src[t1 - d];
        dst[t0] = v0; dst[t1] = v1;
        __syncthreads();
        int* tmp = src; src = dst; dst = tmp;
    }
    if (tid == 0) { g_off[0] = 0; g_kmax = skmax; }
    g_off[t0 + 1] = src[t0];
    g_off[t1 + 1] = src[t1];
    sc[t0] = 0; sc[t1] = 0;
    __syncthreads();
    int base0 = (age0 == 0) ? 0 : src[age0 - 1];
    g_order[base0 + atomicAdd(&sc[age0], 1)] = t0;
    int base1 = (age1 == 0) ? 0 : src[age1 - 1];
    g_order[base1 + atomicAdd(&sc[age1], 1)] = t1;
}

// ---------------- grid barrier ----------------
__device__ inline void grid_bar(unsigned* barp, unsigned target) {
    __syncthreads();
    if (threadIdx.x == 0) {
        asm volatile("red.release.gpu.global.add.u32 [%0], %1;" :: "l"(barp), "r"(1u) : "memory");
        unsigned v;
        do {
            asm volatile("ld.acquire.gpu.global.u32 %0, [%1];" : "=r"(v) : "l"(barp) : "memory");
        } while (v < target);
    }
    __syncthreads();
}

__device__ __forceinline__ void store_state(int t, int j, float hnew, float* out) {
    g_states[(size_t)t * HD + j] = hnew;
    __half h = __float2half_rn(hnew);
    g_sth[(size_t)t * HD + j] = h;
    g_stl[(size_t)t * HD + j] = __float2half_rn(hnew - __half2float(h));
    if (t == T_STEPS - 1) out[(size_t)T_STEPS * ACTD + j] = hnew;
}

// ---------------- segment-parallel GRU scan, register-resident whh, 4 rows/iter ----------------
__global__ __launch_bounds__(256, 1) void scan_kernel(
    const float* __restrict__ whh, const float* __restrict__ gbn,
    const int* __restrict__ start, const float* __restrict__ state,
    float* __restrict__ out) {
    __shared__ float sH[4][HD];
    const int tid = threadIdx.x;
    const int w = tid >> 5, lane = tid & 31;
    const int j = blockIdx.x * 8 + w;

    const float4* w4 = (const float4*)whh;
    float4 wr[8], wz[8], wn[8];
#pragma unroll
    for (int q = 0; q < 8; q++) {
        wr[q] = w4[(size_t)(0 * HD + j) * 256 + lane + 32 * q];
        wz[q] = w4[(size_t)(1 * HD + j) * 256 + lane + 32 * q];
        wn[q] = w4[(size_t)(2 * HD + j) * 256 + lane + 32 * q];
    }
    const float bnj = gbn[j];
    unsigned* barp = &g_bar;
    const int kmax = g_kmax;
    const int s0 = start[0];
    unsigned epoch = 0;

    // ---- round 0: t=0 with start[0]==0 (h_in = state) ----
    if (s0 == 0) {
        ((float4*)sH[0])[tid] = ((const float4*)state)[tid];
        __syncthreads();
        float ir = 0.f, iz = 0.f, inn = 0.f;
        if (lane == 0) { ir = g_ig[j]; iz = g_ig[HD + j]; inn = g_ig[2 * HD + j]; }
        float aR = 0.f, aZ = 0.f, aN = 0.f;
#pragma unroll
        for (int q = 0; q < 8; q++) {
            float4 h4 = ((const float4*)sH[0])[lane + 32 * q];
            aR = fmaf(h4.x, wr[q].x, fmaf(h4.y, wr[q].y, fmaf(h4.z, wr[q].z, fmaf(h4.w, wr[q].w, aR))));
            aZ = fmaf(h4.x, wz[q].x, fmaf(h4.y, wz[q].y, fmaf(h4.z, wz[q].z, fmaf(h4.w, wz[q].w, aZ))));
            aN = fmaf(h4.x, wn[q].x, fmaf(h4.y, wn[q].y, fmaf(h4.z, wn[q].z, fmaf(h4.w, wn[q].w, aN))));
        }
#pragma unroll
        for (int off = 16; off; off >>= 1) {
            aR += __shfl_xor_sync(0xffffffffu, aR, off);
            aZ += __shfl_xor_sync(0xffffffffu, aZ, off);
            aN += __shfl_xor_sync(0xffffffffu, aN, off);
        }
        if (lane == 0) {
            float rv = sigmoidf_(ir + aR);
            float uv = sigmoidf_(iz + aZ);
            float nv = tanhf(inn + rv * (aN + bnj));
            float hin = sH[0][j];
            store_state(0, j, nv + uv * (hin - nv), out);
        }
        __syncthreads();
    }
    // round 0: start rows (h_in = 0), lane-parallel
    {
        const int beg = g_off[0], end = g_off[1];
        for (int r = beg + lane; r < end; r += 32) {
            const int t = g_order[r];
            if (t == 0 && s0 == 0) continue;
            const float* igt = g_ig + (size_t)t * (3 * HD);
            float rv = sigmoidf_(igt[j]);
            float uv = sigmoidf_(igt[HD + j]);
            float nv = tanhf(igt[2 * HD + j] + rv * bnj);
            store_state(t, j, nv - uv * nv, out);
        }
    }
    grid_bar(barp, (++epoch) * SCAN_BLOCKS);

    // ---- rounds k >= 1: four independent rows per iteration, lane-parallel tail ----
    for (int k = 1; k < kmax; k++) {
        const int beg = g_off[k], end = g_off[k + 1];
        int r = beg;
        int tt[4] = {-1, -1, -1, -1};
        float4 nx[4];
#pragma unroll
        for (int i = 0; i < 4; i++) {
            if (r + i < end) {
                tt[i] = g_order[r + i];
                nx[i] = __ldcg((const float4*)(g_states + (size_t)(tt[i] - 1) * HD) + tid);
            }
        }

        while (r < end) {
            int cur[4];
#pragma unroll
            for (int i = 0; i < 4; i++) cur[i] = tt[i];
            if (cur[0] >= 0) ((float4*)sH[0])[tid] = nx[0];
            if (cur[1] >= 0) ((float4*)sH[1])[tid] = nx[1];
            if (cur[2] >= 0) ((float4*)sH[2])[tid] = nx[2];
            if (cur[3] >= 0) ((float4*)sH[3])[tid] = nx[3];
            __syncthreads();

            const int rn = r + 4;
#pragma unroll
            for (int i = 0; i < 4; i++) {
                tt[i] = -1;
                if (rn + i < end) {
                    tt[i] = g_order[rn + i];
                    nx[i] = __ldcg((const float4*)(g_states + (size_t)(tt[i] - 1) * HD) + tid);
                }
            }

            // lane L (< 4) owns row L's input gates + tail
            float ir = 0.f, iz = 0.f, inn = 0.f;
            int myt = -1;
            if (lane < 4) {
                myt = cur[lane];
                if (myt >= 0) {
                    const float* igt = g_ig + (size_t)myt * (3 * HD);
                    ir = igt[j]; iz = igt[HD + j]; inn = igt[2 * HD + j];
                }
            }

            float aR[4] = {}, aZ[4] = {}, aN[4] = {};
#pragma unroll
            for (int q = 0; q < 8; q++) {
                const int c = lane + 32 * q;
                float4 r4v = wr[q], z4v = wz[q], n4v = wn[q];
#pragma unroll
                for (int i = 0; i < 4; i++) {
                    float4 h4 = ((const float4*)sH[i])[c];
                    aR[i] = fmaf(h4.x, r4v.x, fmaf(h4.y, r4v.y, fmaf(h4.z, r4v.z, fmaf(h4.w, r4v.w, aR[i]))));
                    aZ[i] = fmaf(h4.x, z4v.x, fmaf(h4.y, z4v.y, fmaf(h4.z, z4v.z, fmaf(h4.w, z4v.w, aZ[i]))));
                    aN[i] = fmaf(h4.x, n4v.x, fmaf(h4.y, n4v.y, fmaf(h4.z, n4v.z, fmaf(h4.w, n4v.w, aN[i]))));
                }
            }
#pragma unroll
            for (int off = 16; off; off >>= 1) {
#pragma unroll
                for (int i = 0; i < 4; i++) {
                    aR[i] += __shfl_xor_sync(0xffffffffu, aR[i], off);
                    aZ[i] += __shfl_xor_sync(0xffffffffu, aZ[i], off);
                    aN[i] += __shfl_xor_sync(0xffffffffu, aN[i], off);
                }
            }
            if (lane < 4 && myt >= 0) {
                float sR = aR[lane], sZ = aZ[lane], sN = aN[lane];
                float rv = sigmoidf_(ir + sR);
                float uv = sigmoidf_(iz + sZ);
                float nv = tanhf(inn + rv * (sN + bnj));
                float hin = sH[lane][j];
                store_state(myt, j, nv + uv * (hin - nv), out);
            }
            __syncthreads();
            r = rn;
        }
        grid_bar(barp, (++epoch) * SCAN_BLOCKS);
    }
}

// ---------------- launch ----------------
extern "C" void kernel_launch(void* const* d_in, const int* in_sizes, int n_in,
                              void* d_out, int out_size) {
    (void)in_sizes; (void)n_in;
    const float* x      = (const float*)d_in[0];
    const float* state  = (const float*)d_in[1];
    const int*   start  = (const int*)d_in[2];
    const float* pre_wm = (const float*)d_in[4];
    const float* pre_ws = (const float*)d_in[5];
    const float* pre_bm = (const float*)d_in[6];
    const float* pre_bs = (const float*)d_in[7];
    const float* wih    = (const float*)d_in[8];
    const float* whh    = (const float*)d_in[9];
    const float* gru_b  = (const float*)d_in[10];
    const float* gru_bn = (const float*)d_in[11];
    const float* p1_wm  = (const float*)d_in[12];
    const float* p1_ws  = (const float*)d_in[13];
    const float* p1_bm  = (const float*)d_in[14];
    const float* p1_bs  = (const float*)d_in[15];
    const float* p2_wm  = (const float*)d_in[16];
    const float* p2_ws  = (const float*)d_in[17];
    const float* p2_bm  = (const float*)d_in[18];
    const float* p2_bs  = (const float*)d_in[19];
    const float* p3_wm  = (const float*)d_in[20];
    const float* p3_ws  = (const float*)d_in[21];
    const float* p3_bm  = (const float*)d_in[22];
    const float* p3_bs  = (const float*)d_in[23];
    float* out = (float*)d_out;
    (void)out_size;

    unsigned nk[8][2];
    for (int i = 0; i < 8; i++) {
        unsigned a = 0u, b = (unsigned)i;
        tf_block(0u, 7u, a, b);
        nk[i][0] = a; nk[i][1] = b;
    }

    float *preB, *p1B, *p2B, *p3W, *p3B, *ig, *states, *y2;
    __half *xh, *xl, *preWh, *preWl, *wihh, *wihl, *p1Wh, *p1Wl, *p2Wh, *p2Wl;
    __half *zh, *zl, *sth, *stl, *y1h, *y1l;
    cudaGetSymbolAddress((void**)&preB, g_preB);
    cudaGetSymbolAddress((void**)&p1B, g_p1B);
    cudaGetSymbolAddress((void**)&p2B, g_p2B);
    cudaGetSymbolAddress((void**)&p3W, g_p3W);
    cudaGetSymbolAddress((void**)&p3B, g_p3B);
    cudaGetSymbolAddress((void**)&ig, g_ig);
    cudaGetSymbolAddress((void**)&states, g_states);
    cudaGetSymbolAddress((void**)&y2, g_y2);
    cudaGetSymbolAddress((void**)&xh, g_xh);
    cudaGetSymbolAddress((void**)&xl, g_xl);
    cudaGetSymbolAddress((void**)&preWh, g_preWh);
    cudaGetSymbolAddress((void**)&preWl, g_preWl);
    cudaGetSymbolAddress((void**)&wihh, g_wihh);
    cudaGetSymbolAddress((void**)&wihl, g_wihl);
    cudaGetSymbolAddress((void**)&p1Wh, g_p1Wh);
    cudaGetSymbolAddress((void**)&p1Wl, g_p1Wl);
    cudaGetSymbolAddress((void**)&p2Wh, g_p2Wh);
    cudaGetSymbolAddress((void**)&p2Wl, g_p2Wl);
    cudaGetSymbolAddress((void**)&zh, g_zh);
    cudaGetSymbolAddress((void**)&zl, g_zl);
    cudaGetSymbolAddress((void**)&sth, g_sth);
    cudaGetSymbolAddress((void**)&stl, g_stl);
    cudaGetSymbolAddress((void**)&y1h, g_y1h);
    cudaGetSymbolAddress((void**)&y1l, g_y1l);

    cudaFuncSetAttribute(mma_gemm_kernel, cudaFuncAttributeMaxDynamicSharedMemorySize,
                         MMA_SMEM_BYTES);

    static cudaStream_t sB = nullptr;
    static cudaEvent_t evFork, evPre, evWih, evPrep, evP1, evP2, evP3;
    if (sB == nullptr) {
        cudaStreamCreateWithFlags(&sB, cudaStreamNonBlocking);
        cudaEventCreateWithFlags(&evFork, cudaEventDisableTiming);
        cudaEventCreateWithFlags(&evPre, cudaEventDisableTiming);
        cudaEventCreateWithFlags(&evWih, cudaEventDisableTiming);
        cudaEventCreateWithFlags(&evPrep, cudaEventDisableTiming);
        cudaEventCreateWithFlags(&evP1, cudaEventDisableTiming);
        cudaEventCreateWithFlags(&evP2, cudaEventDisableTiming);
        cudaEventCreateWithFlags(&evP3, cudaEventDisableTiming);
    }

    cudaEventRecord(evFork, 0);
    cudaStreamWaitEvent(sB, evFork, 0);

    // main: x split
    conv_split_kernel<<<(T_STEPS * OBS / 4 + 255) / 256, 256>>>(x, xh, xl, T_STEPS * OBS / 4);
    // side: pre noise + all small noise (biases + p3W)
    { int n = MLPD * OBS; gen_noisy_w_kernel<<<(n + 255) / 256, 256, 0, sB>>>(pre_wm, pre_ws, preWh, preWl, n, nk[0][0], nk[0][1]); }
    gen_small_kernel<<<(19472 + 255) / 256, 256, 0, sB>>>(
        p3_wm, p3_ws, p3W, nk[6][0], nk[6][1],
        pre_bm, pre_bs, preB, nk[1][0], nk[1][1],
        p1_bm, p1_bs, p1B, nk[3][0], nk[3][1],
        p2_bm, p2_bs, p2B, nk[5][0], nk[5][1],
        p3_bm, p3_bs, p3B, nk[7][0], nk[7][1]);
    cudaEventRecord(evPre, sB);

    // main: GEMM1
    cudaStreamWaitEvent(0, evPre, 0);
    mma_gemm_kernel<<<dim3(MLPD / 128, T_STEPS / 64), 256, MMA_SMEM_BYTES>>>(
        xh, xl, preWh, preWl, preB, nullptr, zh, zl, T_STEPS, MLPD, OBS, 1, 1);

    // side: wih split (overlaps GEMM1)
    conv_split_kernel<<<(3 * HD * MLPD / 4 + 255) / 256, 256, 0, sB>>>(wih, wihh, wihl, 3 * HD * MLPD / 4);
    cudaEventRecord(evWih, sB);
    // side: prep
    prep_kernel<<<1, 1024, 0, sB>>>(start);
    cudaEventRecord(evPrep, sB);

    // main: GEMM2
    cudaStreamWaitEvent(0, evWih, 0);
    mma_gemm_kernel<<<dim3(3 * HD / 128, T_STEPS / 64), 256, MMA_SMEM_BYTES>>>(
        zh, zl, wihh, wihl, gru_b, ig, nullptr, nullptr, T_STEPS, 3 * HD, MLPD, 0, 0);

    // side: p1/p2 noise (overlaps GEMM2 + scan)
    { int n = MLPD * HD;   gen_noisy_w_kernel<<<(n + 255) / 256, 256, 0, sB>>>(p1_wm, p1_ws, p1Wh, p1Wl, n, nk[2][0], nk[2][1]); }
    cudaEventRecord(evP1, sB);
    { int n = MLPD * MLPD; gen_noisy_w_kernel<<<(n + 255) / 256, 256, 0, sB>>>(p2_wm, p2_ws, p2Wh, p2Wl, n, nk[4][0], nk[4][1]); }
    cudaEventRecord(evP2, sB);

    // main: scan
    cudaStreamWaitEvent(0, evPrep, 0);
    scan_kernel<<<SCAN_BLOCKS, 256>>>(whh, gru_bn, start, state, out);

    // main: GEMM3
    cudaStreamWaitEvent(0, evP1, 0);
    mma_gemm_kernel<<<dim3(MLPD / 128, T_STEPS / 64), 256, MMA_SMEM_BYTES>>>(
        sth, stl, p1Wh, p1Wl, p1B, nullptr, y1h, y1l, T_STEPS, MLPD, HD, 1, 1);

    // main: GEMM4
    cudaStreamWaitEvent(0, evP2, 0);
    mma_gemm_kernel<<<dim3(MLPD / 128, T_STEPS / 64), 256, MMA_SMEM_BYTES>>>(
        y1h, y1l, p2Wh, p2Wl, p2B, y2, nullptr, nullptr, T_STEPS, MLPD, MLPD, 1, 0);

    // main: final layer -> d_out[0 : 2048*16]
    sgemm64_kernel<<<dim3(1, T_STEPS / 64), 256>>>(y2, p3W, p3B, out, T_STEPS, ACTD, MLPD);
}

// round 14
// speedup vs baseline: 1.4912x; 1.2145x over previous
#include <cuda_runtime.h>
#include <cuda_fp16.h>
#include <cstdint>

#define T_STEPS 2048
#define OBS 512
#define MLPD 1024
#define HD 1024
#define ACTD 16
#define SCAN_BLOCKS 128
#define KGEMM 6

// ---------------- device scratch (no allocations allowed) ----------------
__device__ float g_preB[MLPD];
__device__ float g_p1B[MLPD];
__device__ float g_p2B[MLPD];
__device__ float g_p3W[ACTD * MLPD];
__device__ float g_p3B[ACTD];
__device__ float g_ig[(size_t)T_STEPS * 3 * HD];
__device__ float g_states[(size_t)T_STEPS * HD];
__device__ float g_hg[(size_t)T_STEPS * 3 * HD];
__device__ float g_y2[T_STEPS * MLPD];
__device__ __half g_xh[T_STEPS * OBS],  g_xl[T_STEPS * OBS];
__device__ __half g_preWh[MLPD * OBS],  g_preWl[MLPD * OBS];
__device__ __half g_wihh[3 * HD * MLPD], g_wihl[3 * HD * MLPD];
__device__ __half g_whhh[3 * HD * MLPD], g_whhl[3 * HD * MLPD];
__device__ __half g_p1Wh[MLPD * HD],    g_p1Wl[MLPD * HD];
__device__ __half g_p2Wh[MLPD * MLPD],  g_p2Wl[MLPD * MLPD];
__device__ __half g_zh[T_STEPS * MLPD], g_zl[T_STEPS * MLPD];
__device__ __half g_sth[(size_t)T_STEPS * HD], g_stl[(size_t)T_STEPS * HD];
__device__ __half g_y1h[T_STEPS * MLPD], g_y1l[T_STEPS * MLPD];
__device__ unsigned g_bar;
__device__ int g_order[T_STEPS];
__device__ int g_off[T_STEPS + 1];
__device__ int g_kmax;

// ---------------- threefry2x32 (matches JAX) ----------------
#define TF_ROUND(x0, x1, R) { x0 += x1; x1 = (x1 << R) | (x1 >> (32 - R)); x1 ^= x0; }

__host__ __device__ inline void tf_block(unsigned k0, unsigned k1, unsigned &x0, unsigned &x1) {
    unsigned ks2 = k0 ^ k1 ^ 0x1BD11BDAu;
    x0 += k0; x1 += k1;
    TF_ROUND(x0, x1, 13) TF_ROUND(x0, x1, 15) TF_ROUND(x0, x1, 26) TF_ROUND(x0, x1, 6)
    x0 += k1; x1 += ks2 + 1u;
    TF_ROUND(x0, x1, 17) TF_ROUND(x0, x1, 29) TF_ROUND(x0, x1, 16) TF_ROUND(x0, x1, 24)
    x0 += ks2; x1 += k0 + 2u;
    TF_ROUND(x0, x1, 13) TF_ROUND(x0, x1, 15) TF_ROUND(x0, x1, 26) TF_ROUND(x0, x1, 6)
    x0 += k0; x1 += k1 + 3u;
    TF_ROUND(x0, x1, 17) TF_ROUND(x0, x1, 29) TF_ROUND(x0, x1, 16) TF_ROUND(x0, x1, 24)
    x0 += k1; x1 += ks2 + 4u;
    TF_ROUND(x0, x1, 13) TF_ROUND(x0, x1, 15) TF_ROUND(x0, x1, 26) TF_ROUND(x0, x1, 6)
    x0 += ks2; x1 += k0 + 5u;
}

// XLA f32 erf_inv (Giles)
__device__ inline float xla_erfinv(float x) {
    float w = -log1pf(-x * x);
    float p;
    if (w < 5.0f) {
        w -= 2.5f;
        p = 2.81022636e-08f;
        p = fmaf(p, w, 3.43273939e-07f);
        p = fmaf(p, w, -3.5233877e-06f);
        p = fmaf(p, w, -4.39150654e-06f);
        p = fmaf(p, w, 0.00021858087f);
        p = fmaf(p, w, -0.00125372503f);
        p = fmaf(p, w, -0.00417768164f);
        p = fmaf(p, w, 0.246640727f);
        p = fmaf(p, w, 1.50140941f);
    } else {
        w = sqrtf(w) - 3.0f;
        p = -0.000200214257f;
        p = fmaf(p, w, 0.000100950558f);
        p = fmaf(p, w, 0.00134934322f);
        p = fmaf(p, w, -0.00367342844f);
        p = fmaf(p, w, 0.00573950773f);
        p = fmaf(p, w, -0.0076224613f);
        p = fmaf(p, w, 0.00943887047f);
        p = fmaf(p, w, 1.00167406f);
        p = fmaf(p, w, 2.83297682f);
    }
    return p * x;
}

__device__ inline float bits_to_normal(unsigned b) {
    float u1 = __uint_as_float((b >> 9) | 0x3f800000u) - 1.0f;
    float v = fmaf(u1, 1.99999994f, -0.99999994f);
    v = fmaxf(v, -0.99999994f);
    return 1.41421356f * xla_erfinv(v);
}

__device__ inline float tf_normal(unsigned k0, unsigned k1, unsigned i) {
    unsigned x0 = 0u, x1 = i;
    tf_block(k0, k1, x0, x1);
    return bits_to_normal(x0 ^ x1);
}

__global__ void gen_noisy_w_kernel(const float* __restrict__ wm, const float* __restrict__ ws,
                                   __half* __restrict__ hi, __half* __restrict__ lo,
                                   int n, unsigned k0, unsigned k1) {
    int i = blockIdx.x * blockDim.x + threadIdx.x;
    if (i >= n) return;
    float v = fmaf(ws[i], tf_normal(k0, k1, (unsigned)i), wm[i]);
    __half h = __float2half_rn(v);
    hi[i] = h;
    lo[i] = __float2half_rn(v - __half2float(h));
}

__global__ void gen_small_kernel(
    const float* p3wm, const float* p3ws, float* p3w, unsigned kw0, unsigned kw1,
    const float* prebm, const float* prebs, float* preb, unsigned ka0, unsigned ka1,
    const float* p1bm, const float* p1bs, float* p1b, unsigned kb0, unsigned kb1,
    const float* p2bm, const float* p2bs, float* p2b, unsigned kc0, unsigned kc1,
    const float* p3bm, const float* p3bs, float* p3b, unsigned kd0, unsigned kd1) {
    int i = blockIdx.x * blockDim.x + threadIdx.x;
    if (i < 16384) {
        p3w[i] = fmaf(p3ws[i], tf_normal(kw0, kw1, (unsigned)i), p3wm[i]);
    } else if (i < 17408) {
        int l = i - 16384;
        preb[l] = fmaf(prebs[l], tf_normal(ka0, ka1, (unsigned)l), prebm[l]);
    } else if (i < 18432) {
        int l = i - 17408;
        p1b[l] = fmaf(p1bs[l], tf_normal(kb0, kb1, (unsigned)l), p1bm[l]);
    } else if (i < 19456) {
        int l = i - 18432;
        p2b[l] = fmaf(p2bs[l], tf_normal(kc0, kc1, (unsigned)l), p2bm[l]);
    } else if (i < 19472) {
        int l = i - 19456;
        p3b[l] = fmaf(p3bs[l], tf_normal(kd0, kd1, (unsigned)l), p3bm[l]);
    }
}

// ---------------- activations ----------------
__device__ inline float mishf(float x) {
    float sp = fmaxf(x, 0.0f) + log1pf(expf(-fabsf(x)));
    return x * tanhf(sp);
}
__device__ inline float sigmoidf_(float x) { return 1.0f / (1.0f + expf(-x)); }

__device__ __forceinline__ uint32_t h2u(__half2 v) {
    return *reinterpret_cast<uint32_t*>(&v);
}

// ---------------- fp32 -> fp16 hi/lo split (n4 = n/4) ----------------
__global__ void conv_split_kernel(const float* __restrict__ src,
                                  __half* __restrict__ hi,
                                  __half* __restrict__ lo, int n4) {
    int i = blockIdx.x * blockDim.x + threadIdx.x;
    if (i >= n4) return;
    float4 v = ((const float4*)src)[i];
    __half2 h0, h1, l0, l1;
    h0.x = __float2half_rn(v.x); h0.y = __float2half_rn(v.y);
    h1.x = __float2half_rn(v.z); h1.y = __float2half_rn(v.w);
    l0.x = __float2half_rn(v.x - __half2float(h0.x));
    l0.y = __float2half_rn(v.y - __half2float(h0.y));
    l1.x = __float2half_rn(v.z - __half2float(h1.x));
    l1.y = __float2half_rn(v.w - __half2float(h1.y));
    ((uint2*)hi)[i] = make_uint2(h2u(h0), h2u(h1));
    ((uint2*)lo)[i] = make_uint2(h2u(l0), h2u(l1));
}

// ---------------- mma / ldmatrix / cp.async wrappers ----------------
__device__ __forceinline__ void mma16816(float* c, const uint32_t* a, const uint32_t* b) {
    asm volatile(
        "mma.sync.aligned.m16n8k16.row.col.f32.f16.f16.f32 "
        "{%0,%1,%2,%3}, {%4,%5,%6,%7}, {%8,%9}, {%0,%1,%2,%3};\n"
        : "+f"(c[0]), "+f"(c[1]), "+f"(c[2]), "+f"(c[3])
        : "r"(a[0]), "r"(a[1]), "r"(a[2]), "r"(a[3]), "r"(b[0]), "r"(b[1]));
}
__device__ __forceinline__ void mma16816h(uint32_t* c, const uint32_t* a, const uint32_t* b) {
    asm volatile(
        "mma.sync.aligned.m16n8k16.row.col.f16.f16.f16.f16 "
        "{%0,%1}, {%2,%3,%4,%5}, {%6,%7}, {%0,%1};\n"
        : "+r"(c[0]), "+r"(c[1])
        : "r"(a[0]), "r"(a[1]), "r"(a[2]), "r"(a[3]), "r"(b[0]), "r"(b[1]));
}
__device__ __forceinline__ void ldsm4(uint32_t& r0, uint32_t& r1, uint32_t& r2, uint32_t& r3,
                                      uint32_t addr) {
    asm volatile("ldmatrix.sync.aligned.m8n8.x4.shared.b16 {%0,%1,%2,%3}, [%4];"
                 : "=r"(r0), "=r"(r1), "=r"(r2), "=r"(r3) : "r"(addr));
}
__device__ __forceinline__ uint32_t smem_u32(const void* p) {
    uint32_t a;
    asm("{ .reg .u64 t; cvta.to.shared.u64 t, %1; cvt.u32.u64 %0, t; }" : "=r"(a) : "l"(p));
    return a;
}
__device__ __forceinline__ void cp16(uint32_t saddr, const void* gptr) {
    asm volatile("cp.async.cg.shared.global [%0], [%1], 16;" :: "r"(saddr), "l"(gptr));
}
__device__ __forceinline__ void cp_commit() {
    asm volatile("cp.async.commit_group;" ::: "memory");
}
__device__ __forceinline__ void cp_wait1() {
    asm volatile("cp.async.wait_group 1;" ::: "memory");
}
__device__ __forceinline__ void cp_wait0() {
    asm volatile("cp.async.wait_group 0;" ::: "memory");
}

// ============ split-fp16 tensor-core GEMM: CTA 64x128, 8 warps 32x32 ============
#define PADE 40
#define OFF_AH 0
#define OFF_AL (64 * PADE)
#define OFF_BH (2 * 64 * PADE)
#define OFF_BL (2 * 64 * PADE + 128 * PADE)
#define BUFE (2 * 64 * PADE + 2 * 128 * PADE)
#define MMA_SMEM_BYTES (2 * BUFE * 2)

__global__ __launch_bounds__(256, 2) void mma_gemm_kernel(
    const __half* __restrict__ Ah, const __half* __restrict__ Al,
    const __half* __restrict__ Bh, const __half* __restrict__ Bl,
    const float* __restrict__ bias, float* __restrict__ C,
    __half* __restrict__ Ch, __half* __restrict__ Cl,
    int M, int N, int K, int act, int osplit) {
    extern __shared__ __half smb[];
    const uint32_t sbase = smem_u32(smb);
    const int tid = threadIdx.x;
    const int wid = tid >> 5, lane = tid & 31;
    const int r4 = lane >> 2, lq = lane & 3;
    const int m0 = blockIdx.y * 64, n0 = blockIdx.x * 128;
    const int wm = (wid & 1) * 32, wn = (wid >> 1) * 32;

    const int aro = lane & 15, ako = (lane >> 4) << 3;
    const int bro = (lane & 7) + ((lane >> 4) << 3), bko = ((lane >> 3) & 1) << 3;

    float acc[2][4][4] = {};
    uint32_t corr[2][4][2] = {};
    const int nch = K >> 5;

    const int ld_r = tid >> 2, ld_q = tid & 3;
    const uint32_t ld_e = (uint32_t)(ld_r * PADE + ld_q * 8) * 2;

#pragma unroll
    for (int c = 0; c < 2; c++) {
        if (c >= nch) break;
        const int k0 = c << 5;
        const uint32_t bb = sbase + (uint32_t)((c & 1) * BUFE * 2);
        {
            size_t goA = (size_t)(m0 + ld_r) * K + k0 + ld_q * 8;
            cp16(bb + OFF_AH * 2 + ld_e, Ah + goA);
            cp16(bb + OFF_AL * 2 + ld_e, Al + goA);
        }
#pragma unroll
        for (int q = 0; q < 2; q++) {
            int r = ld_r + 64 * q;
            uint32_t e = ld_e + (uint32_t)(64 * q * PADE) * 2;
            size_t goB = (size_t)(n0 + r) * K + k0 + ld_q * 8;
            cp16(bb + OFF_BH * 2 + e, Bh + goB);
            cp16(bb + OFF_BL * 2 + e, Bl + goB);
        }
        cp_commit();
    }

    for (int c = 0; c < nch; c++) {
        if (c + 1 < nch) cp_wait1(); else cp_wait0();
        __syncthreads();

        const uint32_t bb = sbase + (uint32_t)((c & 1) * BUFE * 2);
#pragma unroll
        for (int ks = 0; ks < 2; ks++) {
            uint32_t ahf[2][4], alf[2][4], bhf[4][2], blf[4][2];
#pragma unroll
            for (int am = 0; am < 2; am++) {
                uint32_t ar = (uint32_t)((wm + am * 16 + aro) * PADE + ks * 16 + ako) * 2;
                ldsm4(ahf[am][0], ahf[am][1], ahf[am][2], ahf[am][3], bb + OFF_AH * 2 + ar);
                ldsm4(alf[am][0], alf[am][1], alf[am][2], alf[am][3], bb + OFF_AL * 2 + ar);
            }
#pragma unroll
            for (int nb = 0; nb < 2; nb++) {
                uint32_t br = (uint32_t)((wn + nb * 16 + bro) * PADE + ks * 16 + bko) * 2;
                ldsm4(bhf[nb * 2][0], bhf[nb * 2][1], bhf[nb * 2 + 1][0], bhf[nb * 2 + 1][1],
                      bb + OFF_BH * 2 + br);
                ldsm4(blf[nb * 2][0], blf[nb * 2][1], blf[nb * 2 + 1][0], blf[nb * 2 + 1][1],
                      bb + OFF_BL * 2 + br);
            }
#pragma unroll
            for (int am = 0; am < 2; am++)
#pragma unroll
                for (int bn = 0; bn < 4; bn++) {
                    mma16816(acc[am][bn], ahf[am], bhf[bn]);
                    mma16816h(corr[am][bn], alf[am], bhf[bn]);
                    mma16816h(corr[am][bn], ahf[am], blf[bn]);
                }
        }
        __syncthreads();

        if (c + 2 < nch) {
            const int k0 = (c + 2) << 5;
            const uint32_t nb = sbase + (uint32_t)(((c + 2) & 1) * BUFE * 2);
            {
                size_t goA = (size_t)(m0 + ld_r) * K + k0 + ld_q * 8;
                cp16(nb + OFF_AH * 2 + ld_e, Ah + goA);
                cp16(nb + OFF_AL * 2 + ld_e, Al + goA);
            }
#pragma unroll
            for (int q = 0; q < 2; q++) {
                int r = ld_r + 64 * q;
                uint32_t e = ld_e + (uint32_t)(64 * q * PADE) * 2;
                size_t goB = (size_t)(n0 + r) * K + k0 + ld_q * 8;
                cp16(nb + OFF_BH * 2 + e, Bh + goB);
                cp16(nb + OFF_BL * 2 + e, Bl + goB);
            }
            cp_commit();
        }
    }

#pragma unroll
    for (int am = 0; am < 2; am++) {
        const int row = m0 + wm + am * 16 + r4;
#pragma unroll
        for (int bn = 0; bn < 4; bn++) {
            const int col = n0 + wn + bn * 8 + 2 * lq;
            const float b0 = bias[col], b1 = bias[col + 1];
            float2 c01 = __half22float2(*reinterpret_cast<__half2*>(&corr[am][bn][0]));
            float2 c23 = __half22float2(*reinterpret_cast<__half2*>(&corr[am][bn][1]));
            float v0 = acc[am][bn][0] + c01.x + b0, v1 = acc[am][bn][1] + c01.y + b1;
            float v2 = acc[am][bn][2] + c23.x + b0, v3 = acc[am][bn][3] + c23.y + b1;
            if (act) { v0 = mishf(v0); v1 = mishf(v1); v2 = mishf(v2); v3 = mishf(v3); }
            if (osplit) {
                __half2 h01, h23, l01, l23;
                h01.x = __float2half_rn(v0); h01.y = __float2half_rn(v1);
                h23.x = __float2half_rn(v2); h23.y = __float2half_rn(v3);
                l01.x = __float2half_rn(v0 - __half2float(h01.x));
                l01.y = __float2half_rn(v1 - __half2float(h01.y));
                l23.x = __float2half_rn(v2 - __half2float(h23.x));
                l23.y = __float2half_rn(v3 - __half2float(h23.y));
                *(uint32_t*)(Ch + (size_t)row * N + col) = h2u(h01);
                *(uint32_t*)(Cl + (size_t)row * N + col) = h2u(l01);
                *(uint32_t*)(Ch + (size_t)(row + 8) * N + col) = h2u(h23);
                *(uint32_t*)(Cl + (size_t)(row + 8) * N + col) = h2u(l23);
            } else {
                *(float2*)(C + (size_t)row * N + col) = make_float2(v0, v1);
                *(float2*)(C + (size_t)(row + 8) * N + col) = make_float2(v2, v3);
            }
        }
    }
}

// ============ gather-GEMM for scan round k: hg[m,3072] = sth[order[base+m]-1] @ whh^T ============
__global__ __launch_bounds__(256, 2) void mma_ggemm_kernel(int kround) {
    extern __shared__ __half smb[];
    const int base = g_off[kround];
    const int R = g_off[kround + 1] - base;
    const int m0 = blockIdx.y * 64;
    if (m0 >= R) return;
    const uint32_t sbase = smem_u32(smb);
    const int tid = threadIdx.x;
    const int wid = tid >> 5, lane = tid & 31;
    const int r4 = lane >> 2, lq = lane & 3;
    const int n0 = blockIdx.x * 128;
    const int wm = (wid & 1) * 32, wn = (wid >> 1) * 32;
    const int K = HD, N = 3 * HD;

    const int aro = lane & 15, ako = (lane >> 4) << 3;
    const int bro = (lane & 7) + ((lane >> 4) << 3), bko = ((lane >> 3) & 1) << 3;

    float acc[2][4][4] = {};
    uint32_t corr[2][4][2] = {};
    const int nch = K >> 5;  // 32

    const int ld_r = tid >> 2, ld_q = tid & 3;
    const uint32_t ld_e = (uint32_t)(ld_r * PADE + ld_q * 8) * 2;
    const int gm = m0 + ld_r;
    const int myt = (gm < R) ? (g_order[base + gm] - 1) : (g_order[base] - 1);
    const __half* Ah = g_sth;
    const __half* Al = g_stl;
    const __half* Bh = g_whhh;
    const __half* Bl = g_whhl;

#pragma unroll
    for (int c = 0; c < 2; c++) {
        const int k0 = c << 5;
        const uint32_t bb = sbase + (uint32_t)((c & 1) * BUFE * 2);
        {
            size_t goA = (size_t)myt * K + k0 + ld_q * 8;
            cp16(bb + OFF_AH * 2 + ld_e, Ah + goA);
            cp16(bb + OFF_AL * 2 + ld_e, Al + goA);
        }
#pragma unroll
        for (int q = 0; q < 2; q++) {
            int r = ld_r + 64 * q;
            uint32_t e = ld_e + (uint32_t)(64 * q * PADE) * 2;
            size_t goB = (size_t)(n0 + r) * K + k0 + ld_q * 8;
            cp16(bb + OFF_BH * 2 + e, Bh + goB);
            cp16(bb + OFF_BL * 2 + e, Bl + goB);
        }
        cp_commit();
    }

    for (int c = 0; c < nch; c++) {
        if (c + 1 < nch) cp_wait1(); else cp_wait0();
        __syncthreads();

        const uint32_t bb = sbase + (uint32_t)((c & 1) * BUFE * 2);
#pragma unroll
        for (int ks = 0; ks < 2; ks++) {
            uint32_t ahf[2][4], alf[2][4], bhf[4][2], blf[4][2];
#pragma unroll
            for (int am = 0; am < 2; am++) {
                uint32_t ar = (uint32_t)((wm + am * 16 + aro) * PADE + ks * 16 + ako) * 2;
                ldsm4(ahf[am][0], ahf[am][1], ahf[am][2], ahf[am][3], bb + OFF_AH * 2 + ar);
                ldsm4(alf[am][0], alf[am][1], alf[am][2], alf[am][3], bb + OFF_AL * 2 + ar);
            }
#pragma unroll
            for (int nb = 0; nb < 2; nb++) {
                uint32_t br = (uint32_t)((wn + nb * 16 + bro) * PADE + ks * 16 + bko) * 2;
                ldsm4(bhf[nb * 2][0], bhf[nb * 2][1], bhf[nb * 2 + 1][0], bhf[nb * 2 + 1][1],
                      bb + OFF_BH * 2 + br);
                ldsm4(blf[nb * 2][0], blf[nb * 2][1], blf[nb * 2 + 1][0], blf[nb * 2 + 1][1],
                      bb + OFF_BL * 2 + br);
            }
#pragma unroll
            for (int am = 0; am < 2; am++)
#pragma unroll
                for (int bn = 0; bn < 4; bn++) {
                    mma16816(acc[am][bn], ahf[am], bhf[bn]);
                    mma16816h(corr[am][bn], alf[am], bhf[bn]);
                    mma16816h(corr[am][bn], ahf[am], blf[bn]);
                }
        }
        __syncthreads();

        if (c + 2 < nch) {
            const int k0 = (c + 2) << 5;
            const uint32_t nb = sbase + (uint32_t)(((c + 2) & 1) * BUFE * 2);
            {
                size_t goA = (size_t)myt * K + k0 + ld_q * 8;
                cp16(nb + OFF_AH * 2 + ld_e, Ah + goA);
                cp16(nb + OFF_AL * 2 + ld_e, Al + goA);
            }
#pragma unroll
            for (int q = 0; q < 2; q++) {
                int r = ld_r + 64 * q;
                uint32_t e = ld_e + (uint32_t)(64 * q * PADE) * 2;
                size_t goB = (size_t)(n0 + r) * K + k0 + ld_q * 8;
                cp16(nb + OFF_BH * 2 + e, Bh + goB);
                cp16(nb + OFF_BL * 2 + e, Bl + goB);
            }
            cp_commit();
        }
    }

#pragma unroll
    for (int am = 0; am < 2; am++) {
        const int row = m0 + wm + am * 16 + r4;
#pragma unroll
        for (int bn = 0; bn < 4; bn++) {
            const int col = n0 + wn + bn * 8 + 2 * lq;
            float2 c01 = __half22float2(*reinterpret_cast<__half2*>(&corr[am][bn][0]));
            float2 c23 = __half22float2(*reinterpret_cast<__half2*>(&corr[am][bn][1]));
            if (row < R)
                *(float2*)(g_hg + (size_t)row * N + col) =
                    make_float2(acc[am][bn][0] + c01.x, acc[am][bn][1] + c01.y);
            if (row + 8 < R)
                *(float2*)(g_hg + (size_t)(row + 8) * N + col) =
                    make_float2(acc[am][bn][2] + c23.x, acc[am][bn][3] + c23.y);
        }
    }
}

__device__ __forceinline__ void store_state(int t, int j, float hnew, float* out) {
    g_states[(size_t)t * HD + j] = hnew;
    __half h = __float2half_rn(hnew);
    g_sth[(size_t)t * HD + j] = h;
    g_stl[(size_t)t * HD + j] = __float2half_rn(hnew - __half2float(h));
    if (t == T_STEPS - 1) out[(size_t)T_STEPS * ACTD + j] = hnew;
}

// pointwise gates for a GEMM round
__global__ __launch_bounds__(256) void gate_kernel(const float* __restrict__ gbn,
                                                   float* __restrict__ out, int kround) {
    const int base = g_off[kround];
    const int R = g_off[kround + 1] - base;
    const int idx = blockIdx.x * blockDim.x + threadIdx.x;
    if (idx >= R * HD) return;
    const int m = idx >> 10, j = idx & (HD - 1);
    const int t = g_order[base + m];
    const float* hg = g_hg + (size_t)m * (3 * HD);
    const float* igt = g_ig + (size_t)t * (3 * HD);
    float rv = sigmoidf_(igt[j] + hg[j]);
    float uv = sigmoidf_(igt[HD + j] + hg[HD + j]);
    float nv = tanhf(igt[2 * HD + j] + rv * (hg[2 * HD + j] + gbn[j]));
    float hin = g_states[(size_t)(t - 1) * HD + j];
    store_state(t, j, nv + uv * (hin - nv), out);
}

// ---------------- small SGEMM (p3, N=16) ----------------
__global__ __launch_bounds__(256) void sgemm64_kernel(
    const float* __restrict__ A, const float* __restrict__ B,
    const float* __restrict__ bias, float* __restrict__ C,
    int M, int N, int K) {
    __shared__ float As[16][64];
    __shared__ float Bs[16][64];
    const int m0 = blockIdx.y * 64;
    const int n0 = blockIdx.x * 64;
    const int tid = threadIdx.x;
    const int tx = tid & 15, ty = tid >> 4;
    const int lr = tid >> 2, lq = tid & 3;
    float acc[4][4] = {};
    for (int k0 = 0; k0 < K; k0 += 16) {
        float4 a4 = *(const float4*)(A + (size_t)(m0 + lr) * K + k0 + lq * 4);
        As[lq * 4 + 0][lr] = a4.x; As[lq * 4 + 1][lr] = a4.y;
        As[lq * 4 + 2][lr] = a4.z; As[lq * 4 + 3][lr] = a4.w;
        float4 b4 = make_float4(0.f, 0.f, 0.f, 0.f);
        if (n0 + lr < N) b4 = *(const float4*)(B + (size_t)(n0 + lr) * K + k0 + lq * 4);
        Bs[lq * 4 + 0][lr] = b4.x; Bs[lq * 4 + 1][lr] = b4.y;
        Bs[lq * 4 + 2][lr] = b4.z; Bs[lq * 4 + 3][lr] = b4.w;
        __syncthreads();
#pragma unroll
        for (int k = 0; k < 16; k++) {
            float4 av = *(const float4*)(&As[k][ty * 4]);
            float4 bv = *(const float4*)(&Bs[k][tx * 4]);
            float avs[4] = {av.x, av.y, av.z, av.w};
            float bvs[4] = {bv.x, bv.y, bv.z, bv.w};
#pragma unroll
            for (int i = 0; i < 4; i++)
#pragma unroll
                for (int jj = 0; jj < 4; jj++)
                    acc[i][jj] = fmaf(avs[i], bvs[jj], acc[i][jj]);
        }
        __syncthreads();
    }
#pragma unroll
    for (int i = 0; i < 4; i++) {
        int m = m0 + ty * 4 + i;
#pragma unroll
        for (int jj = 0; jj < 4; jj++) {
            int n = n0 + tx * 4 + jj;
            if (n < N) C[(size_t)m * N + n] = acc[i][jj] + (bias ? bias[n] : 0.0f);
        }
    }
}

// ---------------- prep: bucket timesteps by age within reset-segment ----------------
__global__ __launch_bounds__(1024) void prep_kernel(const int* __restrict__ start) {
    __shared__ int sa[2048], sb_[2048], sc[2048];
    __shared__ int skmax;
    const int tid = threadIdx.x;
    const int t0 = tid, t1 = tid + 1024;
    if (tid == 0) { g_bar = 0u; skmax = 0; }
    sa[t0] = start[t0] ? t0 : -1;
    sa[t1] = start[t1] ? t1 : -1;
    __syncthreads();
    int* src = sa; int* dst = sb_;
    for (int d = 1; d < 2048; d <<= 1) {
        int v0 = src[t0]; if (t0 >= d) v0 = max(v0, src[t0 - d]);
        int v1 = src[t1]; if (t1 >= d) v1 = max(v1, src[t1 - d]);
        dst[t0] = v0; dst[t1] = v1;
        __syncthreads();
        int* tmp = src; src = dst; dst = tmp;
    }
    int r0v = src[t0], r1v = src[t1];
    int age0 = (r0v < 0) ? t0 : t0 - r0v;
    int age1 = (r1v < 0) ? t1 : t1 - r1v;
    __syncthreads();
    sc[t0] = 0; sc[t1] = 0;
    __syncthreads();
    atomicAdd(&sc[age0], 1);
    atomicAdd(&sc[age1], 1);
    atomicMax(&skmax, max(age0, age1) + 1);
    __syncthreads();
    sa[t0] = sc[t0]; sa[t1] = sc[t1];
    __syncthreads();
    src = sa; dst = sb_;
    for (int d = 1; d < 2048; d <<= 1) {
        int v0 = src[t0]; if (t0 >= d) v0 += src[t0 - d];
        int v1 = src[t1]; if (t1 >= d) v1 += src[t1 - d];
        dst[t0] = v0; dst[t1] = v1;
        __syncthreads();
        int* tmp = src; src = dst; dst = tmp;
    }
    if (tid == 0) { g_off[0] = 0; g_kmax = skmax; }
    g_off[t0 + 1] = src[t0];
    g_off[t1 + 1] = src[t1];
    sc[t0] = 0; sc[t1] = 0;
    __syncthreads();
    int base0 = (age0 == 0) ? 0 : src[age0 - 1];
    g_order[base0 + atomicAdd(&sc[age0], 1)] = t0;
    int base1 = (age1 == 0) ? 0 : src[age1 - 1];
    g_order[base1 + atomicAdd(&sc[age1], 1)] = t1;
}

// ---------------- grid barrier ----------------
__device__ inline void grid_bar(unsigned* barp, unsigned target) {
    __syncthreads();
    if (threadIdx.x == 0) {
        asm volatile("red.release.gpu.global.add.u32 [%0], %1;" :: "l"(barp), "r"(1u) : "memory");
        unsigned v;
        do {
            asm volatile("ld.acquire.gpu.global.u32 %0, [%1];" : "=r"(v) : "l"(barp) : "memory");
        } while (v < target);
    }
    __syncthreads();
}

// ---------------- round 0 (no barrier): t=0 full matvec + start rows closed-form ----------------
__global__ __launch_bounds__(256, 1) void round0_kernel(
    const float* __restrict__ whh, const float* __restrict__ gbn,
    const int* __restrict__ start, const float* __restrict__ state,
    float* __restrict__ out) {
    __shared__ float sH[HD];
    const int tid = threadIdx.x;
    const int w = tid >> 5, lane = tid & 31;
    const int j = blockIdx.x * 8 + w;
    const float bnj = gbn[j];
    const int s0 = start[0];

    if (s0 == 0) {
        ((float4*)sH)[tid] = ((const float4*)state)[tid];
        __syncthreads();
        const float4* w4 = (const float4*)whh;
        float ir = 0.f, iz = 0.f, inn = 0.f;
        if (lane == 0) { ir = g_ig[j]; iz = g_ig[HD + j]; inn = g_ig[2 * HD + j]; }
        float aR = 0.f, aZ = 0.f, aN = 0.f;
#pragma unroll
        for (int q = 0; q < 8; q++) {
            float4 h4 = ((const float4*)sH)[lane + 32 * q];
            float4 r4v = w4[(size_t)(0 * HD + j) * 256 + lane + 32 * q];
            float4 z4v = w4[(size_t)(1 * HD + j) * 256 + lane + 32 * q];
            float4 n4v = w4[(size_t)(2 * HD + j) * 256 + lane + 32 * q];
            aR = fmaf(h4.x, r4v.x, fmaf(h4.y, r4v.y, fmaf(h4.z, r4v.z, fmaf(h4.w, r4v.w, aR))));
            aZ = fmaf(h4.x, z4v.x, fmaf(h4.y, z4v.y, fmaf(h4.z, z4v.z, fmaf(h4.w, z4v.w, aZ))));
            aN = fmaf(h4.x, n4v.x, fmaf(h4.y, n4v.y, fmaf(h4.z, n4v.z, fmaf(h4.w, n4v.w, aN))));
        }
#pragma unroll
        for (int off = 16; off; off >>= 1) {
            aR += __shfl_xor_sync(0xffffffffu, aR, off);
            aZ += __shfl_xor_sync(0xffffffffu, aZ, off);
            aN += __shfl_xor_sync(0xffffffffu, aN, off);
        }
        if (lane == 0) {
            float rv = sigmoidf_(ir + aR);
            float uv = sigmoidf_(iz + aZ);
            float nv = tanhf(inn + rv * (aN + bnj));
            float hin = sH[j];
            store_state(0, j, nv + uv * (hin - nv), out);
        }
    }
    {
        const int beg = g_off[0], end = g_off[1];
        for (int r = beg + lane; r < end; r += 32) {
            const int t = g_order[r];
            if (t == 0 && s0 == 0) continue;
            const float* igt = g_ig + (size_t)t * (3 * HD);
            float rv = sigmoidf_(igt[j]);
            float uv = sigmoidf_(igt[HD + j]);
            float nv = tanhf(igt[2 * HD + j] + rv * bnj);
            store_state(t, j, nv - uv * nv, out);
        }
    }
}

// ---------------- cleanup scan: rounds kstart..kmax (tiny tails), 4 rows/iter ----------------
__global__ __launch_bounds__(256, 1) void cleanup_scan_kernel(
    const float* __restrict__ whh, const float* __restrict__ gbn,
    float* __restrict__ out, int kstart) {
    __shared__ float sH[4][HD];
    const int tid = threadIdx.x;
    const int w = tid >> 5, lane = tid & 31;
    const int j = blockIdx.x * 8 + w;
    const int kmax = g_kmax;
    if (kstart >= kmax) return;

    const float4* w4 = (const float4*)whh;
    float4 wr[8], wz[8], wn[8];
#pragma unroll
    for (int q = 0; q < 8; q++) {
        wr[q] = w4[(size_t)(0 * HD + j) * 256 + lane + 32 * q];
        wz[q] = w4[(size_t)(1 * HD + j) * 256 + lane + 32 * q];
        wn[q] = w4[(size_t)(2 * HD + j) * 256 + lane + 32 * q];
    }
    const float bnj = gbn[j];
    unsigned* barp = &g_bar;
    unsigned epoch = 0;

    for (int k = kstart; k < kmax; k++) {
        const int beg = g_off[k], end = g_off[k + 1];
        int r = beg;
        int tt[4] = {-1, -1, -1, -1};
        float4 nx[4];
#pragma unroll
        for (int i = 0; i < 4; i++) {
            if (r + i < end) {
                tt[i] = g_order[r + i];
                nx[i] = __ldcg((const float4*)(g_states + (size_t)(tt[i] - 1) * HD) + tid);
            }
        }

        while (r < end) {
            int cur[4];
#pragma unroll
            for (int i = 0; i < 4; i++) cur[i] = tt[i];
            if (cur[0] >= 0) ((float4*)sH[0])[tid] = nx[0];
            if (cur[1] >= 0) ((float4*)sH[1])[tid] = nx[1];
            if (cur[2] >= 0) ((float4*)sH[2])[tid] = nx[2];
            if (cur[3] >= 0) ((float4*)sH[3])[tid] = nx[3];
            __syncthreads();

            const int rn = r + 4;
#pragma unroll
            for (int i = 0; i < 4; i++) {
                tt[i] = -1;
                if (rn + i < end) {
                    tt[i] = g_order[rn + i];
                    nx[i] = __ldcg((const float4*)(g_states + (size_t)(tt[i] - 1) * HD) + tid);
                }
            }

            float ir = 0.f, iz = 0.f, inn = 0.f;
            int myt = -1;
            if (lane < 4) {
                myt = cur[lane];
                if (myt >= 0) {
                    const float* igt = g_ig + (size_t)myt * (3 * HD);
                    ir = igt[j]; iz = igt[HD + j]; inn = igt[2 * HD + j];
                }
            }

            float aR[4] = {}, aZ[4] = {}, aN[4] = {};
#pragma unroll
            for (int q = 0; q < 8; q++) {
                const int c = lane + 32 * q;
                float4 r4v = wr[q], z4v = wz[q], n4v = wn[q];
#pragma unroll
                for (int i = 0; i < 4; i++) {
                    float4 h4 = ((const float4*)sH[i])[c];
                    aR[i] = fmaf(h4.x, r4v.x, fmaf(h4.y, r4v.y, fmaf(h4.z, r4v.z, fmaf(h4.w, r4v.w, aR[i]))));
                    aZ[i] = fmaf(h4.x, z4v.x, fmaf(h4.y, z4v.y, fmaf(h4.z, z4v.z, fmaf(h4.w, z4v.w, aZ[i]))));
                    aN[i] = fmaf(h4.x, n4v.x, fmaf(h4.y, n4v.y, fmaf(h4.z, n4v.z, fmaf(h4.w, n4v.w, aN[i]))));
                }
            }
#pragma unroll
            for (int off = 16; off; off >>= 1) {
#pragma unroll
                for (int i = 0; i < 4; i++) {
                    aR[i] += __shfl_xor_sync(0xffffffffu, aR[i], off);
                    aZ[i] += __shfl_xor_sync(0xffffffffu, aZ[i], off);
                    aN[i] += __shfl_xor_sync(0xffffffffu, aN[i], off);
                }
            }
            if (lane < 4 && myt >= 0) {
                float rv = sigmoidf_(ir + aR[lane]);
                float uv = sigmoidf_(iz + aZ[lane]);
                float nv = tanhf(inn + rv * (aN[lane] + bnj));
                float hin = sH[lane][j];
                store_state(myt, j, nv + uv * (hin - nv), out);
            }
            __syncthreads();
            r = rn;
        }
        grid_bar(barp, (++epoch) * SCAN_BLOCKS);
    }
}

// ---------------- launch ----------------
extern "C" void kernel_launch(void* const* d_in, const int* in_sizes, int n_in,
                              void* d_out, int out_size) {
    (void)in_sizes; (void)n_in;
    const float* x      = (const float*)d_in[0];
    const float* state  = (const float*)d_in[1];
    const int*   start  = (const int*)d_in[2];
    const float* pre_wm = (const float*)d_in[4];
    const float* pre_ws = (const float*)d_in[5];
    const float* pre_bm = (const float*)d_in[6];
    const float* pre_bs = (const float*)d_in[7];
    const float* wih    = (const float*)d_in[8];
    const float* whh    = (const float*)d_in[9];
    const float* gru_b  = (const float*)d_in[10];
    const float* gru_bn = (const float*)d_in[11];
    const float* p1_wm  = (const float*)d_in[12];
    const float* p1_ws  = (const float*)d_in[13];
    const float* p1_bm  = (const float*)d_in[14];
    const float* p1_bs  = (const float*)d_in[15];
    const float* p2_wm  = (const float*)d_in[16];
    const float* p2_ws  = (const float*)d_in[17];
    const float* p2_bm  = (const float*)d_in[18];
    const float* p2_bs  = (const float*)d_in[19];
    const float* p3_wm  = (const float*)d_in[20];
    const float* p3_ws  = (const float*)d_in[21];
    const float* p3_bm  = (const float*)d_in[22];
    const float* p3_bs  = (const float*)d_in[23];
    float* out = (float*)d_out;
    (void)out_size;

    unsigned nk[8][2];
    for (int i = 0; i < 8; i++) {
        unsigned a = 0u, b = (unsigned)i;
        tf_block(0u, 7u, a, b);
        nk[i][0] = a; nk[i][1] = b;
    }

    float *preB, *p1B, *p2B, *p3W, *p3B, *ig, *states, *y2;
    __half *xh, *xl, *preWh, *preWl, *wihh, *wihl, *whhh, *whhl, *p1Wh, *p1Wl, *p2Wh, *p2Wl;
    __half *zh, *zl, *sth, *stl, *y1h, *y1l;
    cudaGetSymbolAddress((void**)&preB, g_preB);
    cudaGetSymbolAddress((void**)&p1B, g_p1B);
    cudaGetSymbolAddress((void**)&p2B, g_p2B);
    cudaGetSymbolAddress((void**)&p3W, g_p3W);
    cudaGetSymbolAddress((void**)&p3B, g_p3B);
    cudaGetSymbolAddress((void**)&ig, g_ig);
    cudaGetSymbolAddress((void**)&states, g_states);
    cudaGetSymbolAddress((void**)&y2, g_y2);
    cudaGetSymbolAddress((void**)&xh, g_xh);
    cudaGetSymbolAddress((void**)&xl, g_xl);
    cudaGetSymbolAddress((void**)&preWh, g_preWh);
    cudaGetSymbolAddress((void**)&preWl, g_preWl);
    cudaGetSymbolAddress((void**)&wihh, g_wihh);
    cudaGetSymbolAddress((void**)&wihl, g_wihl);
    cudaGetSymbolAddress((void**)&whhh, g_whhh);
    cudaGetSymbolAddress((void**)&whhl, g_whhl);
    cudaGetSymbolAddress((void**)&p1Wh, g_p1Wh);
    cudaGetSymbolAddress((void**)&p1Wl, g_p1Wl);
    cudaGetSymbolAddress((void**)&p2Wh, g_p2Wh);
    cudaGetSymbolAddress((void**)&p2Wl, g_p2Wl);
    cudaGetSymbolAddress((void**)&zh, g_zh);
    cudaGetSymbolAddress((void**)&zl, g_zl);
    cudaGetSymbolAddress((void**)&sth, g_sth);
    cudaGetSymbolAddress((void**)&stl, g_stl);
    cudaGetSymbolAddress((void**)&y1h, g_y1h);
    cudaGetSymbolAddress((void**)&y1l, g_y1l);

    cudaFuncSetAttribute(mma_gemm_kernel, cudaFuncAttributeMaxDynamicSharedMemorySize,
                         MMA_SMEM_BYTES);
    cudaFuncSetAttribute(mma_ggemm_kernel, cudaFuncAttributeMaxDynamicSharedMemorySize,
                         MMA_SMEM_BYTES);

    static cudaStream_t sB = nullptr;
    static cudaEvent_t evFork, evPre, evWih, evWhh, evPrep, evP1, evP2;
    if (sB == nullptr) {
        cudaStreamCreateWithFlags(&sB, cudaStreamNonBlocking);
        cudaEventCreateWithFlags(&evFork, cudaEventDisableTiming);
        cudaEventCreateWithFlags(&evPre, cudaEventDisableTiming);
        cudaEventCreateWithFlags(&evWih, cudaEventDisableTiming);
        cudaEventCreateWithFlags(&evWhh, cudaEventDisableTiming);
        cudaEventCreateWithFlags(&evPrep, cudaEventDisableTiming);
        cudaEventCreateWithFlags(&evP1, cudaEventDisableTiming);
        cudaEventCreateWithFlags(&evP2, cudaEventDisableTiming);
    }

    cudaEventRecord(evFork, 0);
    cudaStreamWaitEvent(sB, evFork, 0);

    // main: x split
    conv_split_kernel<<<(T_STEPS * OBS / 4 + 255) / 256, 256>>>(x, xh, xl, T_STEPS * OBS / 4);
    // side: pre noise + small noise
    { int n = MLPD * OBS; gen_noisy_w_kernel<<<(n + 255) / 256, 256, 0, sB>>>(pre_wm, pre_ws, preWh, preWl, n, nk[0][0], nk[0][1]); }
    gen_small_kernel<<<(19472 + 255) / 256, 256, 0, sB>>>(
        p3_wm, p3_ws, p3W, nk[6][0], nk[6][1],
        pre_bm, pre_bs, preB, nk[1][0], nk[1][1],
        p1_bm, p1_bs, p1B, nk[3][0], nk[3][1],
        p2_bm, p2_bs, p2B, nk[5][0], nk[5][1],
        p3_bm, p3_bs, p3B, nk[7][0], nk[7][1]);
    cudaEventRecord(evPre, sB);

    // main: GEMM1
    cudaStreamWaitEvent(0, evPre, 0);
    mma_gemm_kernel<<<dim3(MLPD / 128, T_STEPS / 64), 256, MMA_SMEM_BYTES>>>(
        xh, xl, preWh, preWl, preB, nullptr, zh, zl, T_STEPS, MLPD, OBS, 1, 1);

    // side: wih split, whh split, prep (all overlap GEMM1/2)
    conv_split_kernel<<<(3 * HD * MLPD / 4 + 255) / 256, 256, 0, sB>>>(wih, wihh, wihl, 3 * HD * MLPD / 4);
    cudaEventRecord(evWih, sB);
    conv_split_kernel<<<(3 * HD * MLPD / 4 + 255) / 256, 256, 0, sB>>>(whh, whhh, whhl, 3 * HD * MLPD / 4);
    cudaEventRecord(evWhh, sB);
    prep_kernel<<<1, 1024, 0, sB>>>(start);
    cudaEventRecord(evPrep, sB);

    // main: GEMM2
    cudaStreamWaitEvent(0, evWih, 0);
    mma_gemm_kernel<<<dim3(3 * HD / 128, T_STEPS / 64), 256, MMA_SMEM_BYTES>>>(
        zh, zl, wihh, wihl, gru_b, ig, nullptr, nullptr, T_STEPS, 3 * HD, MLPD, 0, 0);

    // side: p1/p2 noise (overlaps GEMM2 + scan rounds)
    { int n = MLPD * HD;   gen_noisy_w_kernel<<<(n + 255) / 256, 256, 0, sB>>>(p1_wm, p1_ws, p1Wh, p1Wl, n, nk[2][0], nk[2][1]); }
    cudaEventRecord(evP1, sB);
    { int n = MLPD * MLPD; gen_noisy_w_kernel<<<(n + 255) / 256, 256, 0, sB>>>(p2_wm, p2_ws, p2Wh, p2Wl, n, nk[4][0], nk[4][1]); }
    cudaEventRecord(evP2, sB);

    // main: round 0 (needs prep + ig)
    cudaStreamWaitEvent(0, evPrep, 0);
    round0_kernel<<<SCAN_BLOCKS, 256>>>(whh, gru_bn, start, state, out);

    // main: GEMM rounds 1..KGEMM (need whh split)
    cudaStreamWaitEvent(0, evWhh, 0);
    for (int k = 1; k <= KGEMM; k++) {
        mma_ggemm_kernel<<<dim3(3 * HD / 128, T_STEPS / 64), 256, MMA_SMEM_BYTES>>>(k);
        gate_kernel<<<(T_STEPS * HD) / 256, 256>>>(gru_bn, out, k);
    }

    // main: cleanup scan for rounds > KGEMM
    cleanup_scan_kernel<<<SCAN_BLOCKS, 256>>>(whh, gru_bn, out, KGEMM + 1);

    // main: GEMM3
    cudaStreamWaitEvent(0, evP1, 0);
    mma_gemm_kernel<<<dim3(MLPD / 128, T_STEPS / 64), 256, MMA_SMEM_BYTES>>>(
        sth, stl, p1Wh, p1Wl, p1B, nullptr, y1h, y1l, T_STEPS, MLPD, HD, 1, 1);

    // main: GEMM4
    cudaStreamWaitEvent(0, evP2, 0);
    mma_gemm_kernel<<<dim3(MLPD / 128, T_STEPS / 64), 256, MMA_SMEM_BYTES>>>(
        y1h, y1l, p2Wh, p2Wl, p2B, y2, nullptr, nullptr, T_STEPS, MLPD, MLPD, 1, 0);

    // main: final layer -> d_out[0 : 2048*16]
    sgemm64_kernel<<<dim3(1, T_STEPS / 64), 256>>>(y2, p3W, p3B, out, T_STEPS, ACTD, MLPD);
}

// round 15
// speedup vs baseline: 1.6175x; 1.0847x over previous
#include <cuda_runtime.h>
#include <cuda_fp16.h>
#include <cstdint>

#define T_STEPS 2048
#define OBS 512
#define MLPD 1024
#define HD 1024
#define ACTD 16
#define SCAN_BLOCKS 128
#define KGEMM 4

// ---------------- device scratch (no allocations allowed) ----------------
__device__ float g_preB[MLPD];
__device__ float g_p1B[MLPD];
__device__ float g_p2B[MLPD];
__device__ float g_p3W[ACTD * MLPD];
__device__ float g_p3B[ACTD];
__device__ float g_ig[(size_t)T_STEPS * 3 * HD];
__device__ float g_states[(size_t)T_STEPS * HD];
__device__ float g_hg[(size_t)T_STEPS * 3 * HD];
__device__ float g_y2[T_STEPS * MLPD];
__device__ __half g_xh[T_STEPS * OBS],  g_xl[T_STEPS * OBS];
__device__ __half g_preWh[MLPD * OBS],  g_preWl[MLPD * OBS];
__device__ __half g_wihh[3 * HD * MLPD], g_wihl[3 * HD * MLPD];
__device__ __half g_whhh[3 * HD * MLPD], g_whhl[3 * HD * MLPD];
__device__ __half g_p1Wh[MLPD * HD],    g_p1Wl[MLPD * HD];
__device__ __half g_p2Wh[MLPD * MLPD],  g_p2Wl[MLPD * MLPD];
__device__ __half g_zh[T_STEPS * MLPD], g_zl[T_STEPS * MLPD];
__device__ __half g_sth[(size_t)T_STEPS * HD], g_stl[(size_t)T_STEPS * HD];
__device__ __half g_y1h[T_STEPS * MLPD], g_y1l[T_STEPS * MLPD];
__device__ unsigned g_bar;
__device__ int g_order[T_STEPS];
__device__ int g_off[T_STEPS + 1];
__device__ int g_kmax;

// ---------------- threefry2x32 (matches JAX) ----------------
#define TF_ROUND(x0, x1, R) { x0 += x1; x1 = (x1 << R) | (x1 >> (32 - R)); x1 ^= x0; }

__host__ __device__ inline void tf_block(unsigned k0, unsigned k1, unsigned &x0, unsigned &x1) {
    unsigned ks2 = k0 ^ k1 ^ 0x1BD11BDAu;
    x0 += k0; x1 += k1;
    TF_ROUND(x0, x1, 13) TF_ROUND(x0, x1, 15) TF_ROUND(x0, x1, 26) TF_ROUND(x0, x1, 6)
    x0 += k1; x1 += ks2 + 1u;
    TF_ROUND(x0, x1, 17) TF_ROUND(x0, x1, 29) TF_ROUND(x0, x1, 16) TF_ROUND(x0, x1, 24)
    x0 += ks2; x1 += k0 + 2u;
    TF_ROUND(x0, x1, 13) TF_ROUND(x0, x1, 15) TF_ROUND(x0, x1, 26) TF_ROUND(x0, x1, 6)
    x0 += k0; x1 += k1 + 3u;
    TF_ROUND(x0, x1, 17) TF_ROUND(x0, x1, 29) TF_ROUND(x0, x1, 16) TF_ROUND(x0, x1, 24)
    x0 += k1; x1 += ks2 + 4u;
    TF_ROUND(x0, x1, 13) TF_ROUND(x0, x1, 15) TF_ROUND(x0, x1, 26) TF_ROUND(x0, x1, 6)
    x0 += ks2; x1 += k0 + 5u;
}

// XLA f32 erf_inv (Giles)
__device__ inline float xla_erfinv(float x) {
    float w = -log1pf(-x * x);
    float p;
    if (w < 5.0f) {
        w -= 2.5f;
        p = 2.81022636e-08f;
        p = fmaf(p, w, 3.43273939e-07f);
        p = fmaf(p, w, -3.5233877e-06f);
        p = fmaf(p, w, -4.39150654e-06f);
        p = fmaf(p, w, 0.00021858087f);
        p = fmaf(p, w, -0.00125372503f);
        p = fmaf(p, w, -0.00417768164f);
        p = fmaf(p, w, 0.246640727f);
        p = fmaf(p, w, 1.50140941f);
    } else {
        w = sqrtf(w) - 3.0f;
        p = -0.000200214257f;
        p = fmaf(p, w, 0.000100950558f);
        p = fmaf(p, w, 0.00134934322f);
        p = fmaf(p, w, -0.00367342844f);
        p = fmaf(p, w, 0.00573950773f);
        p = fmaf(p, w, -0.0076224613f);
        p = fmaf(p, w, 0.00943887047f);
        p = fmaf(p, w, 1.00167406f);
        p = fmaf(p, w, 2.83297682f);
    }
    return p * x;
}

__device__ inline float bits_to_normal(unsigned b) {
    float u1 = __uint_as_float((b >> 9) | 0x3f800000u) - 1.0f;
    float v = fmaf(u1, 1.99999994f, -0.99999994f);
    v = fmaxf(v, -0.99999994f);
    return 1.41421356f * xla_erfinv(v);
}

__device__ inline float tf_normal(unsigned k0, unsigned k1, unsigned i) {
    unsigned x0 = 0u, x1 = i;
    tf_block(k0, k1, x0, x1);
    return bits_to_normal(x0 ^ x1);
}

__global__ void gen_noisy_w_kernel(const float* __restrict__ wm, const float* __restrict__ ws,
                                   __half* __restrict__ hi, __half* __restrict__ lo,
                                   int n, unsigned k0, unsigned k1) {
    int i = blockIdx.x * blockDim.x + threadIdx.x;
    if (i >= n) return;
    float v = fmaf(ws[i], tf_normal(k0, k1, (unsigned)i), wm[i]);
    __half h = __float2half_rn(v);
    hi[i] = h;
    lo[i] = __float2half_rn(v - __half2float(h));
}

__global__ void gen_small_kernel(
    const float* p3wm, const float* p3ws, float* p3w, unsigned kw0, unsigned kw1,
    const float* prebm, const float* prebs, float* preb, unsigned ka0, unsigned ka1,
    const float* p1bm, const float* p1bs, float* p1b, unsigned kb0, unsigned kb1,
    const float* p2bm, const float* p2bs, float* p2b, unsigned kc0, unsigned kc1,
    const float* p3bm, const float* p3bs, float* p3b, unsigned kd0, unsigned kd1) {
    int i = blockIdx.x * blockDim.x + threadIdx.x;
    if (i < 16384) {
        p3w[i] = fmaf(p3ws[i], tf_normal(kw0, kw1, (unsigned)i), p3wm[i]);
    } else if (i < 17408) {
        int l = i - 16384;
        preb[l] = fmaf(prebs[l], tf_normal(ka0, ka1, (unsigned)l), prebm[l]);
    } else if (i < 18432) {
        int l = i - 17408;
        p1b[l] = fmaf(p1bs[l], tf_normal(kb0, kb1, (unsigned)l), p1bm[l]);
    } else if (i < 19456) {
        int l = i - 18432;
        p2b[l] = fmaf(p2bs[l], tf_normal(kc0, kc1, (unsigned)l), p2bm[l]);
    } else if (i < 19472) {
        int l = i - 19456;
        p3b[l] = fmaf(p3bs[l], tf_normal(kd0, kd1, (unsigned)l), p3bm[l]);
    }
}

// ---------------- activations ----------------
__device__ inline float mishf(float x) {
    float sp = fmaxf(x, 0.0f) + log1pf(expf(-fabsf(x)));
    return x * tanhf(sp);
}
__device__ inline float sigmoidf_(float x) { return 1.0f / (1.0f + expf(-x)); }

__device__ __forceinline__ uint32_t h2u(__half2 v) {
    return *reinterpret_cast<uint32_t*>(&v);
}

// ---------------- fp32 -> fp16 hi/lo split (n4 = n/4) ----------------
__global__ void conv_split_kernel(const float* __restrict__ src,
                                  __half* __restrict__ hi,
                                  __half* __restrict__ lo, int n4) {
    int i = blockIdx.x * blockDim.x + threadIdx.x;
    if (i >= n4) return;
    float4 v = ((const float4*)src)[i];
    __half2 h0, h1, l0, l1;
    h0.x = __float2half_rn(v.x); h0.y = __float2half_rn(v.y);
    h1.x = __float2half_rn(v.z); h1.y = __float2half_rn(v.w);
    l0.x = __float2half_rn(v.x - __half2float(h0.x));
    l0.y = __float2half_rn(v.y - __half2float(h0.y));
    l1.x = __float2half_rn(v.z - __half2float(h1.x));
    l1.y = __float2half_rn(v.w - __half2float(h1.y));
    ((uint2*)hi)[i] = make_uint2(h2u(h0), h2u(h1));
    ((uint2*)lo)[i] = make_uint2(h2u(l0), h2u(l1));
}

// ---------------- mma / ldmatrix / cp.async wrappers ----------------
__device__ __forceinline__ void mma16816(float* c, const uint32_t* a, const uint32_t* b) {
    asm volatile(
        "mma.sync.aligned.m16n8k16.row.col.f32.f16.f16.f32 "
        "{%0,%1,%2,%3}, {%4,%5,%6,%7}, {%8,%9}, {%0,%1,%2,%3};\n"
        : "+f"(c[0]), "+f"(c[1]), "+f"(c[2]), "+f"(c[3])
        : "r"(a[0]), "r"(a[1]), "r"(a[2]), "r"(a[3]), "r"(b[0]), "r"(b[1]));
}
__device__ __forceinline__ void mma16816h(uint32_t* c, const uint32_t* a, const uint32_t* b) {
    asm volatile(
        "mma.sync.aligned.m16n8k16.row.col.f16.f16.f16.f16 "
        "{%0,%1}, {%2,%3,%4,%5}, {%6,%7}, {%0,%1};\n"
        : "+r"(c[0]), "+r"(c[1])
        : "r"(a[0]), "r"(a[1]), "r"(a[2]), "r"(a[3]), "r"(b[0]), "r"(b[1]));
}
__device__ __forceinline__ void ldsm4(uint32_t& r0, uint32_t& r1, uint32_t& r2, uint32_t& r3,
                                      uint32_t addr) {
    asm volatile("ldmatrix.sync.aligned.m8n8.x4.shared.b16 {%0,%1,%2,%3}, [%4];"
                 : "=r"(r0), "=r"(r1), "=r"(r2), "=r"(r3) : "r"(addr));
}
__device__ __forceinline__ uint32_t smem_u32(const void* p) {
    uint32_t a;
    asm("{ .reg .u64 t; cvta.to.shared.u64 t, %1; cvt.u32.u64 %0, t; }" : "=r"(a) : "l"(p));
    return a;
}
__device__ __forceinline__ void cp16(uint32_t saddr, const void* gptr) {
    asm volatile("cp.async.cg.shared.global [%0], [%1], 16;" :: "r"(saddr), "l"(gptr));
}
__device__ __forceinline__ void cp_commit() {
    asm volatile("cp.async.commit_group;" ::: "memory");
}
__device__ __forceinline__ void cp_wait1() {
    asm volatile("cp.async.wait_group 1;" ::: "memory");
}
__device__ __forceinline__ void cp_wait0() {
    asm volatile("cp.async.wait_group 0;" ::: "memory");
}

// ============ split-fp16 tensor-core GEMM: CTA 64x128, 8 warps 32x32 ============
// 3-stage cp.async ring, ONE __syncthreads per chunk.
#define PADE 40
#define OFF_AH 0
#define OFF_AL (64 * PADE)
#define OFF_BH (2 * 64 * PADE)
#define OFF_BL (2 * 64 * PADE + 128 * PADE)
#define BUFE (2 * 64 * PADE + 2 * 128 * PADE)
#define MMA_SMEM_BYTES (3 * BUFE * 2)

__global__ __launch_bounds__(256, 2) void mma_gemm_kernel(
    const __half* __restrict__ Ah, const __half* __restrict__ Al,
    const __half* __restrict__ Bh, const __half* __restrict__ Bl,
    const float* __restrict__ bias, float* __restrict__ C,
    __half* __restrict__ Ch, __half* __restrict__ Cl,
    int M, int N, int K, int act, int osplit) {
    extern __shared__ __half smb[];
    const uint32_t sbase = smem_u32(smb);
    const int tid = threadIdx.x;
    const int wid = tid >> 5, lane = tid & 31;
    const int r4 = lane >> 2, lq = lane & 3;
    const int m0 = blockIdx.y * 64, n0 = blockIdx.x * 128;
    const int wm = (wid & 1) * 32, wn = (wid >> 1) * 32;

    const int aro = lane & 15, ako = (lane >> 4) << 3;
    const int bro = (lane & 7) + ((lane >> 4) << 3), bko = ((lane >> 3) & 1) << 3;

    float acc[2][4][4] = {};
    uint32_t corr[2][4][2] = {};
    const int nch = K >> 5;

    const int ld_r = tid >> 2, ld_q = tid & 3;
    const uint32_t ld_e = (uint32_t)(ld_r * PADE + ld_q * 8) * 2;

#pragma unroll
    for (int c = 0; c < 2; c++) {
        const int k0 = c << 5;
        const uint32_t bb = sbase + (uint32_t)((c % 3) * BUFE * 2);
        {
            size_t goA = (size_t)(m0 + ld_r) * K + k0 + ld_q * 8;
            cp16(bb + OFF_AH * 2 + ld_e, Ah + goA);
            cp16(bb + OFF_AL * 2 + ld_e, Al + goA);
        }
#pragma unroll
        for (int q = 0; q < 2; q++) {
            int r = ld_r + 64 * q;
            uint32_t e = ld_e + (uint32_t)(64 * q * PADE) * 2;
            size_t goB = (size_t)(n0 + r) * K + k0 + ld_q * 8;
            cp16(bb + OFF_BH * 2 + e, Bh + goB);
            cp16(bb + OFF_BL * 2 + e, Bl + goB);
        }
        cp_commit();
    }

    for (int c = 0; c < nch; c++) {
        if (c + 1 < nch) cp_wait1(); else cp_wait0();
        __syncthreads();

        if (c + 2 < nch) {
            const int k0 = (c + 2) << 5;
            const uint32_t nb = sbase + (uint32_t)(((c + 2) % 3) * BUFE * 2);
            {
                size_t goA = (size_t)(m0 + ld_r) * K + k0 + ld_q * 8;
                cp16(nb + OFF_AH * 2 + ld_e, Ah + goA);
                cp16(nb + OFF_AL * 2 + ld_e, Al + goA);
            }
#pragma unroll
            for (int q = 0; q < 2; q++) {
                int r = ld_r + 64 * q;
                uint32_t e = ld_e + (uint32_t)(64 * q * PADE) * 2;
                size_t goB = (size_t)(n0 + r) * K + k0 + ld_q * 8;
                cp16(nb + OFF_BH * 2 + e, Bh + goB);
                cp16(nb + OFF_BL * 2 + e, Bl + goB);
            }
            cp_commit();
        }

        const uint32_t bb = sbase + (uint32_t)((c % 3) * BUFE * 2);
#pragma unroll
        for (int ks = 0; ks < 2; ks++) {
            uint32_t ahf[2][4], alf[2][4], bhf[4][2], blf[4][2];
#pragma unroll
            for (int am = 0; am < 2; am++) {
                uint32_t ar = (uint32_t)((wm + am * 16 + aro) * PADE + ks * 16 + ako) * 2;
                ldsm4(ahf[am][0], ahf[am][1], ahf[am][2], ahf[am][3], bb + OFF_AH * 2 + ar);
                ldsm4(alf[am][0], alf[am][1], alf[am][2], alf[am][3], bb + OFF_AL * 2 + ar);
            }
#pragma unroll
            for (int nb = 0; nb < 2; nb++) {
                uint32_t br = (uint32_t)((wn + nb * 16 + bro) * PADE + ks * 16 + bko) * 2;
                ldsm4(bhf[nb * 2][0], bhf[nb * 2][1], bhf[nb * 2 + 1][0], bhf[nb * 2 + 1][1],
                      bb + OFF_BH * 2 + br);
                ldsm4(blf[nb * 2][0], blf[nb * 2][1], blf[nb * 2 + 1][0], blf[nb * 2 + 1][1],
                      bb + OFF_BL * 2 + br);
            }
#pragma unroll
            for (int am = 0; am < 2; am++)
#pragma unroll
                for (int bn = 0; bn < 4; bn++) {
                    mma16816(acc[am][bn], ahf[am], bhf[bn]);
                    mma16816h(corr[am][bn], alf[am], bhf[bn]);
                    mma16816h(corr[am][bn], ahf[am], blf[bn]);
                }
        }
    }

#pragma unroll
    for (int am = 0; am < 2; am++) {
        const int row = m0 + wm + am * 16 + r4;
#pragma unroll
        for (int bn = 0; bn < 4; bn++) {
            const int col = n0 + wn + bn * 8 + 2 * lq;
            const float b0 = bias[col], b1 = bias[col + 1];
            float2 c01 = __half22float2(*reinterpret_cast<__half2*>(&corr[am][bn][0]));
            float2 c23 = __half22float2(*reinterpret_cast<__half2*>(&corr[am][bn][1]));
            float v0 = acc[am][bn][0] + c01.x + b0, v1 = acc[am][bn][1] + c01.y + b1;
            float v2 = acc[am][bn][2] + c23.x + b0, v3 = acc[am][bn][3] + c23.y + b1;
            if (act) { v0 = mishf(v0); v1 = mishf(v1); v2 = mishf(v2); v3 = mishf(v3); }
            if (osplit) {
                __half2 h01, h23, l01, l23;
                h01.x = __float2half_rn(v0); h01.y = __float2half_rn(v1);
                h23.x = __float2half_rn(v2); h23.y = __float2half_rn(v3);
                l01.x = __float2half_rn(v0 - __half2float(h01.x));
                l01.y = __float2half_rn(v1 - __half2float(h01.y));
                l23.x = __float2half_rn(v2 - __half2float(h23.x));
                l23.y = __float2half_rn(v3 - __half2float(h23.y));
                *(uint32_t*)(Ch + (size_t)row * N + col) = h2u(h01);
                *(uint32_t*)(Cl + (size_t)row * N + col) = h2u(l01);
                *(uint32_t*)(Ch + (size_t)(row + 8) * N + col) = h2u(h23);
                *(uint32_t*)(Cl + (size_t)(row + 8) * N + col) = h2u(l23);
            } else {
                *(float2*)(C + (size_t)row * N + col) = make_float2(v0, v1);
                *(float2*)(C + (size_t)(row + 8) * N + col) = make_float2(v2, v3);
            }
        }
    }
}

// ============ gather-GEMM for scan round k: hg[m,3072] = sth[order[base+m]-1] @ whh^T ============
__global__ __launch_bounds__(256, 2) void mma_ggemm_kernel(int kround) {
    extern __shared__ __half smb[];
    const int base = g_off[kround];
    const int R = g_off[kround + 1] - base;
    const int m0 = blockIdx.y * 64;
    if (m0 >= R) return;
    const uint32_t sbase = smem_u32(smb);
    const int tid = threadIdx.x;
    const int wid = tid >> 5, lane = tid & 31;
    const int r4 = lane >> 2, lq = lane & 3;
    const int n0 = blockIdx.x * 128;
    const int wm = (wid & 1) * 32, wn = (wid >> 1) * 32;
    const int K = HD, N = 3 * HD;

    const int aro = lane & 15, ako = (lane >> 4) << 3;
    const int bro = (lane & 7) + ((lane >> 4) << 3), bko = ((lane >> 3) & 1) << 3;

    float acc[2][4][4] = {};
    uint32_t corr[2][4][2] = {};
    const int nch = K >> 5;

    const int ld_r = tid >> 2, ld_q = tid & 3;
    const uint32_t ld_e = (uint32_t)(ld_r * PADE + ld_q * 8) * 2;
    const int gm = m0 + ld_r;
    const int myt = (gm < R) ? (g_order[base + gm] - 1) : (g_order[base] - 1);
    const __half* Ah = g_sth;
    const __half* Al = g_stl;
    const __half* Bh = g_whhh;
    const __half* Bl = g_whhl;

#pragma unroll
    for (int c = 0; c < 2; c++) {
        const int k0 = c << 5;
        const uint32_t bb = sbase + (uint32_t)((c % 3) * BUFE * 2);
        {
            size_t goA = (size_t)myt * K + k0 + ld_q * 8;
            cp16(bb + OFF_AH * 2 + ld_e, Ah + goA);
            cp16(bb + OFF_AL * 2 + ld_e, Al + goA);
        }
#pragma unroll
        for (int q = 0; q < 2; q++) {
            int r = ld_r + 64 * q;
            uint32_t e = ld_e + (uint32_t)(64 * q * PADE) * 2;
            size_t goB = (size_t)(n0 + r) * K + k0 + ld_q * 8;
            cp16(bb + OFF_BH * 2 + e, Bh + goB);
            cp16(bb + OFF_BL * 2 + e, Bl + goB);
        }
        cp_commit();
    }

    for (int c = 0; c < nch; c++) {
        if (c + 1 < nch) cp_wait1(); else cp_wait0();
        __syncthreads();

        if (c + 2 < nch) {
            const int k0 = (c + 2) << 5;
            const uint32_t nb = sbase + (uint32_t)(((c + 2) % 3) * BUFE * 2);
            {
                size_t goA = (size_t)myt * K + k0 + ld_q * 8;
                cp16(nb + OFF_AH * 2 + ld_e, Ah + goA);
                cp16(nb + OFF_AL * 2 + ld_e, Al + goA);
            }
#pragma unroll
            for (int q = 0; q < 2; q++) {
                int r = ld_r + 64 * q;
                uint32_t e = ld_e + (uint32_t)(64 * q * PADE) * 2;
                size_t goB = (size_t)(n0 + r) * K + k0 + ld_q * 8;
                cp16(nb + OFF_BH * 2 + e, Bh + goB);
                cp16(nb + OFF_BL * 2 + e, Bl + goB);
            }
            cp_commit();
        }

        const uint32_t bb = sbase + (uint32_t)((c % 3) * BUFE * 2);
#pragma unroll
        for (int ks = 0; ks < 2; ks++) {
            uint32_t ahf[2][4], alf[2][4], bhf[4][2], blf[4][2];
#pragma unroll
            for (int am = 0; am < 2; am++) {
                uint32_t ar = (uint32_t)((wm + am * 16 + aro) * PADE + ks * 16 + ako) * 2;
                ldsm4(ahf[am][0], ahf[am][1], ahf[am][2], ahf[am][3], bb + OFF_AH * 2 + ar);
                ldsm4(alf[am][0], alf[am][1], alf[am][2], alf[am][3], bb + OFF_AL * 2 + ar);
            }
#pragma unroll
            for (int nb = 0; nb < 2; nb++) {
                uint32_t br = (uint32_t)((wn + nb * 16 + bro) * PADE + ks * 16 + bko) * 2;
                ldsm4(bhf[nb * 2][0], bhf[nb * 2][1], bhf[nb * 2 + 1][0], bhf[nb * 2 + 1][1],
                      bb + OFF_BH * 2 + br);
                ldsm4(blf[nb * 2][0], blf[nb * 2][1], blf[nb * 2 + 1][0], blf[nb * 2 + 1][1],
                      bb + OFF_BL * 2 + br);
            }
#pragma unroll
            for (int am = 0; am < 2; am++)
#pragma unroll
                for (int bn = 0; bn < 4; bn++) {
                    mma16816(acc[am][bn], ahf[am], bhf[bn]);
                    mma16816h(corr[am][bn], alf[am], bhf[bn]);
                    mma16816h(corr[am][bn], ahf[am], blf[bn]);
                }
        }
    }

#pragma unroll
    for (int am = 0; am < 2; am++) {
        const int row = m0 + wm + am * 16 + r4;
#pragma unroll
        for (int bn = 0; bn < 4; bn++) {
            const int col = n0 + wn + bn * 8 + 2 * lq;
            float2 c01 = __half22float2(*reinterpret_cast<__half2*>(&corr[am][bn][0]));
            float2 c23 = __half22float2(*reinterpret_cast<__half2*>(&corr[am][bn][1]));
            if (row < R)
                *(float2*)(g_hg + (size_t)row * N + col) =
                    make_float2(acc[am][bn][0] + c01.x, acc[am][bn][1] + c01.y);
            if (row + 8 < R)
                *(float2*)(g_hg + (size_t)(row + 8) * N + col) =
                    make_float2(acc[am][bn][2] + c23.x, acc[am][bn][3] + c23.y);
        }
    }
}

__device__ __forceinline__ void store_state(int t, int j, float hnew, float* out) {
    g_states[(size_t)t * HD + j] = hnew;
    __half h = __float2half_rn(hnew);
    g_sth[(size_t)t * HD + j] = h;
    g_stl[(size_t)t * HD + j] = __float2half_rn(hnew - __half2float(h));
    if (t == T_STEPS - 1) out[(size_t)T_STEPS * ACTD + j] = hnew;
}

// pointwise gates for a GEMM round
__global__ __launch_bounds__(256) void gate_kernel(const float* __restrict__ gbn,
                                                   float* __restrict__ out, int kround) {
    const int base = g_off[kround];
    const int R = g_off[kround + 1] - base;
    const int idx = blockIdx.x * blockDim.x + threadIdx.x;
    if (idx >= R * HD) return;
    const int m = idx >> 10, j = idx & (HD - 1);
    const int t = g_order[base + m];
    const float* hg = g_hg + (size_t)m * (3 * HD);
    const float* igt = g_ig + (size_t)t * (3 * HD);
    float rv = sigmoidf_(igt[j] + hg[j]);
    float uv = sigmoidf_(igt[HD + j] + hg[HD + j]);
    float nv = tanhf(igt[2 * HD + j] + rv * (hg[2 * HD + j] + gbn[j]));
    float hin = g_states[(size_t)(t - 1) * HD + j];
    store_state(t, j, nv + uv * (hin - nv), out);
}

// ---------------- small SGEMM (p3, N=16) ----------------
__global__ __launch_bounds__(256) void sgemm64_kernel(
    const float* __restrict__ A, const float* __restrict__ B,
    const float* __restrict__ bias, float* __restrict__ C,
    int M, int N, int K) {
    __shared__ float As[16][64];
    __shared__ float Bs[16][64];
    const int m0 = blockIdx.y * 64;
    const int n0 = blockIdx.x * 64;
    const int tid = threadIdx.x;
    const int tx = tid & 15, ty = tid >> 4;
    const int lr = tid >> 2, lq = tid & 3;
    float acc[4][4] = {};
    for (int k0 = 0; k0 < K; k0 += 16) {
        float4 a4 = *(const float4*)(A + (size_t)(m0 + lr) * K + k0 + lq * 4);
        As[lq * 4 + 0][lr] = a4.x; As[lq * 4 + 1][lr] = a4.y;
        As[lq * 4 + 2][lr] = a4.z; As[lq * 4 + 3][lr] = a4.w;
        float4 b4 = make_float4(0.f, 0.f, 0.f, 0.f);
        if (n0 + lr < N) b4 = *(const float4*)(B + (size_t)(n0 + lr) * K + k0 + lq * 4);
        Bs[lq * 4 + 0][lr] = b4.x; Bs[lq * 4 + 1][lr] = b4.y;
        Bs[lq * 4 + 2][lr] = b4.z; Bs[lq * 4 + 3][lr] = b4.w;
        __syncthreads();
#pragma unroll
        for (int k = 0; k < 16; k++) {
            float4 av = *(const float4*)(&As[k][ty * 4]);
            float4 bv = *(const float4*)(&Bs[k][tx * 4]);
            float avs[4] = {av.x, av.y, av.z, av.w};
            float bvs[4] = {bv.x, bv.y, bv.z, bv.w};
#pragma unroll
            for (int i = 0; i < 4; i++)
#pragma unroll
                for (int jj = 0; jj < 4; jj++)
                    acc[i][jj] = fmaf(avs[i], bvs[jj], acc[i][jj]);
        }
        __syncthreads();
    }
#pragma unroll
    for (int i = 0; i < 4; i++) {
        int m = m0 + ty * 4 + i;
#pragma unroll
        for (int jj = 0; jj < 4; jj++) {
            int n = n0 + tx * 4 + jj;
            if (n < N) C[(size_t)m * N + n] = acc[i][jj] + (bias ? bias[n] : 0.0f);
        }
    }
}

// ---------------- prep: bucket timesteps by age within reset-segment ----------------
__global__ __launch_bounds__(1024) void prep_kernel(const int* __restrict__ start) {
    __shared__ int sa[2048], sb_[2048], sc[2048];
    __shared__ int skmax;
    const int tid = threadIdx.x;
    const int t0 = tid, t1 = tid + 1024;
    if (tid == 0) { g_bar = 0u; skmax = 0; }
    sa[t0] = start[t0] ? t0 : -1;
    sa[t1] = start[t1] ? t1 : -1;
    __syncthreads();
    int* src = sa; int* dst = sb_;
    for (int d = 1; d < 2048; d <<= 1) {
        int v0 = src[t0]; if (t0 >= d) v0 = max(v0, src[t0 - d]);
        int v1 = src[t1]; if (t1 >= d) v1 = max(v1, src[t1 - d]);
        dst[t0] = v0; dst[t1] = v1;
        __syncthreads();
        int* tmp = src; src = dst; dst = tmp;
    }
    int r0v = src[t0], r1v = src[t1];
    int age0 = (r0v < 0) ? t0 : t0 - r0v;
    int age1 = (r1v < 0) ? t1 : t1 - r1v;
    __syncthreads();
    sc[t0] = 0; sc[t1] = 0;
    __syncthreads();
    atomicAdd(&sc[age0], 1);
    atomicAdd(&sc[age1], 1);
    atomicMax(&skmax, max(age0, age1) + 1);
    __syncthreads();
    sa[t0] = sc[t0]; sa[t1] = sc[t1];
    __syncthreads();
    src = sa; dst = sb_;
    for (int d = 1; d < 2048; d <<= 1) {
        int v0 = src[t0]; if (t0 >= d) v0 += src[t0 - d];
        int v1 = src[t1]; if (t1 >= d) v1 += src[t1 - d];
        dst[t0] = v0; dst[t1] = v1;
        __syncthreads();
        int* tmp = src; src = dst; dst = tmp;
    }
    if (tid == 0) { g_off[0] = 0; g_kmax = skmax; }
    g_off[t0 + 1] = src[t0];
    g_off[t1 + 1] = src[t1];
    sc[t0] = 0; sc[t1] = 0;
    __syncthreads();
    int base0 = (age0 == 0) ? 0 : src[age0 - 1];
    g_order[base0 + atomicAdd(&sc[age0], 1)] = t0;
    int base1 = (age1 == 0) ? 0 : src[age1 - 1];
    g_order[base1 + atomicAdd(&sc[age1], 1)] = t1;
}

// ---------------- grid barrier ----------------
__device__ inline void grid_bar(unsigned* barp, unsigned target) {
    __syncthreads();
    if (threadIdx.x == 0) {
        asm volatile("red.release.gpu.global.add.u32 [%0], %1;" :: "l"(barp), "r"(1u) : "memory");
        unsigned v;
        do {
            asm volatile("ld.acquire.gpu.global.u32 %0, [%1];" : "=r"(v) : "l"(barp) : "memory");
        } while (v < target);
    }
    __syncthreads();
}

// ---------------- round 0: t=0 full matvec + start rows closed-form ----------------
__global__ __launch_bounds__(256, 1) void round0_kernel(
    const float* __restrict__ whh, const float* __restrict__ gbn,
    const int* __restrict__ start, const float* __restrict__ state,
    float* __restrict__ out) {
    __shared__ float sH[HD];
    const int tid = threadIdx.x;
    const int w = tid >> 5, lane = tid & 31;
    const int j = blockIdx.x * 8 + w;
    const float bnj = gbn[j];
    const int s0 = start[0];

    if (s0 == 0) {
        ((float4*)sH)[tid] = ((const float4*)state)[tid];
        __syncthreads();
        const float4* w4 = (const float4*)whh;
        float ir = 0.f, iz = 0.f, inn = 0.f;
        if (lane == 0) { ir = g_ig[j]; iz = g_ig[HD + j]; inn = g_ig[2 * HD + j]; }
        float aR = 0.f, aZ = 0.f, aN = 0.f;
#pragma unroll
        for (int q = 0; q < 8; q++) {
            float4 h4 = ((const float4*)sH)[lane + 32 * q];
            float4 r4v = w4[(size_t)(0 * HD + j) * 256 + lane + 32 * q];
            float4 z4v = w4[(size_t)(1 * HD + j) * 256 + lane + 32 * q];
            float4 n4v = w4[(size_t)(2 * HD + j) * 256 + lane + 32 * q];
            aR = fmaf(h4.x, r4v.x, fmaf(h4.y, r4v.y, fmaf(h4.z, r4v.z, fmaf(h4.w, r4v.w, aR))));
            aZ = fmaf(h4.x, z4v.x, fmaf(h4.y, z4v.y, fmaf(h4.z, z4v.z, fmaf(h4.w, z4v.w, aZ))));
            aN = fmaf(h4.x, n4v.x, fmaf(h4.y, n4v.y, fmaf(h4.z, n4v.z, fmaf(h4.w, n4v.w, aN))));
        }
#pragma unroll
        for (int off = 16; off; off >>= 1) {
            aR += __shfl_xor_sync(0xffffffffu, aR, off);
            aZ += __shfl_xor_sync(0xffffffffu, aZ, off);
            aN += __shfl_xor_sync(0xffffffffu, aN, off);
        }
        if (lane == 0) {
            float rv = sigmoidf_(ir + aR);
            float uv = sigmoidf_(iz + aZ);
            float nv = tanhf(inn + rv * (aN + bnj));
            float hin = sH[j];
            store_state(0, j, nv + uv * (hin - nv), out);
        }
    }
    {
        const int beg = g_off[0], end = g_off[1];
        for (int r = beg + lane; r < end; r += 32) {
            const int t = g_order[r];
            if (t == 0 && s0 == 0) continue;
            const float* igt = g_ig + (size_t)t * (3 * HD);
            float rv = sigmoidf_(igt[j]);
            float uv = sigmoidf_(igt[HD + j]);
            float nv = tanhf(igt[2 * HD + j] + rv * bnj);
            store_state(t, j, nv - uv * nv, out);
        }
    }
}

// ---------------- cleanup scan: rounds kstart..kmax (tiny tails), 4 rows/iter ----------------
__global__ __launch_bounds__(256, 1) void cleanup_scan_kernel(
    const float* __restrict__ whh, const float* __restrict__ gbn,
    float* __restrict__ out, int kstart) {
    __shared__ float sH[4][HD];
    const int tid = threadIdx.x;
    const int w = tid >> 5, lane = tid & 31;
    const int j = blockIdx.x * 8 + w;
    const int kmax = g_kmax;
    if (kstart >= kmax) return;

    const float4* w4 = (const float4*)whh;
    float4 wr[8], wz[8], wn[8];
#pragma unroll
    for (int q = 0; q < 8; q++) {
        wr[q] = w4[(size_t)(0 * HD + j) * 256 + lane + 32 * q];
        wz[q] = w4[(size_t)(1 * HD + j) * 256 + lane + 32 * q];
        wn[q] = w4[(size_t)(2 * HD + j) * 256 + lane + 32 * q];
    }
    const float bnj = gbn[j];
    unsigned* barp = &g_bar;
    unsigned epoch = 0;

    for (int k = kstart; k < kmax; k++) {
        const int beg = g_off[k], end = g_off[k + 1];
        int r = beg;
        int tt[4] = {-1, -1, -1, -1};
        float4 nx[4];
#pragma unroll
        for (int i = 0; i < 4; i++) {
            if (r + i < end) {
                tt[i] = g_order[r + i];
                nx[i] = __ldcg((const float4*)(g_states + (size_t)(tt[i] - 1) * HD) + tid);
            }
        }

        while (r < end) {
            int cur[4];
#pragma unroll
            for (int i = 0; i < 4; i++) cur[i] = tt[i];
            if (cur[0] >= 0) ((float4*)sH[0])[tid] = nx[0];
            if (cur[1] >= 0) ((float4*)sH[1])[tid] = nx[1];
            if (cur[2] >= 0) ((float4*)sH[2])[tid] = nx[2];
            if (cur[3] >= 0) ((float4*)sH[3])[tid] = nx[3];
            __syncthreads();

            const int rn = r + 4;
#pragma unroll
            for (int i = 0; i < 4; i++) {
                tt[i] = -1;
                if (rn + i < end) {
                    tt[i] = g_order[rn + i];
                    nx[i] = __ldcg((const float4*)(g_states + (size_t)(tt[i] - 1) * HD) + tid);
                }
            }

            float ir = 0.f, iz = 0.f, inn = 0.f;
            int myt = -1;
            if (lane < 4) {
                myt = cur[lane];
                if (myt >= 0) {
                    const float* igt = g_ig + (size_t)myt * (3 * HD);
                    ir = igt[j]; iz = igt[HD + j]; inn = igt[2 * HD + j];
                }
            }

            float aR[4] = {}, aZ[4] = {}, aN[4] = {};
#pragma unroll
            for (int q = 0; q < 8; q++) {
                const int c = lane + 32 * q;
                float4 r4v = wr[q], z4v = wz[q], n4v = wn[q];
#pragma unroll
                for (int i = 0; i < 4; i++) {
                    float4 h4 = ((const float4*)sH[i])[c];
                    aR[i] = fmaf(h4.x, r4v.x, fmaf(h4.y, r4v.y, fmaf(h4.z, r4v.z, fmaf(h4.w, r4v.w, aR[i]))));
                    aZ[i] = fmaf(h4.x, z4v.x, fmaf(h4.y, z4v.y, fmaf(h4.z, z4v.z, fmaf(h4.w, z4v.w, aZ[i]))));
                    aN[i] = fmaf(h4.x, n4v.x, fmaf(h4.y, n4v.y, fmaf(h4.z, n4v.z, fmaf(h4.w, n4v.w, aN[i]))));
                }
            }
#pragma unroll
            for (int off = 16; off; off >>= 1) {
#pragma unroll
                for (int i = 0; i < 4; i++) {
                    aR[i] += __shfl_xor_sync(0xffffffffu, aR[i], off);
                    aZ[i] += __shfl_xor_sync(0xffffffffu, aZ[i], off);
                    aN[i] += __shfl_xor_sync(0xffffffffu, aN[i], off);
                }
            }
            if (lane < 4 && myt >= 0) {
                float rv = sigmoidf_(ir + aR[lane]);
                float uv = sigmoidf_(iz + aZ[lane]);
                float nv = tanhf(inn + rv * (aN[lane] + bnj));
                float hin = sH[lane][j];
                store_state(myt, j, nv + uv * (hin - nv), out);
            }
            __syncthreads();
            r = rn;
        }
        grid_bar(barp, (++epoch) * SCAN_BLOCKS);
    }
}

// ---------------- launch ----------------
extern "C" void kernel_launch(void* const* d_in, const int* in_sizes, int n_in,
                              void* d_out, int out_size) {
    (void)in_sizes; (void)n_in;
    const float* x      = (const float*)d_in[0];
    const float* state  = (const float*)d_in[1];
    const int*   start  = (const int*)d_in[2];
    const float* pre_wm = (const float*)d_in[4];
    const float* pre_ws = (const float*)d_in[5];
    const float* pre_bm = (const float*)d_in[6];
    const float* pre_bs = (const float*)d_in[7];
    const float* wih    = (const float*)d_in[8];
    const float* whh    = (const float*)d_in[9];
    const float* gru_b  = (const float*)d_in[10];
    const float* gru_bn = (const float*)d_in[11];
    const float* p1_wm  = (const float*)d_in[12];
    const float* p1_ws  = (const float*)d_in[13];
    const float* p1_bm  = (const float*)d_in[14];
    const float* p1_bs  = (const float*)d_in[15];
    const float* p2_wm  = (const float*)d_in[16];
    const float* p2_ws  = (const float*)d_in[17];
    const float* p2_bm  = (const float*)d_in[18];
    const float* p2_bs  = (const float*)d_in[19];
    const float* p3_wm  = (const float*)d_in[20];
    const float* p3_ws  = (const float*)d_in[21];
    const float* p3_bm  = (const float*)d_in[22];
    const float* p3_bs  = (const float*)d_in[23];
    float* out = (float*)d_out;
    (void)out_size;

    unsigned nk[8][2];
    for (int i = 0; i < 8; i++) {
        unsigned a = 0u, b = (unsigned)i;
        tf_block(0u, 7u, a, b);
        nk[i][0] = a; nk[i][1] = b;
    }

    float *preB, *p1B, *p2B, *p3W, *p3B, *ig, *states, *y2;
    __half *xh, *xl, *preWh, *preWl, *wihh, *wihl, *whhh, *whhl, *p1Wh, *p1Wl, *p2Wh, *p2Wl;
    __half *zh, *zl, *sth, *stl, *y1h, *y1l;
    cudaGetSymbolAddress((void**)&preB, g_preB);
    cudaGetSymbolAddress((void**)&p1B, g_p1B);
    cudaGetSymbolAddress((void**)&p2B, g_p2B);
    cudaGetSymbolAddress((void**)&p3W, g_p3W);
    cudaGetSymbolAddress((void**)&p3B, g_p3B);
    cudaGetSymbolAddress((void**)&ig, g_ig);
    cudaGetSymbolAddress((void**)&states, g_states);
    cudaGetSymbolAddress((void**)&y2, g_y2);
    cudaGetSymbolAddress((void**)&xh, g_xh);
    cudaGetSymbolAddress((void**)&xl, g_xl);
    cudaGetSymbolAddress((void**)&preWh, g_preWh);
    cudaGetSymbolAddress((void**)&preWl, g_preWl);
    cudaGetSymbolAddress((void**)&wihh, g_wihh);
    cudaGetSymbolAddress((void**)&wihl, g_wihl);
    cudaGetSymbolAddress((void**)&whhh, g_whhh);
    cudaGetSymbolAddress((void**)&whhl, g_whhl);
    cudaGetSymbolAddress((void**)&p1Wh, g_p1Wh);
    cudaGetSymbolAddress((void**)&p1Wl, g_p1Wl);
    cudaGetSymbolAddress((void**)&p2Wh, g_p2Wh);
    cudaGetSymbolAddress((void**)&p2Wl, g_p2Wl);
    cudaGetSymbolAddress((void**)&zh, g_zh);
    cudaGetSymbolAddress((void**)&zl, g_zl);
    cudaGetSymbolAddress((void**)&sth, g_sth);
    cudaGetSymbolAddress((void**)&stl, g_stl);
    cudaGetSymbolAddress((void**)&y1h, g_y1h);
    cudaGetSymbolAddress((void**)&y1l, g_y1l);

    cudaFuncSetAttribute(mma_gemm_kernel, cudaFuncAttributeMaxDynamicSharedMemorySize,
                         MMA_SMEM_BYTES);
    cudaFuncSetAttribute(mma_ggemm_kernel, cudaFuncAttributeMaxDynamicSharedMemorySize,
                         MMA_SMEM_BYTES);

    static cudaStream_t sB = nullptr;
    static cudaEvent_t evFork, evPre, evWih, evWhh, evPrep, evP1, evP2;
    if (sB == nullptr) {
        cudaStreamCreateWithFlags(&sB, cudaStreamNonBlocking);
        cudaEventCreateWithFlags(&evFork, cudaEventDisableTiming);
        cudaEventCreateWithFlags(&evPre, cudaEventDisableTiming);
        cudaEventCreateWithFlags(&evWih, cudaEventDisableTiming);
        cudaEventCreateWithFlags(&evWhh, cudaEventDisableTiming);
        cudaEventCreateWithFlags(&evPrep, cudaEventDisableTiming);
        cudaEventCreateWithFlags(&evP1, cudaEventDisableTiming);
        cudaEventCreateWithFlags(&evP2, cudaEventDisableTiming);
    }

    cudaEventRecord(evFork, 0);
    cudaStreamWaitEvent(sB, evFork, 0);

    // main: x split
    conv_split_kernel<<<(T_STEPS * OBS / 4 + 255) / 256, 256>>>(x, xh, xl, T_STEPS * OBS / 4);
    // side: pre noise + small noise
    { int n = MLPD * OBS; gen_noisy_w_kernel<<<(n + 255) / 256, 256, 0, sB>>>(pre_wm, pre_ws, preWh, preWl, n, nk[0][0], nk[0][1]); }
    gen_small_kernel<<<(19472 + 255) / 256, 256, 0, sB>>>(
        p3_wm, p3_ws, p3W, nk[6][0], nk[6][1],
        pre_bm, pre_bs, preB, nk[1][0], nk[1][1],
        p1_bm, p1_bs, p1B, nk[3][0], nk[3][1],
        p2_bm, p2_bs, p2B, nk[5][0], nk[5][1],
        p3_bm, p3_bs, p3B, nk[7][0], nk[7][1]);
    cudaEventRecord(evPre, sB);

    // main: GEMM1
    cudaStreamWaitEvent(0, evPre, 0);
    mma_gemm_kernel<<<dim3(MLPD / 128, T_STEPS / 64), 256, MMA_SMEM_BYTES>>>(
        xh, xl, preWh, preWl, preB, nullptr, zh, zl, T_STEPS, MLPD, OBS, 1, 1);

    // side: wih split, whh split, prep (all overlap GEMM1/2)
    conv_split_kernel<<<(3 * HD * MLPD / 4 + 255) / 256, 256, 0, sB>>>(wih, wihh, wihl, 3 * HD * MLPD / 4);
    cudaEventRecord(evWih, sB);
    conv_split_kernel<<<(3 * HD * MLPD / 4 + 255) / 256, 256, 0, sB>>>(whh, whhh, whhl, 3 * HD * MLPD / 4);
    cudaEventRecord(evWhh, sB);
    prep_kernel<<<1, 1024, 0, sB>>>(start);
    cudaEventRecord(evPrep, sB);

    // main: GEMM2
    cudaStreamWaitEvent(0, evWih, 0);
    mma_gemm_kernel<<<dim3(3 * HD / 128, T_STEPS / 64), 256, MMA_SMEM_BYTES>>>(
        zh, zl, wihh, wihl, gru_b, ig, nullptr, nullptr, T_STEPS, 3 * HD, MLPD, 0, 0);

    // side: p1/p2 noise (overlaps GEMM2 + scan rounds)
    { int n = MLPD * HD;   gen_noisy_w_kernel<<<(n + 255) / 256, 256, 0, sB>>>(p1_wm, p1_ws, p1Wh, p1Wl, n, nk[2][0], nk[2][1]); }
    cudaEventRecord(evP1, sB);
    { int n = MLPD * MLPD; gen_noisy_w_kernel<<<(n + 255) / 256, 256, 0, sB>>>(p2_wm, p2_ws, p2Wh, p2Wl, n, nk[4][0], nk[4][1]); }
    cudaEventRecord(evP2, sB);

    // main: round 0
    cudaStreamWaitEvent(0, evPrep, 0);
    round0_kernel<<<SCAN_BLOCKS, 256>>>(whh, gru_bn, start, state, out);

    // main: GEMM rounds 1..KGEMM
    cudaStreamWaitEvent(0, evWhh, 0);
    for (int k = 1; k <= KGEMM; k++) {
        mma_ggemm_kernel<<<dim3(3 * HD / 128, T_STEPS / 64), 256, MMA_SMEM_BYTES>>>(k);
        gate_kernel<<<(T_STEPS * HD) / 256, 256>>>(gru_bn, out, k);
    }

    // main: cleanup scan for rounds > KGEMM
    cleanup_scan_kernel<<<SCAN_BLOCKS, 256>>>(whh, gru_bn, out, KGEMM + 1);

    // main: GEMM3
    cudaStreamWaitEvent(0, evP1, 0);
    mma_gemm_kernel<<<dim3(MLPD / 128, T_STEPS / 64), 256, MMA_SMEM_BYTES>>>(
        sth, stl, p1Wh, p1Wl, p1B, nullptr, y1h, y1l, T_STEPS, MLPD, HD, 1, 1);

    // main: GEMM4
    cudaStreamWaitEvent(0, evP2, 0);
    mma_gemm_kernel<<<dim3(MLPD / 128, T_STEPS / 64), 256, MMA_SMEM_BYTES>>>(
        y1h, y1l, p2Wh, p2Wl, p2B, y2, nullptr, nullptr, T_STEPS, MLPD, MLPD, 1, 0);

    // main: final layer -> d_out[0 : 2048*16]
    sgemm64_kernel<<<dim3(1, T_STEPS / 64), 256>>>(y2, p3W, p3B, out, T_STEPS, ACTD, MLPD);
}

// round 16
// speedup vs baseline: 1.7373x; 1.0741x over previous
#include <cuda_runtime.h>
#include <cuda_fp16.h>
#include <cstdint>

#define T_STEPS 2048
#define OBS 512
#define MLPD 1024
#define HD 1024
#define ACTD 16
#define SCAN_BLOCKS 128
#define KGEMM 4

// ---------------- device scratch (no allocations allowed) ----------------
__device__ float g_preB[MLPD];
__device__ float g_p1B[MLPD];
__device__ float g_p2B[MLPD];
__device__ float g_p3W[ACTD * MLPD];
__device__ float g_p3B[ACTD];
__device__ float g_ig[(size_t)T_STEPS * 3 * HD];
__device__ float g_states[(size_t)T_STEPS * HD];
__device__ float g_hg[4][(size_t)1024 * 3 * HD];  // split-K partials
__device__ float g_y2[T_STEPS * MLPD];
__device__ __half g_xh[T_STEPS * OBS],  g_xl[T_STEPS * OBS];
__device__ __half g_preWh[MLPD * OBS],  g_preWl[MLPD * OBS];
__device__ __half g_wihh[3 * HD * MLPD], g_wihl[3 * HD * MLPD];
__device__ __half g_whhh[3 * HD * MLPD], g_whhl[3 * HD * MLPD];
__device__ __half g_p1Wh[MLPD * HD],    g_p1Wl[MLPD * HD];
__device__ __half g_p2Wh[MLPD * MLPD],  g_p2Wl[MLPD * MLPD];
__device__ __half g_zh[T_STEPS * MLPD], g_zl[T_STEPS * MLPD];
__device__ __half g_sth[(size_t)T_STEPS * HD], g_stl[(size_t)T_STEPS * HD];
__device__ __half g_y1h[T_STEPS * MLPD], g_y1l[T_STEPS * MLPD];
__device__ unsigned g_bar;
__device__ int g_order[T_STEPS];
__device__ int g_off[T_STEPS + 1];
__device__ int g_kmax;

// ---------------- threefry2x32 (matches JAX) ----------------
#define TF_ROUND(x0, x1, R) { x0 += x1; x1 = (x1 << R) | (x1 >> (32 - R)); x1 ^= x0; }

__host__ __device__ inline void tf_block(unsigned k0, unsigned k1, unsigned &x0, unsigned &x1) {
    unsigned ks2 = k0 ^ k1 ^ 0x1BD11BDAu;
    x0 += k0; x1 += k1;
    TF_ROUND(x0, x1, 13) TF_ROUND(x0, x1, 15) TF_ROUND(x0, x1, 26) TF_ROUND(x0, x1, 6)
    x0 += k1; x1 += ks2 + 1u;
    TF_ROUND(x0, x1, 17) TF_ROUND(x0, x1, 29) TF_ROUND(x0, x1, 16) TF_ROUND(x0, x1, 24)
    x0 += ks2; x1 += k0 + 2u;
    TF_ROUND(x0, x1, 13) TF_ROUND(x0, x1, 15) TF_ROUND(x0, x1, 26) TF_ROUND(x0, x1, 6)
    x0 += k0; x1 += k1 + 3u;
    TF_ROUND(x0, x1, 17) TF_ROUND(x0, x1, 29) TF_ROUND(x0, x1, 16) TF_ROUND(x0, x1, 24)
    x0 += k1; x1 += ks2 + 4u;
    TF_ROUND(x0, x1, 13) TF_ROUND(x0, x1, 15) TF_ROUND(x0, x1, 26) TF_ROUND(x0, x1, 6)
    x0 += ks2; x1 += k0 + 5u;
}

// XLA f32 erf_inv (Giles)
__device__ inline float xla_erfinv(float x) {
    float w = -log1pf(-x * x);
    float p;
    if (w < 5.0f) {
        w -= 2.5f;
        p = 2.81022636e-08f;
        p = fmaf(p, w, 3.43273939e-07f);
        p = fmaf(p, w, -3.5233877e-06f);
        p = fmaf(p, w, -4.39150654e-06f);
        p = fmaf(p, w, 0.00021858087f);
        p = fmaf(p, w, -0.00125372503f);
        p = fmaf(p, w, -0.00417768164f);
        p = fmaf(p, w, 0.246640727f);
        p = fmaf(p, w, 1.50140941f);
    } else {
        w = sqrtf(w) - 3.0f;
        p = -0.000200214257f;
        p = fmaf(p, w, 0.000100950558f);
        p = fmaf(p, w, 0.00134934322f);
        p = fmaf(p, w, -0.00367342844f);
        p = fmaf(p, w, 0.00573950773f);
        p = fmaf(p, w, -0.0076224613f);
        p = fmaf(p, w, 0.00943887047f);
        p = fmaf(p, w, 1.00167406f);
        p = fmaf(p, w, 2.83297682f);
    }
    return p * x;
}

__device__ inline float bits_to_normal(unsigned b) {
    float u1 = __uint_as_float((b >> 9) | 0x3f800000u) - 1.0f;
    float v = fmaf(u1, 1.99999994f, -0.99999994f);
    v = fmaxf(v, -0.99999994f);
    return 1.41421356f * xla_erfinv(v);
}

__device__ inline float tf_normal(unsigned k0, unsigned k1, unsigned i) {
    unsigned x0 = 0u, x1 = i;
    tf_block(k0, k1, x0, x1);
    return bits_to_normal(x0 ^ x1);
}

__global__ void gen_noisy_w_kernel(const float* __restrict__ wm, const float* __restrict__ ws,
                                   __half* __restrict__ hi, __half* __restrict__ lo,
                                   int n, unsigned k0, unsigned k1) {
    int i = blockIdx.x * blockDim.x + threadIdx.x;
    if (i >= n) return;
    float v = fmaf(ws[i], tf_normal(k0, k1, (unsigned)i), wm[i]);
    __half h = __float2half_rn(v);
    hi[i] = h;
    lo[i] = __float2half_rn(v - __half2float(h));
}

__global__ void gen_small_kernel(
    const float* p3wm, const float* p3ws, float* p3w, unsigned kw0, unsigned kw1,
    const float* prebm, const float* prebs, float* preb, unsigned ka0, unsigned ka1,
    const float* p1bm, const float* p1bs, float* p1b, unsigned kb0, unsigned kb1,
    const float* p2bm, const float* p2bs, float* p2b, unsigned kc0, unsigned kc1,
    const float* p3bm, const float* p3bs, float* p3b, unsigned kd0, unsigned kd1) {
    int i = blockIdx.x * blockDim.x + threadIdx.x;
    if (i < 16384) {
        p3w[i] = fmaf(p3ws[i], tf_normal(kw0, kw1, (unsigned)i), p3wm[i]);
    } else if (i < 17408) {
        int l = i - 16384;
        preb[l] = fmaf(prebs[l], tf_normal(ka0, ka1, (unsigned)l), prebm[l]);
    } else if (i < 18432) {
        int l = i - 17408;
        p1b[l] = fmaf(p1bs[l], tf_normal(kb0, kb1, (unsigned)l), p1bm[l]);
    } else if (i < 19456) {
        int l = i - 18432;
        p2b[l] = fmaf(p2bs[l], tf_normal(kc0, kc1, (unsigned)l), p2bm[l]);
    } else if (i < 19472) {
        int l = i - 19456;
        p3b[l] = fmaf(p3bs[l], tf_normal(kd0, kd1, (unsigned)l), p3bm[l]);
    }
}

// ---------------- activations ----------------
__device__ inline float mishf(float x) {
    float sp = fmaxf(x, 0.0f) + log1pf(expf(-fabsf(x)));
    return x * tanhf(sp);
}
__device__ inline float sigmoidf_(float x) { return 1.0f / (1.0f + expf(-x)); }

__device__ __forceinline__ uint32_t h2u(__half2 v) {
    return *reinterpret_cast<uint32_t*>(&v);
}

// ---------------- fp32 -> fp16 hi/lo split (n4 = n/4) ----------------
__global__ void conv_split_kernel(const float* __restrict__ src,
                                  __half* __restrict__ hi,
                                  __half* __restrict__ lo, int n4) {
    int i = blockIdx.x * blockDim.x + threadIdx.x;
    if (i >= n4) return;
    float4 v = ((const float4*)src)[i];
    __half2 h0, h1, l0, l1;
    h0.x = __float2half_rn(v.x); h0.y = __float2half_rn(v.y);
    h1.x = __float2half_rn(v.z); h1.y = __float2half_rn(v.w);
    l0.x = __float2half_rn(v.x - __half2float(h0.x));
    l0.y = __float2half_rn(v.y - __half2float(h0.y));
    l1.x = __float2half_rn(v.z - __half2float(h1.x));
    l1.y = __float2half_rn(v.w - __half2float(h1.y));
    ((uint2*)hi)[i] = make_uint2(h2u(h0), h2u(h1));
    ((uint2*)lo)[i] = make_uint2(h2u(l0), h2u(l1));
}

// ---------------- mma / ldmatrix / cp.async wrappers ----------------
__device__ __forceinline__ void mma16816(float* c, const uint32_t* a, const uint32_t* b) {
    asm volatile(
        "mma.sync.aligned.m16n8k16.row.col.f32.f16.f16.f32 "
        "{%0,%1,%2,%3}, {%4,%5,%6,%7}, {%8,%9}, {%0,%1,%2,%3};\n"
        : "+f"(c[0]), "+f"(c[1]), "+f"(c[2]), "+f"(c[3])
        : "r"(a[0]), "r"(a[1]), "r"(a[2]), "r"(a[3]), "r"(b[0]), "r"(b[1]));
}
__device__ __forceinline__ void mma16816h(uint32_t* c, const uint32_t* a, const uint32_t* b) {
    asm volatile(
        "mma.sync.aligned.m16n8k16.row.col.f16.f16.f16.f16 "
        "{%0,%1}, {%2,%3,%4,%5}, {%6,%7}, {%0,%1};\n"
        : "+r"(c[0]), "+r"(c[1])
        : "r"(a[0]), "r"(a[1]), "r"(a[2]), "r"(a[3]), "r"(b[0]), "r"(b[1]));
}
__device__ __forceinline__ void ldsm4(uint32_t& r0, uint32_t& r1, uint32_t& r2, uint32_t& r3,
                                      uint32_t addr) {
    asm volatile("ldmatrix.sync.aligned.m8n8.x4.shared.b16 {%0,%1,%2,%3}, [%4];"
                 : "=r"(r0), "=r"(r1), "=r"(r2), "=r"(r3) : "r"(addr));
}
__device__ __forceinline__ uint32_t smem_u32(const void* p) {
    uint32_t a;
    asm("{ .reg .u64 t; cvta.to.shared.u64 t, %1; cvt.u32.u64 %0, t; }" : "=r"(a) : "l"(p));
    return a;
}
__device__ __forceinline__ void cp16(uint32_t saddr, const void* gptr) {
    asm volatile("cp.async.cg.shared.global [%0], [%1], 16;" :: "r"(saddr), "l"(gptr));
}
__device__ __forceinline__ void cp_commit() {
    asm volatile("cp.async.commit_group;" ::: "memory");
}
__device__ __forceinline__ void cp_wait1() {
    asm volatile("cp.async.wait_group 1;" ::: "memory");
}
__device__ __forceinline__ void cp_wait0() {
    asm volatile("cp.async.wait_group 0;" ::: "memory");
}

// ============ split-fp16 tensor-core GEMM: CTA 64x128, 8 warps 32x32 ============
// 3-stage cp.async ring, one __syncthreads per chunk.
#define PADE 40
#define OFF_AH 0
#define OFF_AL (64 * PADE)
#define OFF_BH (2 * 64 * PADE)
#define OFF_BL (2 * 64 * PADE + 128 * PADE)
#define BUFE (2 * 64 * PADE + 2 * 128 * PADE)
#define MMA_SMEM_BYTES (3 * BUFE * 2)

__global__ __launch_bounds__(256, 2) void mma_gemm_kernel(
    const __half* __restrict__ Ah, const __half* __restrict__ Al,
    const __half* __restrict__ Bh, const __half* __restrict__ Bl,
    const float* __restrict__ bias, float* __restrict__ C,
    __half* __restrict__ Ch, __half* __restrict__ Cl,
    int M, int N, int K, int act, int osplit) {
    extern __shared__ __half smb[];
    const uint32_t sbase = smem_u32(smb);
    const int tid = threadIdx.x;
    const int wid = tid >> 5, lane = tid & 31;
    const int r4 = lane >> 2, lq = lane & 3;
    const int m0 = blockIdx.y * 64, n0 = blockIdx.x * 128;
    const int wm = (wid & 1) * 32, wn = (wid >> 1) * 32;

    const int aro = lane & 15, ako = (lane >> 4) << 3;
    const int bro = (lane & 7) + ((lane >> 4) << 3), bko = ((lane >> 3) & 1) << 3;

    float acc[2][4][4] = {};
    uint32_t corr[2][4][2] = {};
    const int nch = K >> 5;

    const int ld_r = tid >> 2, ld_q = tid & 3;
    const uint32_t ld_e = (uint32_t)(ld_r * PADE + ld_q * 8) * 2;

#pragma unroll
    for (int c = 0; c < 2; c++) {
        const int k0 = c << 5;
        const uint32_t bb = sbase + (uint32_t)((c % 3) * BUFE * 2);
        {
            size_t goA = (size_t)(m0 + ld_r) * K + k0 + ld_q * 8;
            cp16(bb + OFF_AH * 2 + ld_e, Ah + goA);
            cp16(bb + OFF_AL * 2 + ld_e, Al + goA);
        }
#pragma unroll
        for (int q = 0; q < 2; q++) {
            int r = ld_r + 64 * q;
            uint32_t e = ld_e + (uint32_t)(64 * q * PADE) * 2;
            size_t goB = (size_t)(n0 + r) * K + k0 + ld_q * 8;
            cp16(bb + OFF_BH * 2 + e, Bh + goB);
            cp16(bb + OFF_BL * 2 + e, Bl + goB);
        }
        cp_commit();
    }

    for (int c = 0; c < nch; c++) {
        if (c + 1 < nch) cp_wait1(); else cp_wait0();
        __syncthreads();

        if (c + 2 < nch) {
            const int k0 = (c + 2) << 5;
            const uint32_t nb = sbase + (uint32_t)(((c + 2) % 3) * BUFE * 2);
            {
                size_t goA = (size_t)(m0 + ld_r) * K + k0 + ld_q * 8;
                cp16(nb + OFF_AH * 2 + ld_e, Ah + goA);
                cp16(nb + OFF_AL * 2 + ld_e, Al + goA);
            }
#pragma unroll
            for (int q = 0; q < 2; q++) {
                int r = ld_r + 64 * q;
                uint32_t e = ld_e + (uint32_t)(64 * q * PADE) * 2;
                size_t goB = (size_t)(n0 + r) * K + k0 + ld_q * 8;
                cp16(nb + OFF_BH * 2 + e, Bh + goB);
                cp16(nb + OFF_BL * 2 + e, Bl + goB);
            }
            cp_commit();
        }

        const uint32_t bb = sbase + (uint32_t)((c % 3) * BUFE * 2);
#pragma unroll
        for (int ks = 0; ks < 2; ks++) {
            uint32_t ahf[2][4], alf[2][4], bhf[4][2], blf[4][2];
#pragma unroll
            for (int am = 0; am < 2; am++) {
                uint32_t ar = (uint32_t)((wm + am * 16 + aro) * PADE + ks * 16 + ako) * 2;
                ldsm4(ahf[am][0], ahf[am][1], ahf[am][2], ahf[am][3], bb + OFF_AH * 2 + ar);
                ldsm4(alf[am][0], alf[am][1], alf[am][2], alf[am][3], bb + OFF_AL * 2 + ar);
            }
#pragma unroll
            for (int nb = 0; nb < 2; nb++) {
                uint32_t br = (uint32_t)((wn + nb * 16 + bro) * PADE + ks * 16 + bko) * 2;
                ldsm4(bhf[nb * 2][0], bhf[nb * 2][1], bhf[nb * 2 + 1][0], bhf[nb * 2 + 1][1],
                      bb + OFF_BH * 2 + br);
                ldsm4(blf[nb * 2][0], blf[nb * 2][1], blf[nb * 2 + 1][0], blf[nb * 2 + 1][1],
                      bb + OFF_BL * 2 + br);
            }
#pragma unroll
            for (int am = 0; am < 2; am++)
#pragma unroll
                for (int bn = 0; bn < 4; bn++) {
                    mma16816(acc[am][bn], ahf[am], bhf[bn]);
                    mma16816h(corr[am][bn], alf[am], bhf[bn]);
                    mma16816h(corr[am][bn], ahf[am], blf[bn]);
                }
        }
    }

#pragma unroll
    for (int am = 0; am < 2; am++) {
        const int row = m0 + wm + am * 16 + r4;
#pragma unroll
        for (int bn = 0; bn < 4; bn++) {
            const int col = n0 + wn + bn * 8 + 2 * lq;
            const float b0 = bias[col], b1 = bias[col + 1];
            float2 c01 = __half22float2(*reinterpret_cast<__half2*>(&corr[am][bn][0]));
            float2 c23 = __half22float2(*reinterpret_cast<__half2*>(&corr[am][bn][1]));
            float v0 = acc[am][bn][0] + c01.x + b0, v1 = acc[am][bn][1] + c01.y + b1;
            float v2 = acc[am][bn][2] + c23.x + b0, v3 = acc[am][bn][3] + c23.y + b1;
            if (act) { v0 = mishf(v0); v1 = mishf(v1); v2 = mishf(v2); v3 = mishf(v3); }
            if (osplit) {
                __half2 h01, h23, l01, l23;
                h01.x = __float2half_rn(v0); h01.y = __float2half_rn(v1);
                h23.x = __float2half_rn(v2); h23.y = __float2half_rn(v3);
                l01.x = __float2half_rn(v0 - __half2float(h01.x));
                l01.y = __float2half_rn(v1 - __half2float(h01.y));
                l23.x = __float2half_rn(v2 - __half2float(h23.x));
                l23.y = __float2half_rn(v3 - __half2float(h23.y));
                *(uint32_t*)(Ch + (size_t)row * N + col) = h2u(h01);
                *(uint32_t*)(Cl + (size_t)row * N + col) = h2u(l01);
                *(uint32_t*)(Ch + (size_t)(row + 8) * N + col) = h2u(h23);
                *(uint32_t*)(Cl + (size_t)(row + 8) * N + col) = h2u(l23);
            } else {
                *(float2*)(C + (size_t)row * N + col) = make_float2(v0, v1);
                *(float2*)(C + (size_t)(row + 8) * N + col) = make_float2(v2, v3);
            }
        }
    }
}

// ============ split-K gather-GEMM for scan round k ============
// gridDim.z = SK slices of the K walk; slice z writes partials to g_hg[z].
__global__ __launch_bounds__(256, 2) void mma_ggemm_kernel(int kround) {
    extern __shared__ __half smb[];
    const int base = g_off[kround];
    const int R = g_off[kround + 1] - base;
    const int m0 = blockIdx.y * 64;
    if (m0 >= R) return;
    const uint32_t sbase = smem_u32(smb);
    const int tid = threadIdx.x;
    const int wid = tid >> 5, lane = tid & 31;
    const int r4 = lane >> 2, lq = lane & 3;
    const int n0 = blockIdx.x * 128;
    const int wm = (wid & 1) * 32, wn = (wid >> 1) * 32;
    const int K = HD, N = 3 * HD;
    const int sk = gridDim.z, z = blockIdx.z;

    const int aro = lane & 15, ako = (lane >> 4) << 3;
    const int bro = (lane & 7) + ((lane >> 4) << 3), bko = ((lane >> 3) & 1) << 3;

    float acc[2][4][4] = {};
    uint32_t corr[2][4][2] = {};
    const int nch_tot = K >> 5;
    const int cbeg = z * (nch_tot / sk);
    const int cend = (z + 1) * (nch_tot / sk);
    const int nch = cend - cbeg;

    const int ld_r = tid >> 2, ld_q = tid & 3;
    const uint32_t ld_e = (uint32_t)(ld_r * PADE + ld_q * 8) * 2;
    const int gm = m0 + ld_r;
    const int myt = (gm < R) ? (g_order[base + gm] - 1) : (g_order[base] - 1);
    const __half* Ah = g_sth;
    const __half* Al = g_stl;
    const __half* Bh = g_whhh;
    const __half* Bl = g_whhl;
    float* hgout = g_hg[z];

#pragma unroll
    for (int c = 0; c < 2; c++) {
        const int k0 = (cbeg + c) << 5;
        const uint32_t bb = sbase + (uint32_t)((c % 3) * BUFE * 2);
        {
            size_t goA = (size_t)myt * K + k0 + ld_q * 8;
            cp16(bb + OFF_AH * 2 + ld_e, Ah + goA);
            cp16(bb + OFF_AL * 2 + ld_e, Al + goA);
        }
#pragma unroll
        for (int q = 0; q < 2; q++) {
            int r = ld_r + 64 * q;
            uint32_t e = ld_e + (uint32_t)(64 * q * PADE) * 2;
            size_t goB = (size_t)(n0 + r) * K + k0 + ld_q * 8;
            cp16(bb + OFF_BH * 2 + e, Bh + goB);
            cp16(bb + OFF_BL * 2 + e, Bl + goB);
        }
        cp_commit();
    }

    for (int c = 0; c < nch; c++) {
        if (c + 1 < nch) cp_wait1(); else cp_wait0();
        __syncthreads();

        if (c + 2 < nch) {
            const int k0 = (cbeg + c + 2) << 5;
            const uint32_t nb = sbase + (uint32_t)(((c + 2) % 3) * BUFE * 2);
            {
                size_t goA = (size_t)myt * K + k0 + ld_q * 8;
                cp16(nb + OFF_AH * 2 + ld_e, Ah + goA);
                cp16(nb + OFF_AL * 2 + ld_e, Al + goA);
            }
#pragma unroll
            for (int q = 0; q < 2; q++) {
                int r = ld_r + 64 * q;
                uint32_t e = ld_e + (uint32_t)(64 * q * PADE) * 2;
                size_t goB = (size_t)(n0 + r) * K + k0 + ld_q * 8;
                cp16(nb + OFF_BH * 2 + e, Bh + goB);
                cp16(nb + OFF_BL * 2 + e, Bl + goB);
            }
            cp_commit();
        }

        const uint32_t bb = sbase + (uint32_t)((c % 3) * BUFE * 2);
#pragma unroll
        for (int ks = 0; ks < 2; ks++) {
            uint32_t ahf[2][4], alf[2][4], bhf[4][2], blf[4][2];
#pragma unroll
            for (int am = 0; am < 2; am++) {
                uint32_t ar = (uint32_t)((wm + am * 16 + aro) * PADE + ks * 16 + ako) * 2;
                ldsm4(ahf[am][0], ahf[am][1], ahf[am][2], ahf[am][3], bb + OFF_AH * 2 + ar);
                ldsm4(alf[am][0], alf[am][1], alf[am][2], alf[am][3], bb + OFF_AL * 2 + ar);
            }
#pragma unroll
            for (int nb = 0; nb < 2; nb++) {
                uint32_t br = (uint32_t)((wn + nb * 16 + bro) * PADE + ks * 16 + bko) * 2;
                ldsm4(bhf[nb * 2][0], bhf[nb * 2][1], bhf[nb * 2 + 1][0], bhf[nb * 2 + 1][1],
                      bb + OFF_BH * 2 + br);
                ldsm4(blf[nb * 2][0], blf[nb * 2][1], blf[nb * 2 + 1][0], blf[nb * 2 + 1][1],
                      bb + OFF_BL * 2 + br);
            }
#pragma unroll
            for (int am = 0; am < 2; am++)
#pragma unroll
                for (int bn = 0; bn < 4; bn++) {
                    mma16816(acc[am][bn], ahf[am], bhf[bn]);
                    mma16816h(corr[am][bn], alf[am], bhf[bn]);
                    mma16816h(corr[am][bn], ahf[am], blf[bn]);
                }
        }
    }

#pragma unroll
    for (int am = 0; am < 2; am++) {
        const int row = m0 + wm + am * 16 + r4;
#pragma unroll
        for (int bn = 0; bn < 4; bn++) {
            const int col = n0 + wn + bn * 8 + 2 * lq;
            float2 c01 = __half22float2(*reinterpret_cast<__half2*>(&corr[am][bn][0]));
            float2 c23 = __half22float2(*reinterpret_cast<__half2*>(&corr[am][bn][1]));
            if (row < R)
                *(float2*)(hgout + (size_t)row * N + col) =
                    make_float2(acc[am][bn][0] + c01.x, acc[am][bn][1] + c01.y);
            if (row + 8 < R)
                *(float2*)(hgout + (size_t)(row + 8) * N + col) =
                    make_float2(acc[am][bn][2] + c23.x, acc[am][bn][3] + c23.y);
        }
    }
}

__device__ __forceinline__ void store_state(int t, int j, float hnew, float* out) {
    g_states[(size_t)t * HD + j] = hnew;
    __half h = __float2half_rn(hnew);
    g_sth[(size_t)t * HD + j] = h;
    g_stl[(size_t)t * HD + j] = __float2half_rn(hnew - __half2float(h));
    if (t == T_STEPS - 1) out[(size_t)T_STEPS * ACTD + j] = hnew;
}

// pointwise gates for a GEMM round (sums sk split-K partials)
__global__ __launch_bounds__(256) void gate_kernel(const float* __restrict__ gbn,
                                                   float* __restrict__ out, int kround, int sk) {
    const int base = g_off[kround];
    const int R = g_off[kround + 1] - base;
    const int idx = blockIdx.x * blockDim.x + threadIdx.x;
    if (idx >= R * HD) return;
    const int m = idx >> 10, j = idx & (HD - 1);
    const int t = g_order[base + m];
    float hr = 0.f, hz = 0.f, hn = 0.f;
    for (int z = 0; z < sk; z++) {
        const float* hg = g_hg[z] + (size_t)m * (3 * HD);
        hr += hg[j]; hz += hg[HD + j]; hn += hg[2 * HD + j];
    }
    const float* igt = g_ig + (size_t)t * (3 * HD);
    float rv = sigmoidf_(igt[j] + hr);
    float uv = sigmoidf_(igt[HD + j] + hz);
    float nv = tanhf(igt[2 * HD + j] + rv * (hn + gbn[j]));
    float hin = g_states[(size_t)(t - 1) * HD + j];
    store_state(t, j, nv + uv * (hin - nv), out);
}

// ---------------- small SGEMM (p3, N=16) ----------------
__global__ __launch_bounds__(256) void sgemm64_kernel(
    const float* __restrict__ A, const float* __restrict__ B,
    const float* __restrict__ bias, float* __restrict__ C,
    int M, int N, int K) {
    __shared__ float As[16][64];
    __shared__ float Bs[16][64];
    const int m0 = blockIdx.y * 64;
    const int n0 = blockIdx.x * 64;
    const int tid = threadIdx.x;
    const int tx = tid & 15, ty = tid >> 4;
    const int lr = tid >> 2, lq = tid & 3;
    float acc[4][4] = {};
    for (int k0 = 0; k0 < K; k0 += 16) {
        float4 a4 = *(const float4*)(A + (size_t)(m0 + lr) * K + k0 + lq * 4);
        As[lq * 4 + 0][lr] = a4.x; As[lq * 4 + 1][lr] = a4.y;
        As[lq * 4 + 2][lr] = a4.z; As[lq * 4 + 3][lr] = a4.w;
        float4 b4 = make_float4(0.f, 0.f, 0.f, 0.f);
        if (n0 + lr < N) b4 = *(const float4*)(B + (size_t)(n0 + lr) * K + k0 + lq * 4);
        Bs[lq * 4 + 0][lr] = b4.x; Bs[lq * 4 + 1][lr] = b4.y;
        Bs[lq * 4 + 2][lr] = b4.z; Bs[lq * 4 + 3][lr] = b4.w;
        __syncthreads();
#pragma unroll
        for (int k = 0; k < 16; k++) {
            float4 av = *(const float4*)(&As[k][ty * 4]);
            float4 bv = *(const float4*)(&Bs[k][tx * 4]);
            float avs[4] = {av.x, av.y, av.z, av.w};
            float bvs[4] = {bv.x, bv.y, bv.z, bv.w};
#pragma unroll
            for (int i = 0; i < 4; i++)
#pragma unroll
                for (int jj = 0; jj < 4; jj++)
                    acc[i][jj] = fmaf(avs[i], bvs[jj], acc[i][jj]);
        }
        __syncthreads();
    }
#pragma unroll
    for (int i = 0; i < 4; i++) {
        int m = m0 + ty * 4 + i;
#pragma unroll
        for (int jj = 0; jj < 4; jj++) {
            int n = n0 + tx * 4 + jj;
            if (n < N) C[(size_t)m * N + n] = acc[i][jj] + (bias ? bias[n] : 0.0f);
        }
    }
}

// ---------------- prep: bucket timesteps by age within reset-segment ----------------
__global__ __launch_bounds__(1024) void prep_kernel(const int* __restrict__ start) {
    __shared__ int sa[2048], sb_[2048], sc[2048];
    __shared__ int skmax;
    const int tid = threadIdx.x;
    const int t0 = tid, t1 = tid + 1024;
    if (tid == 0) { g_bar = 0u; skmax = 0; }
    sa[t0] = start[t0] ? t0 : -1;
    sa[t1] = start[t1] ? t1 : -1;
    __syncthreads();
    int* src = sa; int* dst = sb_;
    for (int d = 1; d < 2048; d <<= 1) {
        int v0 = src[t0]; if (t0 >= d) v0 = max(v0, src[t0 - d]);
        int v1 = src[t1]; if (t1 >= d) v1 = max(v1, src[t1 - d]);
        dst[t0] = v0; dst[t1] = v1;
        __syncthreads();
        int* tmp = src; src = dst; dst = tmp;
    }
    int r0v = src[t0], r1v = src[t1];
    int age0 = (r0v < 0) ? t0 : t0 - r0v;
    int age1 = (r1v < 0) ? t1 : t1 - r1v;
    __syncthreads();
    sc[t0] = 0; sc[t1] = 0;
    __syncthreads();
    atomicAdd(&sc[age0], 1);
    atomicAdd(&sc[age1], 1);
    atomicMax(&skmax, max(age0, age1) + 1);
    __syncthreads();
    sa[t0] = sc[t0]; sa[t1] = sc[t1];
    __syncthreads();
    src = sa; dst = sb_;
    for (int d = 1; d < 2048; d <<= 1) {
        int v0 = src[t0]; if (t0 >= d) v0 += src[t0 - d];
        int v1 = src[t1]; if (t1 >= d) v1 += src[t1 - d];
        dst[t0] = v0; dst[t1] = v1;
        __syncthreads();
        int* tmp = src; src = dst; dst = tmp;
    }
    if (tid == 0) { g_off[0] = 0; g_kmax = skmax; }
    g_off[t0 + 1] = src[t0];
    g_off[t1 + 1] = src[t1];
    sc[t0] = 0; sc[t1] = 0;
    __syncthreads();
    int base0 = (age0 == 0) ? 0 : src[age0 - 1];
    g_order[base0 + atomicAdd(&sc[age0], 1)] = t0;
    int base1 = (age1 == 0) ? 0 : src[age1 - 1];
    g_order[base1 + atomicAdd(&sc[age1], 1)] = t1;
}

// ---------------- grid barrier ----------------
__device__ inline void grid_bar(unsigned* barp, unsigned target) {
    __syncthreads();
    if (threadIdx.x == 0) {
        asm volatile("red.release.gpu.global.add.u32 [%0], %1;" :: "l"(barp), "r"(1u) : "memory");
        unsigned v;
        do {
            asm volatile("ld.acquire.gpu.global.u32 %0, [%1];" : "=r"(v) : "l"(barp) : "memory");
        } while (v < target);
    }
    __syncthreads();
}

// ---------------- round 0: t=0 full matvec + start rows closed-form ----------------
__global__ __launch_bounds__(256, 1) void round0_kernel(
    const float* __restrict__ whh, const float* __restrict__ gbn,
    const int* __restrict__ start, const float* __restrict__ state,
    float* __restrict__ out) {
    __shared__ float sH[HD];
    const int tid = threadIdx.x;
    const int w = tid >> 5, lane = tid & 31;
    const int j = blockIdx.x * 8 + w;
    const float bnj = gbn[j];
    const int s0 = start[0];

    if (s0 == 0) {
        ((float4*)sH)[tid] = ((const float4*)state)[tid];
        __syncthreads();
        const float4* w4 = (const float4*)whh;
        float ir = 0.f, iz = 0.f, inn = 0.f;
        if (lane == 0) { ir = g_ig[j]; iz = g_ig[HD + j]; inn = g_ig[2 * HD + j]; }
        float aR = 0.f, aZ = 0.f, aN = 0.f;
#pragma unroll
        for (int q = 0; q < 8; q++) {
            float4 h4 = ((const float4*)sH)[lane + 32 * q];
            float4 r4v = w4[(size_t)(0 * HD + j) * 256 + lane + 32 * q];
            float4 z4v = w4[(size_t)(1 * HD + j) * 256 + lane + 32 * q];
            float4 n4v = w4[(size_t)(2 * HD + j) * 256 + lane + 32 * q];
            aR = fmaf(h4.x, r4v.x, fmaf(h4.y, r4v.y, fmaf(h4.z, r4v.z, fmaf(h4.w, r4v.w, aR))));
            aZ = fmaf(h4.x, z4v.x, fmaf(h4.y, z4v.y, fmaf(h4.z, z4v.z, fmaf(h4.w, z4v.w, aZ))));
            aN = fmaf(h4.x, n4v.x, fmaf(h4.y, n4v.y, fmaf(h4.z, n4v.z, fmaf(h4.w, n4v.w, aN))));
        }
#pragma unroll
        for (int off = 16; off; off >>= 1) {
            aR += __shfl_xor_sync(0xffffffffu, aR, off);
            aZ += __shfl_xor_sync(0xffffffffu, aZ, off);
            aN += __shfl_xor_sync(0xffffffffu, aN, off);
        }
        if (lane == 0) {
            float rv = sigmoidf_(ir + aR);
            float uv = sigmoidf_(iz + aZ);
            float nv = tanhf(inn + rv * (aN + bnj));
            float hin = sH[j];
            store_state(0, j, nv + uv * (hin - nv), out);
        }
    }
    {
        const int beg = g_off[0], end = g_off[1];
        for (int r = beg + lane; r < end; r += 32) {
            const int t = g_order[r];
            if (t == 0 && s0 == 0) continue;
            const float* igt = g_ig + (size_t)t * (3 * HD);
            float rv = sigmoidf_(igt[j]);
            float uv = sigmoidf_(igt[HD + j]);
            float nv = tanhf(igt[2 * HD + j] + rv * bnj);
            store_state(t, j, nv - uv * nv, out);
        }
    }
}

// ---------------- cleanup scan: rounds kstart..kmax (tiny tails), 4 rows/iter ----------------
__global__ __launch_bounds__(256, 1) void cleanup_scan_kernel(
    const float* __restrict__ whh, const float* __restrict__ gbn,
    float* __restrict__ out, int kstart) {
    __shared__ float sH[4][HD];
    const int tid = threadIdx.x;
    const int w = tid >> 5, lane = tid & 31;
    const int j = blockIdx.x * 8 + w;
    const int kmax = g_kmax;
    if (kstart >= kmax) return;

    const float4* w4 = (const float4*)whh;
    float4 wr[8], wz[8], wn[8];
#pragma unroll
    for (int q = 0; q < 8; q++) {
        wr[q] = w4[(size_t)(0 * HD + j) * 256 + lane + 32 * q];
        wz[q] = w4[(size_t)(1 * HD + j) * 256 + lane + 32 * q];
        wn[q] = w4[(size_t)(2 * HD + j) * 256 + lane + 32 * q];
    }
    const float bnj = gbn[j];
    unsigned* barp = &g_bar;
    unsigned epoch = 0;

    for (int k = kstart; k < kmax; k++) {
        const int beg = g_off[k], end = g_off[k + 1];
        int r = beg;
        int tt[4] = {-1, -1, -1, -1};
        float4 nx[4];
#pragma unroll
        for (int i = 0; i < 4; i++) {
            if (r + i < end) {
                tt[i] = g_order[r + i];
                nx[i] = __ldcg((const float4*)(g_states + (size_t)(tt[i] - 1) * HD) + tid);
            }
        }

        while (r < end) {
            int cur[4];
#pragma unroll
            for (int i = 0; i < 4; i++) cur[i] = tt[i];
            if (cur[0] >= 0) ((float4*)sH[0])[tid] = nx[0];
            if (cur[1] >= 0) ((float4*)sH[1])[tid] = nx[1];
            if (cur[2] >= 0) ((float4*)sH[2])[tid] = nx[2];
            if (cur[3] >= 0) ((float4*)sH[3])[tid] = nx[3];
            __syncthreads();

            const int rn = r + 4;
#pragma unroll
            for (int i = 0; i < 4; i++) {
                tt[i] = -1;
                if (rn + i < end) {
                    tt[i] = g_order[rn + i];
                    nx[i] = __ldcg((const float4*)(g_states + (size_t)(tt[i] - 1) * HD) + tid);
                }
            }

            float ir = 0.f, iz = 0.f, inn = 0.f;
            int myt = -1;
            if (lane < 4) {
                myt = cur[lane];
                if (myt >= 0) {
                    const float* igt = g_ig + (size_t)myt * (3 * HD);
                    ir = igt[j]; iz = igt[HD + j]; inn = igt[2 * HD + j];
                }
            }

            float aR[4] = {}, aZ[4] = {}, aN[4] = {};
#pragma unroll
            for (int q = 0; q < 8; q++) {
                const int c = lane + 32 * q;
                float4 r4v = wr[q], z4v = wz[q], n4v = wn[q];
#pragma unroll
                for (int i = 0; i < 4; i++) {
                    float4 h4 = ((const float4*)sH[i])[c];
                    aR[i] = fmaf(h4.x, r4v.x, fmaf(h4.y, r4v.y, fmaf(h4.z, r4v.z, fmaf(h4.w, r4v.w, aR[i]))));
                    aZ[i] = fmaf(h4.x, z4v.x, fmaf(h4.y, z4v.y, fmaf(h4.z, z4v.z, fmaf(h4.w, z4v.w, aZ[i]))));
                    aN[i] = fmaf(h4.x, n4v.x, fmaf(h4.y, n4v.y, fmaf(h4.z, n4v.z, fmaf(h4.w, n4v.w, aN[i]))));
                }
            }
#pragma unroll
            for (int off = 16; off; off >>= 1) {
#pragma unroll
                for (int i = 0; i < 4; i++) {
                    aR[i] += __shfl_xor_sync(0xffffffffu, aR[i], off);
                    aZ[i] += __shfl_xor_sync(0xffffffffu, aZ[i], off);
                    aN[i] += __shfl_xor_sync(0xffffffffu, aN[i], off);
                }
            }
            if (lane < 4 && myt >= 0) {
                float rv = sigmoidf_(ir + aR[lane]);
                float uv = sigmoidf_(iz + aZ[lane]);
                float nv = tanhf(inn + rv * (aN[lane] + bnj));
                float hin = sH[lane][j];
                store_state(myt, j, nv + uv * (hin - nv), out);
            }
            __syncthreads();
            r = rn;
        }
        grid_bar(barp, (++epoch) * SCAN_BLOCKS);
    }
}

// ---------------- launch ----------------
extern "C" void kernel_launch(void* const* d_in, const int* in_sizes, int n_in,
                              void* d_out, int out_size) {
    (void)in_sizes; (void)n_in;
    const float* x      = (const float*)d_in[0];
    const float* state  = (const float*)d_in[1];
    const int*   start  = (const int*)d_in[2];
    const float* pre_wm = (const float*)d_in[4];
    const float* pre_ws = (const float*)d_in[5];
    const float* pre_bm = (const float*)d_in[6];
    const float* pre_bs = (const float*)d_in[7];
    const float* wih    = (const float*)d_in[8];
    const float* whh    = (const float*)d_in[9];
    const float* gru_b  = (const float*)d_in[10];
    const float* gru_bn = (const float*)d_in[11];
    const float* p1_wm  = (const float*)d_in[12];
    const float* p1_ws  = (const float*)d_in[13];
    const float* p1_bm  = (const float*)d_in[14];
    const float* p1_bs  = (const float*)d_in[15];
    const float* p2_wm  = (const float*)d_in[16];
    const float* p2_ws  = (const float*)d_in[17];
    const float* p2_bm  = (const float*)d_in[18];
    const float* p2_bs  = (const float*)d_in[19];
    const float* p3_wm  = (const float*)d_in[20];
    const float* p3_ws  = (const float*)d_in[21];
    const float* p3_bm  = (const float*)d_in[22];
    const float* p3_bs  = (const float*)d_in[23];
    float* out = (float*)d_out;
    (void)out_size;

    unsigned nk[8][2];
    for (int i = 0; i < 8; i++) {
        unsigned a = 0u, b = (unsigned)i;
        tf_block(0u, 7u, a, b);
        nk[i][0] = a; nk[i][1] = b;
    }

    float *preB, *p1B, *p2B, *p3W, *p3B, *ig, *states, *y2;
    __half *xh, *xl, *preWh, *preWl, *wihh, *wihl, *whhh, *whhl, *p1Wh, *p1Wl, *p2Wh, *p2Wl;
    __half *zh, *zl, *sth, *stl, *y1h, *y1l;
    cudaGetSymbolAddress((void**)&preB, g_preB);
    cudaGetSymbolAddress((void**)&p1B, g_p1B);
    cudaGetSymbolAddress((void**)&p2B, g_p2B);
    cudaGetSymbolAddress((void**)&p3W, g_p3W);
    cudaGetSymbolAddress((void**)&p3B, g_p3B);
    cudaGetSymbolAddress((void**)&ig, g_ig);
    cudaGetSymbolAddress((void**)&states, g_states);
    cudaGetSymbolAddress((void**)&y2, g_y2);
    cudaGetSymbolAddress((void**)&xh, g_xh);
    cudaGetSymbolAddress((void**)&xl, g_xl);
    cudaGetSymbolAddress((void**)&preWh, g_preWh);
    cudaGetSymbolAddress((void**)&preWl, g_preWl);
    cudaGetSymbolAddress((void**)&wihh, g_wihh);
    cudaGetSymbolAddress((void**)&wihl, g_wihl);
    cudaGetSymbolAddress((void**)&whhh, g_whhh);
    cudaGetSymbolAddress((void**)&whhl, g_whhl);
    cudaGetSymbolAddress((void**)&p1Wh, g_p1Wh);
    cudaGetSymbolAddress((void**)&p1Wl, g_p1Wl);
    cudaGetSymbolAddress((void**)&p2Wh, g_p2Wh);
    cudaGetSymbolAddress((void**)&p2Wl, g_p2Wl);
    cudaGetSymbolAddress((void**)&zh, g_zh);
    cudaGetSymbolAddress((void**)&zl, g_zl);
    cudaGetSymbolAddress((void**)&sth, g_sth);
    cudaGetSymbolAddress((void**)&stl, g_stl);
    cudaGetSymbolAddress((void**)&y1h, g_y1h);
    cudaGetSymbolAddress((void**)&y1l, g_y1l);

    cudaFuncSetAttribute(mma_gemm_kernel, cudaFuncAttributeMaxDynamicSharedMemorySize,
                         MMA_SMEM_BYTES);
    cudaFuncSetAttribute(mma_ggemm_kernel, cudaFuncAttributeMaxDynamicSharedMemorySize,
                         MMA_SMEM_BYTES);

    static cudaStream_t sB = nullptr;
    static cudaEvent_t evFork, evPre, evWih, evWhh, evPrep, evP1, evP2;
    if (sB == nullptr) {
        cudaStreamCreateWithFlags(&sB, cudaStreamNonBlocking);
        cudaEventCreateWithFlags(&evFork, cudaEventDisableTiming);
        cudaEventCreateWithFlags(&evPre, cudaEventDisableTiming);
        cudaEventCreateWithFlags(&evWih, cudaEventDisableTiming);
        cudaEventCreateWithFlags(&evWhh, cudaEventDisableTiming);
        cudaEventCreateWithFlags(&evPrep, cudaEventDisableTiming);
        cudaEventCreateWithFlags(&evP1, cudaEventDisableTiming);
        cudaEventCreateWithFlags(&evP2, cudaEventDisableTiming);
    }

    cudaEventRecord(evFork, 0);
    cudaStreamWaitEvent(sB, evFork, 0);

    // main: x split
    conv_split_kernel<<<(T_STEPS * OBS / 4 + 255) / 256, 256>>>(x, xh, xl, T_STEPS * OBS / 4);
    // side: pre noise + small noise
    { int n = MLPD * OBS; gen_noisy_w_kernel<<<(n + 255) / 256, 256, 0, sB>>>(pre_wm, pre_ws, preWh, preWl, n, nk[0][0], nk[0][1]); }
    gen_small_kernel<<<(19472 + 255) / 256, 256, 0, sB>>>(
        p3_wm, p3_ws, p3W, nk[6][0], nk[6][1],
        pre_bm, pre_bs, preB, nk[1][0], nk[1][1],
        p1_bm, p1_bs, p1B, nk[3][0], nk[3][1],
        p2_bm, p2_bs, p2B, nk[5][0], nk[5][1],
        p3_bm, p3_bs, p3B, nk[7][0], nk[7][1]);
    cudaEventRecord(evPre, sB);

    // main: GEMM1
    cudaStreamWaitEvent(0, evPre, 0);
    mma_gemm_kernel<<<dim3(MLPD / 128, T_STEPS / 64), 256, MMA_SMEM_BYTES>>>(
        xh, xl, preWh, preWl, preB, nullptr, zh, zl, T_STEPS, MLPD, OBS, 1, 1);

    // side: wih split, whh split, prep (all overlap GEMM1/2)
    conv_split_kernel<<<(3 * HD * MLPD / 4 + 255) / 256, 256, 0, sB>>>(wih, wihh, wihl, 3 * HD * MLPD / 4);
    cudaEventRecord(evWih, sB);
    conv_split_kernel<<<(3 * HD * MLPD / 4 + 255) / 256, 256, 0, sB>>>(whh, whhh, whhl, 3 * HD * MLPD / 4);
    cudaEventRecord(evWhh, sB);
    prep_kernel<<<1, 1024, 0, sB>>>(start);
    cudaEventRecord(evPrep, sB);

    // main: GEMM2
    cudaStreamWaitEvent(0, evWih, 0);
    mma_gemm_kernel<<<dim3(3 * HD / 128, T_STEPS / 64), 256, MMA_SMEM_BYTES>>>(
        zh, zl, wihh, wihl, gru_b, ig, nullptr, nullptr, T_STEPS, 3 * HD, MLPD, 0, 0);

    // side: p1/p2 noise (overlaps GEMM2 + scan rounds)
    { int n = MLPD * HD;   gen_noisy_w_kernel<<<(n + 255) / 256, 256, 0, sB>>>(p1_wm, p1_ws, p1Wh, p1Wl, n, nk[2][0], nk[2][1]); }
    cudaEventRecord(evP1, sB);
    { int n = MLPD * MLPD; gen_noisy_w_kernel<<<(n + 255) / 256, 256, 0, sB>>>(p2_wm, p2_ws, p2Wh, p2Wl, n, nk[4][0], nk[4][1]); }
    cudaEventRecord(evP2, sB);

    // main: round 0
    cudaStreamWaitEvent(0, evPrep, 0);
    round0_kernel<<<SCAN_BLOCKS, 256>>>(whh, gru_bn, start, state, out);

    // main: split-K GEMM rounds 1..KGEMM
    // round k has R <= 2048/(k+1) rows; y-grid bound accordingly, z = split-K factor.
    cudaStreamWaitEvent(0, evWhh, 0);
    {
        const int ymax[KGEMM + 1] = {0, 16, 11, 8, 7};   // ceil(2048/(k+1)/64)
        const int skv[KGEMM + 1]  = {0, 2, 4, 4, 4};
        const int rbnd[KGEMM + 1] = {0, 1024, 683, 512, 410};
        for (int k = 1; k <= KGEMM; k++) {
            mma_ggemm_kernel<<<dim3(3 * HD / 128, ymax[k], skv[k]), 256, MMA_SMEM_BYTES>>>(k);
            gate_kernel<<<(rbnd[k] * HD + 255) / 256, 256>>>(gru_bn, out, k, skv[k]);
        }
    }

    // main: cleanup scan for rounds > KGEMM
    cleanup_scan_kernel<<<SCAN_BLOCKS, 256>>>(whh, gru_bn, out, KGEMM + 1);

    // main: GEMM3
    cudaStreamWaitEvent(0, evP1, 0);
    mma_gemm_kernel<<<dim3(MLPD / 128, T_STEPS / 64), 256, MMA_SMEM_BYTES>>>(
        sth, stl, p1Wh, p1Wl, p1B, nullptr, y1h, y1l, T_STEPS, MLPD, HD, 1, 1);

    // main: GEMM4
    cudaStreamWaitEvent(0, evP2, 0);
    mma_gemm_kernel<<<dim3(MLPD / 128, T_STEPS / 64), 256, MMA_SMEM_BYTES>>>(
        y1h, y1l, p2Wh, p2Wl, p2B, y2, nullptr, nullptr, T_STEPS, MLPD, MLPD, 1, 0);

    // main: final layer -> d_out[0 : 2048*16]
    sgemm64_kernel<<<dim3(1, T_STEPS / 64), 256>>>(y2, p3W, p3B, out, T_STEPS, ACTD, MLPD);
}

// round 17
// speedup vs baseline: 1.9572x; 1.1266x over previous
#include <cuda_runtime.h>
#include <cuda_fp16.h>
#include <cstdint>

#define T_STEPS 2048
#define OBS 512
#define MLPD 1024
#define HD 1024
#define ACTD 16
#define SCAN_BLOCKS 128
#define KGEMM 4

// ---------------- device scratch (no allocations allowed) ----------------
__device__ float g_preB[MLPD];
__device__ float g_p1B[MLPD];
__device__ float g_p2B[MLPD];
__device__ float g_p3W[ACTD * MLPD];
__device__ float g_p3B[ACTD];
__device__ float g_ig[(size_t)T_STEPS * 3 * HD];
__device__ float g_states[(size_t)T_STEPS * HD];
__device__ float g_hg[4][(size_t)1024 * 3 * HD];  // split-K partials
__device__ float g_y2[T_STEPS * MLPD];
__device__ __half g_xh[T_STEPS * OBS],  g_xl[T_STEPS * OBS];
__device__ __half g_preWh[MLPD * OBS],  g_preWl[MLPD * OBS];
__device__ __half g_wihh[3 * HD * MLPD], g_wihl[3 * HD * MLPD];
__device__ __half g_whhh[3 * HD * MLPD], g_whhl[3 * HD * MLPD];
__device__ __half g_p1Wh[MLPD * HD],    g_p1Wl[MLPD * HD];
__device__ __half g_p2Wh[MLPD * MLPD],  g_p2Wl[MLPD * MLPD];
__device__ __half g_zh[T_STEPS * MLPD], g_zl[T_STEPS * MLPD];
__device__ __half g_sth[(size_t)T_STEPS * HD], g_stl[(size_t)T_STEPS * HD];
__device__ __half g_y1h[T_STEPS * MLPD], g_y1l[T_STEPS * MLPD];
__device__ unsigned g_bar;
__device__ int g_order[T_STEPS];
__device__ int g_off[T_STEPS + 1];
__device__ int g_kmax;

// ---------------- threefry2x32 (matches JAX) ----------------
#define TF_ROUND(x0, x1, R) { x0 += x1; x1 = (x1 << R) | (x1 >> (32 - R)); x1 ^= x0; }

__host__ __device__ inline void tf_block(unsigned k0, unsigned k1, unsigned &x0, unsigned &x1) {
    unsigned ks2 = k0 ^ k1 ^ 0x1BD11BDAu;
    x0 += k0; x1 += k1;
    TF_ROUND(x0, x1, 13) TF_ROUND(x0, x1, 15) TF_ROUND(x0, x1, 26) TF_ROUND(x0, x1, 6)
    x0 += k1; x1 += ks2 + 1u;
    TF_ROUND(x0, x1, 17) TF_ROUND(x0, x1, 29) TF_ROUND(x0, x1, 16) TF_ROUND(x0, x1, 24)
    x0 += ks2; x1 += k0 + 2u;
    TF_ROUND(x0, x1, 13) TF_ROUND(x0, x1, 15) TF_ROUND(x0, x1, 26) TF_ROUND(x0, x1, 6)
    x0 += k0; x1 += k1 + 3u;
    TF_ROUND(x0, x1, 17) TF_ROUND(x0, x1, 29) TF_ROUND(x0, x1, 16) TF_ROUND(x0, x1, 24)
    x0 += k1; x1 += ks2 + 4u;
    TF_ROUND(x0, x1, 13) TF_ROUND(x0, x1, 15) TF_ROUND(x0, x1, 26) TF_ROUND(x0, x1, 6)
    x0 += ks2; x1 += k0 + 5u;
}

// XLA f32 erf_inv (Giles)
__device__ inline float xla_erfinv(float x) {
    float w = -log1pf(-x * x);
    float p;
    if (w < 5.0f) {
        w -= 2.5f;
        p = 2.81022636e-08f;
        p = fmaf(p, w, 3.43273939e-07f);
        p = fmaf(p, w, -3.5233877e-06f);
        p = fmaf(p, w, -4.39150654e-06f);
        p = fmaf(p, w, 0.00021858087f);
        p = fmaf(p, w, -0.00125372503f);
        p = fmaf(p, w, -0.00417768164f);
        p = fmaf(p, w, 0.246640727f);
        p = fmaf(p, w, 1.50140941f);
    } else {
        w = sqrtf(w) - 3.0f;
        p = -0.000200214257f;
        p = fmaf(p, w, 0.000100950558f);
        p = fmaf(p, w, 0.00134934322f);
        p = fmaf(p, w, -0.00367342844f);
        p = fmaf(p, w, 0.00573950773f);
        p = fmaf(p, w, -0.0076224613f);
        p = fmaf(p, w, 0.00943887047f);
        p = fmaf(p, w, 1.00167406f);
        p = fmaf(p, w, 2.83297682f);
    }
    return p * x;
}

__device__ inline float bits_to_normal(unsigned b) {
    float u1 = __uint_as_float((b >> 9) | 0x3f800000u) - 1.0f;
    float v = fmaf(u1, 1.99999994f, -0.99999994f);
    v = fmaxf(v, -0.99999994f);
    return 1.41421356f * xla_erfinv(v);
}

__device__ inline float tf_normal(unsigned k0, unsigned k1, unsigned i) {
    unsigned x0 = 0u, x1 = i;
    tf_block(k0, k1, x0, x1);
    return bits_to_normal(x0 ^ x1);
}

__global__ void gen_noisy_w_kernel(const float* __restrict__ wm, const float* __restrict__ ws,
                                   __half* __restrict__ hi, __half* __restrict__ lo,
                                   int n, unsigned k0, unsigned k1) {
    int i = blockIdx.x * blockDim.x + threadIdx.x;
    if (i >= n) return;
    float v = fmaf(ws[i], tf_normal(k0, k1, (unsigned)i), wm[i]);
    __half h = __float2half_rn(v);
    hi[i] = h;
    lo[i] = __float2half_rn(v - __half2float(h));
}

__global__ void gen_small_kernel(
    const float* p3wm, const float* p3ws, float* p3w, unsigned kw0, unsigned kw1,
    const float* prebm, const float* prebs, float* preb, unsigned ka0, unsigned ka1,
    const float* p1bm, const float* p1bs, float* p1b, unsigned kb0, unsigned kb1,
    const float* p2bm, const float* p2bs, float* p2b, unsigned kc0, unsigned kc1,
    const float* p3bm, const float* p3bs, float* p3b, unsigned kd0, unsigned kd1) {
    int i = blockIdx.x * blockDim.x + threadIdx.x;
    if (i < 16384) {
        p3w[i] = fmaf(p3ws[i], tf_normal(kw0, kw1, (unsigned)i), p3wm[i]);
    } else if (i < 17408) {
        int l = i - 16384;
        preb[l] = fmaf(prebs[l], tf_normal(ka0, ka1, (unsigned)l), prebm[l]);
    } else if (i < 18432) {
        int l = i - 17408;
        p1b[l] = fmaf(p1bs[l], tf_normal(kb0, kb1, (unsigned)l), p1bm[l]);
    } else if (i < 19456) {
        int l = i - 18432;
        p2b[l] = fmaf(p2bs[l], tf_normal(kc0, kc1, (unsigned)l), p2bm[l]);
    } else if (i < 19472) {
        int l = i - 19456;
        p3b[l] = fmaf(p3bs[l], tf_normal(kd0, kd1, (unsigned)l), p3bm[l]);
    }
}

// ---------------- activations ----------------
__device__ inline float mishf(float x) {
    float sp = fmaxf(x, 0.0f) + log1pf(expf(-fabsf(x)));
    return x * tanhf(sp);
}
__device__ inline float sigmoidf_(float x) { return 1.0f / (1.0f + expf(-x)); }

__device__ __forceinline__ uint32_t h2u(__half2 v) {
    return *reinterpret_cast<uint32_t*>(&v);
}

// ---------------- fp32 -> fp16 hi/lo split (n4 = n/4) ----------------
__global__ void conv_split_kernel(const float* __restrict__ src,
                                  __half* __restrict__ hi,
                                  __half* __restrict__ lo, int n4) {
    int i = blockIdx.x * blockDim.x + threadIdx.x;
    if (i >= n4) return;
    float4 v = ((const float4*)src)[i];
    __half2 h0, h1, l0, l1;
    h0.x = __float2half_rn(v.x); h0.y = __float2half_rn(v.y);
    h1.x = __float2half_rn(v.z); h1.y = __float2half_rn(v.w);
    l0.x = __float2half_rn(v.x - __half2float(h0.x));
    l0.y = __float2half_rn(v.y - __half2float(h0.y));
    l1.x = __float2half_rn(v.z - __half2float(h1.x));
    l1.y = __float2half_rn(v.w - __half2float(h1.y));
    ((uint2*)hi)[i] = make_uint2(h2u(h0), h2u(h1));
    ((uint2*)lo)[i] = make_uint2(h2u(l0), h2u(l1));
}

// ---------------- mma / ldmatrix / cp.async wrappers ----------------
__device__ __forceinline__ void mma16816(float* c, const uint32_t* a, const uint32_t* b) {
    asm volatile(
        "mma.sync.aligned.m16n8k16.row.col.f32.f16.f16.f32 "
        "{%0,%1,%2,%3}, {%4,%5,%6,%7}, {%8,%9}, {%0,%1,%2,%3};\n"
        : "+f"(c[0]), "+f"(c[1]), "+f"(c[2]), "+f"(c[3])
        : "r"(a[0]), "r"(a[1]), "r"(a[2]), "r"(a[3]), "r"(b[0]), "r"(b[1]));
}
__device__ __forceinline__ void mma16816h(uint32_t* c, const uint32_t* a, const uint32_t* b) {
    asm volatile(
        "mma.sync.aligned.m16n8k16.row.col.f16.f16.f16.f16 "
        "{%0,%1}, {%2,%3,%4,%5}, {%6,%7}, {%0,%1};\n"
        : "+r"(c[0]), "+r"(c[1])
        : "r"(a[0]), "r"(a[1]), "r"(a[2]), "r"(a[3]), "r"(b[0]), "r"(b[1]));
}
__device__ __forceinline__ void ldsm4(uint32_t& r0, uint32_t& r1, uint32_t& r2, uint32_t& r3,
                                      uint32_t addr) {
    asm volatile("ldmatrix.sync.aligned.m8n8.x4.shared.b16 {%0,%1,%2,%3}, [%4];"
                 : "=r"(r0), "=r"(r1), "=r"(r2), "=r"(r3) : "r"(addr));
}
__device__ __forceinline__ uint32_t smem_u32(const void* p) {
    uint32_t a;
    asm("{ .reg .u64 t; cvta.to.shared.u64 t, %1; cvt.u32.u64 %0, t; }" : "=r"(a) : "l"(p));
    return a;
}
__device__ __forceinline__ void cp16(uint32_t saddr, const void* gptr) {
    asm volatile("cp.async.cg.shared.global [%0], [%1], 16;" :: "r"(saddr), "l"(gptr));
}
__device__ __forceinline__ void cp_commit() {
    asm volatile("cp.async.commit_group;" ::: "memory");
}
__device__ __forceinline__ void cp_wait1() {
    asm volatile("cp.async.wait_group 1;" ::: "memory");
}
__device__ __forceinline__ void cp_wait0() {
    asm volatile("cp.async.wait_group 0;" ::: "memory");
}

// ============ split-fp16 tensor-core GEMM: CTA 64x128, 8 warps 32x32 ============
// 3-stage cp.async ring, one __syncthreads per chunk.
// Chunk body: sync -> LDSM(ks0) -> MMA(ks0) -> refill cp.async -> LDSM(ks1) -> MMA(ks1).
#define PADE 40
#define OFF_AH 0
#define OFF_AL (64 * PADE)
#define OFF_BH (2 * 64 * PADE)
#define OFF_BL (2 * 64 * PADE + 128 * PADE)
#define BUFE (2 * 64 * PADE + 2 * 128 * PADE)
#define MMA_SMEM_BYTES (3 * BUFE * 2)

struct Frag {
    uint32_t ahf[2][4], alf[2][4], bhf[4][2], blf[4][2];
};

__device__ __forceinline__ void load_frags(Frag& f, uint32_t bb, int ks,
                                           int wm, int wn, int aro, int ako, int bro, int bko) {
#pragma unroll
    for (int am = 0; am < 2; am++) {
        uint32_t ar = (uint32_t)((wm + am * 16 + aro) * PADE + ks * 16 + ako) * 2;
        ldsm4(f.ahf[am][0], f.ahf[am][1], f.ahf[am][2], f.ahf[am][3], bb + OFF_AH * 2 + ar);
        ldsm4(f.alf[am][0], f.alf[am][1], f.alf[am][2], f.alf[am][3], bb + OFF_AL * 2 + ar);
    }
#pragma unroll
    for (int nb = 0; nb < 2; nb++) {
        uint32_t br = (uint32_t)((wn + nb * 16 + bro) * PADE + ks * 16 + bko) * 2;
        ldsm4(f.bhf[nb * 2][0], f.bhf[nb * 2][1], f.bhf[nb * 2 + 1][0], f.bhf[nb * 2 + 1][1],
              bb + OFF_BH * 2 + br);
        ldsm4(f.blf[nb * 2][0], f.blf[nb * 2][1], f.blf[nb * 2 + 1][0], f.blf[nb * 2 + 1][1],
              bb + OFF_BL * 2 + br);
    }
}

__device__ __forceinline__ void do_mmas(Frag& f, float acc[2][4][4], uint32_t corr[2][4][2]) {
#pragma unroll
    for (int am = 0; am < 2; am++)
#pragma unroll
        for (int bn = 0; bn < 4; bn++) {
            mma16816(acc[am][bn], f.ahf[am], f.bhf[bn]);
            mma16816h(corr[am][bn], f.alf[am], f.bhf[bn]);
            mma16816h(corr[am][bn], f.ahf[am], f.blf[bn]);
        }
}

__global__ __launch_bounds__(256, 2) void mma_gemm_kernel(
    const __half* __restrict__ Ah, const __half* __restrict__ Al,
    const __half* __restrict__ Bh, const __half* __restrict__ Bl,
    const float* __restrict__ bias, float* __restrict__ C,
    __half* __restrict__ Ch, __half* __restrict__ Cl,
    int M, int N, int K, int act, int osplit) {
    extern __shared__ __half smb[];
    const uint32_t sbase = smem_u32(smb);
    const int tid = threadIdx.x;
    const int wid = tid >> 5, lane = tid & 31;
    const int r4 = lane >> 2, lq = lane & 3;
    const int m0 = blockIdx.y * 64, n0 = blockIdx.x * 128;
    const int wm = (wid & 1) * 32, wn = (wid >> 1) * 32;

    const int aro = lane & 15, ako = (lane >> 4) << 3;
    const int bro = (lane & 7) + ((lane >> 4) << 3), bko = ((lane >> 3) & 1) << 3;

    float acc[2][4][4] = {};
    uint32_t corr[2][4][2] = {};
    const int nch = K >> 5;

    const int ld_r = tid >> 2, ld_q = tid & 3;
    const uint32_t ld_e = (uint32_t)(ld_r * PADE + ld_q * 8) * 2;

#pragma unroll
    for (int c = 0; c < 2; c++) {
        const int k0 = c << 5;
        const uint32_t bb = sbase + (uint32_t)((c % 3) * BUFE * 2);
        {
            size_t goA = (size_t)(m0 + ld_r) * K + k0 + ld_q * 8;
            cp16(bb + OFF_AH * 2 + ld_e, Ah + goA);
            cp16(bb + OFF_AL * 2 + ld_e, Al + goA);
        }
#pragma unroll
        for (int q = 0; q < 2; q++) {
            int r = ld_r + 64 * q;
            uint32_t e = ld_e + (uint32_t)(64 * q * PADE) * 2;
            size_t goB = (size_t)(n0 + r) * K + k0 + ld_q * 8;
            cp16(bb + OFF_BH * 2 + e, Bh + goB);
            cp16(bb + OFF_BL * 2 + e, Bl + goB);
        }
        cp_commit();
    }

    for (int c = 0; c < nch; c++) {
        if (c + 1 < nch) cp_wait1(); else cp_wait0();
        __syncthreads();
        const uint32_t bb = sbase + (uint32_t)((c % 3) * BUFE * 2);

        // ks = 0: LDSM then MMAs (tensor starts ASAP)
        Frag f;
        load_frags(f, bb, 0, wm, wn, aro, ako, bro, bko);
        do_mmas(f, acc, corr);

        // refill under ks0 MMA shadow
        if (c + 2 < nch) {
            const int k0 = (c + 2) << 5;
            const uint32_t nb = sbase + (uint32_t)(((c + 2) % 3) * BUFE * 2);
            {
                size_t goA = (size_t)(m0 + ld_r) * K + k0 + ld_q * 8;
                cp16(nb + OFF_AH * 2 + ld_e, Ah + goA);
                cp16(nb + OFF_AL * 2 + ld_e, Al + goA);
            }
#pragma unroll
            for (int q = 0; q < 2; q++) {
                int r = ld_r + 64 * q;
                uint32_t e = ld_e + (uint32_t)(64 * q * PADE) * 2;
                size_t goB = (size_t)(n0 + r) * K + k0 + ld_q * 8;
                cp16(nb + OFF_BH * 2 + e, Bh + goB);
                cp16(nb + OFF_BL * 2 + e, Bl + goB);
            }
            cp_commit();
        }

        // ks = 1
        load_frags(f, bb, 1, wm, wn, aro, ako, bro, bko);
        do_mmas(f, acc, corr);
    }

#pragma unroll
    for (int am = 0; am < 2; am++) {
        const int row = m0 + wm + am * 16 + r4;
#pragma unroll
        for (int bn = 0; bn < 4; bn++) {
            const int col = n0 + wn + bn * 8 + 2 * lq;
            const float b0 = bias[col], b1 = bias[col + 1];
            float2 c01 = __half22float2(*reinterpret_cast<__half2*>(&corr[am][bn][0]));
            float2 c23 = __half22float2(*reinterpret_cast<__half2*>(&corr[am][bn][1]));
            float v0 = acc[am][bn][0] + c01.x + b0, v1 = acc[am][bn][1] + c01.y + b1;
            float v2 = acc[am][bn][2] + c23.x + b0, v3 = acc[am][bn][3] + c23.y + b1;
            if (act) { v0 = mishf(v0); v1 = mishf(v1); v2 = mishf(v2); v3 = mishf(v3); }
            if (osplit) {
                __half2 h01, h23, l01, l23;
                h01.x = __float2half_rn(v0); h01.y = __float2half_rn(v1);
                h23.x = __float2half_rn(v2); h23.y = __float2half_rn(v3);
                l01.x = __float2half_rn(v0 - __half2float(h01.x));
                l01.y = __float2half_rn(v1 - __half2float(h01.y));
                l23.x = __float2half_rn(v2 - __half2float(h23.x));
                l23.y = __float2half_rn(v3 - __half2float(h23.y));
                *(uint32_t*)(Ch + (size_t)row * N + col) = h2u(h01);
                *(uint32_t*)(Cl + (size_t)row * N + col) = h2u(l01);
                *(uint32_t*)(Ch + (size_t)(row + 8) * N + col) = h2u(h23);
                *(uint32_t*)(Cl + (size_t)(row + 8) * N + col) = h2u(l23);
            } else {
                *(float2*)(C + (size_t)row * N + col) = make_float2(v0, v1);
                *(float2*)(C + (size_t)(row + 8) * N + col) = make_float2(v2, v3);
            }
        }
    }
}

// ============ split-K gather-GEMM for scan round k ============
__global__ __launch_bounds__(256, 2) void mma_ggemm_kernel(int kround) {
    extern __shared__ __half smb[];
    const int base = g_off[kround];
    const int R = g_off[kround + 1] - base;
    const int m0 = blockIdx.y * 64;
    if (m0 >= R) return;
    const uint32_t sbase = smem_u32(smb);
    const int tid = threadIdx.x;
    const int wid = tid >> 5, lane = tid & 31;
    const int r4 = lane >> 2, lq = lane & 3;
    const int n0 = blockIdx.x * 128;
    const int wm = (wid & 1) * 32, wn = (wid >> 1) * 32;
    const int K = HD, N = 3 * HD;
    const int sk = gridDim.z, z = blockIdx.z;

    const int aro = lane & 15, ako = (lane >> 4) << 3;
    const int bro = (lane & 7) + ((lane >> 4) << 3), bko = ((lane >> 3) & 1) << 3;

    float acc[2][4][4] = {};
    uint32_t corr[2][4][2] = {};
    const int nch_tot = K >> 5;
    const int cbeg = z * (nch_tot / sk);
    const int nch = nch_tot / sk;

    const int ld_r = tid >> 2, ld_q = tid & 3;
    const uint32_t ld_e = (uint32_t)(ld_r * PADE + ld_q * 8) * 2;
    const int gm = m0 + ld_r;
    const int myt = (gm < R) ? (g_order[base + gm] - 1) : (g_order[base] - 1);
    const __half* Ah = g_sth;
    const __half* Al = g_stl;
    const __half* Bh = g_whhh;
    const __half* Bl = g_whhl;
    float* hgout = g_hg[z];

#pragma unroll
    for (int c = 0; c < 2; c++) {
        const int k0 = (cbeg + c) << 5;
        const uint32_t bb = sbase + (uint32_t)((c % 3) * BUFE * 2);
        {
            size_t goA = (size_t)myt * K + k0 + ld_q * 8;
            cp16(bb + OFF_AH * 2 + ld_e, Ah + goA);
            cp16(bb + OFF_AL * 2 + ld_e, Al + goA);
        }
#pragma unroll
        for (int q = 0; q < 2; q++) {
            int r = ld_r + 64 * q;
            uint32_t e = ld_e + (uint32_t)(64 * q * PADE) * 2;
            size_t goB = (size_t)(n0 + r) * K + k0 + ld_q * 8;
            cp16(bb + OFF_BH * 2 + e, Bh + goB);
            cp16(bb + OFF_BL * 2 + e, Bl + goB);
        }
        cp_commit();
    }

    for (int c = 0; c < nch; c++) {
        if (c + 1 < nch) cp_wait1(); else cp_wait0();
        __syncthreads();
        const uint32_t bb = sbase + (uint32_t)((c % 3) * BUFE * 2);

        Frag f;
        load_frags(f, bb, 0, wm, wn, aro, ako, bro, bko);
        do_mmas(f, acc, corr);

        if (c + 2 < nch) {
            const int k0 = (cbeg + c + 2) << 5;
            const uint32_t nb = sbase + (uint32_t)(((c + 2) % 3) * BUFE * 2);
            {
                size_t goA = (size_t)myt * K + k0 + ld_q * 8;
                cp16(nb + OFF_AH * 2 + ld_e, Ah + goA);
                cp16(nb + OFF_AL * 2 + ld_e, Al + goA);
            }
#pragma unroll
            for (int q = 0; q < 2; q++) {
                int r = ld_r + 64 * q;
                uint32_t e = ld_e + (uint32_t)(64 * q * PADE) * 2;
                size_t goB = (size_t)(n0 + r) * K + k0 + ld_q * 8;
                cp16(nb + OFF_BH * 2 + e, Bh + goB);
                cp16(nb + OFF_BL * 2 + e, Bl + goB);
            }
            cp_commit();
        }

        load_frags(f, bb, 1, wm, wn, aro, ako, bro, bko);
        do_mmas(f, acc, corr);
    }

#pragma unroll
    for (int am = 0; am < 2; am++) {
        const int row = m0 + wm + am * 16 + r4;
#pragma unroll
        for (int bn = 0; bn < 4; bn++) {
            const int col = n0 + wn + bn * 8 + 2 * lq;
            float2 c01 = __half22float2(*reinterpret_cast<__half2*>(&corr[am][bn][0]));
            float2 c23 = __half22float2(*reinterpret_cast<__half2*>(&corr[am][bn][1]));
            if (row < R)
                *(float2*)(hgout + (size_t)row * N + col) =
                    make_float2(acc[am][bn][0] + c01.x, acc[am][bn][1] + c01.y);
            if (row + 8 < R)
                *(float2*)(hgout + (size_t)(row + 8) * N + col) =
                    make_float2(acc[am][bn][2] + c23.x, acc[am][bn][3] + c23.y);
        }
    }
}

__device__ __forceinline__ void store_state(int t, int j, float hnew, float* out) {
    g_states[(size_t)t * HD + j] = hnew;
    __half h = __float2half_rn(hnew);
    g_sth[(size_t)t * HD + j] = h;
    g_stl[(size_t)t * HD + j] = __float2half_rn(hnew - __half2float(h));
    if (t == T_STEPS - 1) out[(size_t)T_STEPS * ACTD + j] = hnew;
}

// pointwise gates for a GEMM round (sums sk split-K partials)
__global__ __launch_bounds__(256) void gate_kernel(const float* __restrict__ gbn,
                                                   float* __restrict__ out, int kround, int sk) {
    const int base = g_off[kround];
    const int R = g_off[kround + 1] - base;
    const int idx = blockIdx.x * blockDim.x + threadIdx.x;
    if (idx >= R * HD) return;
    const int m = idx >> 10, j = idx & (HD - 1);
    const int t = g_order[base + m];
    float hr = 0.f, hz = 0.f, hn = 0.f;
    for (int z = 0; z < sk; z++) {
        const float* hg = g_hg[z] + (size_t)m * (3 * HD);
        hr += hg[j]; hz += hg[HD + j]; hn += hg[2 * HD + j];
    }
    const float* igt = g_ig + (size_t)t * (3 * HD);
    float rv = sigmoidf_(igt[j] + hr);
    float uv = sigmoidf_(igt[HD + j] + hz);
    float nv = tanhf(igt[2 * HD + j] + rv * (hn + gbn[j]));
    float hin = g_states[(size_t)(t - 1) * HD + j];
    store_state(t, j, nv + uv * (hin - nv), out);
}

// ---------------- parallel p3 GEMM (N=16): 16 rows x 16 cols per block ----------------
__global__ __launch_bounds__(256) void sgemm_p3_kernel(
    const float* __restrict__ A, const float* __restrict__ B,
    const float* __restrict__ bias, float* __restrict__ C, int N, int K) {
    const int idx = threadIdx.x;
    const int r = blockIdx.x * 16 + (idx >> 4);
    const int c = idx & 15;
    const float* a = A + (size_t)r * K;
    const float* b = B + (size_t)c * K;
    float acc = 0.f;
#pragma unroll 8
    for (int k = 0; k < K; k += 4) {
        float4 av = *(const float4*)(a + k);
        float4 bv = *(const float4*)(b + k);
        acc = fmaf(av.x, bv.x, acc);
        acc = fmaf(av.y, bv.y, acc);
        acc = fmaf(av.z, bv.z, acc);
        acc = fmaf(av.w, bv.w, acc);
    }
    C[(size_t)r * N + c] = acc + bias[c];
}

// ---------------- prep: bucket timesteps by age within reset-segment ----------------
__global__ __launch_bounds__(1024) void prep_kernel(const int* __restrict__ start) {
    __shared__ int sa[2048], sb_[2048], sc[2048];
    __shared__ int skmax;
    const int tid = threadIdx.x;
    const int t0 = tid, t1 = tid + 1024;
    if (tid == 0) { g_bar = 0u; skmax = 0; }
    sa[t0] = start[t0] ? t0 : -1;
    sa[t1] = start[t1] ? t1 : -1;
    __syncthreads();
    int* src = sa; int* dst = sb_;
    for (int d = 1; d < 2048; d <<= 1) {
        int v0 = src[t0]; if (t0 >= d) v0 = max(v0, src[t0 - d]);
        int v1 = src[t1]; if (t1 >= d) v1 = max(v1, src[t1 - d]);
        dst[t0] = v0; dst[t1] = v1;
        __syncthreads();
        int* tmp = src; src = dst; dst = tmp;
    }
    int r0v = src[t0], r1v = src[t1];
    int age0 = (r0v < 0) ? t0 : t0 - r0v;
    int age1 = (r1v < 0) ? t1 : t1 - r1v;
    __syncthreads();
    sc[t0] = 0; sc[t1] = 0;
    __syncthreads();
    atomicAdd(&sc[age0], 1);
    atomicAdd(&sc[age1], 1);
    atomicMax(&skmax, max(age0, age1) + 1);
    __syncthreads();
    sa[t0] = sc[t0]; sa[t1] = sc[t1];
    __syncthreads();
    src = sa; dst = sb_;
    for (int d = 1; d < 2048; d <<= 1) {
        int v0 = src[t0]; if (t0 >= d) v0 += src[t0 - d];
        int v1 = src[t1]; if (t1 >= d) v1 += src[t1 - d];
        dst[t0] = v0; dst[t1] = v1;
        __syncthreads();
        int* tmp = src; src = dst; dst = tmp;
    }
    if (tid == 0) { g_off[0] = 0; g_kmax = skmax; }
    g_off[t0 + 1] = src[t0];
    g_off[t1 + 1] = src[t1];
    sc[t0] = 0; sc[t1] = 0;
    __syncthreads();
    int base0 = (age0 == 0) ? 0 : src[age0 - 1];
    g_order[base0 + atomicAdd(&sc[age0], 1)] = t0;
    int base1 = (age1 == 0) ? 0 : src[age1 - 1];
    g_order[base1 + atomicAdd(&sc[age1], 1)] = t1;
}

// ---------------- grid barrier ----------------
__device__ inline void grid_bar(unsigned* barp, unsigned target) {
    __syncthreads();
    if (threadIdx.x == 0) {
        asm volatile("red.release.gpu.global.add.u32 [%0], %1;" :: "l"(barp), "r"(1u) : "memory");
        unsigned v;
        do {
            asm volatile("ld.acquire.gpu.global.u32 %0, [%1];" : "=r"(v) : "l"(barp) : "memory");
        } while (v < target);
    }
    __syncthreads();
}

// ---------------- round 0: t=0 full matvec + start rows closed-form ----------------
__global__ __launch_bounds__(256, 1) void round0_kernel(
    const float* __restrict__ whh, const float* __restrict__ gbn,
    const int* __restrict__ start, const float* __restrict__ state,
    float* __restrict__ out) {
    __shared__ float sH[HD];
    const int tid = threadIdx.x;
    const int w = tid >> 5, lane = tid & 31;
    const int j = blockIdx.x * 8 + w;
    const float bnj = gbn[j];
    const int s0 = start[0];

    if (s0 == 0) {
        ((float4*)sH)[tid] = ((const float4*)state)[tid];
        __syncthreads();
        const float4* w4 = (const float4*)whh;
        float ir = 0.f, iz = 0.f, inn = 0.f;
        if (lane == 0) { ir = g_ig[j]; iz = g_ig[HD + j]; inn = g_ig[2 * HD + j]; }
        float aR = 0.f, aZ = 0.f, aN = 0.f;
#pragma unroll
        for (int q = 0; q < 8; q++) {
            float4 h4 = ((const float4*)sH)[lane + 32 * q];
            float4 r4v = w4[(size_t)(0 * HD + j) * 256 + lane + 32 * q];
            float4 z4v = w4[(size_t)(1 * HD + j) * 256 + lane + 32 * q];
            float4 n4v = w4[(size_t)(2 * HD + j) * 256 + lane + 32 * q];
            aR = fmaf(h4.x, r4v.x, fmaf(h4.y, r4v.y, fmaf(h4.z, r4v.z, fmaf(h4.w, r4v.w, aR))));
            aZ = fmaf(h4.x, z4v.x, fmaf(h4.y, z4v.y, fmaf(h4.z, z4v.z, fmaf(h4.w, z4v.w, aZ))));
            aN = fmaf(h4.x, n4v.x, fmaf(h4.y, n4v.y, fmaf(h4.z, n4v.z, fmaf(h4.w, n4v.w, aN))));
        }
#pragma unroll
        for (int off = 16; off; off >>= 1) {
            aR += __shfl_xor_sync(0xffffffffu, aR, off);
            aZ += __shfl_xor_sync(0xffffffffu, aZ, off);
            aN += __shfl_xor_sync(0xffffffffu, aN, off);
        }
        if (lane == 0) {
            float rv = sigmoidf_(ir + aR);
            float uv = sigmoidf_(iz + aZ);
            float nv = tanhf(inn + rv * (aN + bnj));
            float hin = sH[j];
            store_state(0, j, nv + uv * (hin - nv), out);
        }
    }
    {
        const int beg = g_off[0], end = g_off[1];
        for (int r = beg + lane; r < end; r += 32) {
            const int t = g_order[r];
            if (t == 0 && s0 == 0) continue;
            const float* igt = g_ig + (size_t)t * (3 * HD);
            float rv = sigmoidf_(igt[j]);
            float uv = sigmoidf_(igt[HD + j]);
            float nv = tanhf(igt[2 * HD + j] + rv * bnj);
            store_state(t, j, nv - uv * nv, out);
        }
    }
}

// ---------------- cleanup scan: rounds kstart..kmax (tiny tails), 4 rows/iter ----------------
__global__ __launch_bounds__(256, 1) void cleanup_scan_kernel(
    const float* __restrict__ whh, const float* __restrict__ gbn,
    float* __restrict__ out, int kstart) {
    __shared__ float sH[4][HD];
    const int tid = threadIdx.x;
    const int w = tid >> 5, lane = tid & 31;
    const int j = blockIdx.x * 8 + w;
    const int kmax = g_kmax;
    if (kstart >= kmax) return;

    const float4* w4 = (const float4*)whh;
    float4 wr[8], wz[8], wn[8];
#pragma unroll
    for (int q = 0; q < 8; q++) {
        wr[q] = w4[(size_t)(0 * HD + j) * 256 + lane + 32 * q];
        wz[q] = w4[(size_t)(1 * HD + j) * 256 + lane + 32 * q];
        wn[q] = w4[(size_t)(2 * HD + j) * 256 + lane + 32 * q];
    }
    const float bnj = gbn[j];
    unsigned* barp = &g_bar;
    unsigned epoch = 0;

    for (int k = kstart; k < kmax; k++) {
        const int beg = g_off[k], end = g_off[k + 1];
        int r = beg;
        int tt[4] = {-1, -1, -1, -1};
        float4 nx[4];
#pragma unroll
        for (int i = 0; i < 4; i++) {
            if (r + i < end) {
                tt[i] = g_order[r + i];
                nx[i] = __ldcg((const float4*)(g_states + (size_t)(tt[i] - 1) * HD) + tid);
            }
        }

        while (r < end) {
            int cur[4];
#pragma unroll
            for (int i = 0; i < 4; i++) cur[i] = tt[i];
            if (cur[0] >= 0) ((float4*)sH[0])[tid] = nx[0];
            if (cur[1] >= 0) ((float4*)sH[1])[tid] = nx[1];
            if (cur[2] >= 0) ((float4*)sH[2])[tid] = nx[2];
            if (cur[3] >= 0) ((float4*)sH[3])[tid] = nx[3];
            __syncthreads();

            const int rn = r + 4;
#pragma unroll
            for (int i = 0; i < 4; i++) {
                tt[i] = -1;
                if (rn + i < end) {
                    tt[i] = g_order[rn + i];
                    nx[i] = __ldcg((const float4*)(g_states + (size_t)(tt[i] - 1) * HD) + tid);
                }
            }

            float ir = 0.f, iz = 0.f, inn = 0.f;
            int myt = -1;
            if (lane < 4) {
                myt = cur[lane];
                if (myt >= 0) {
                    const float* igt = g_ig + (size_t)myt * (3 * HD);
                    ir = igt[j]; iz = igt[HD + j]; inn = igt[2 * HD + j];
                }
            }

            float aR[4] = {}, aZ[4] = {}, aN[4] = {};
#pragma unroll
            for (int q = 0; q < 8; q++) {
                const int c = lane + 32 * q;
                float4 r4v = wr[q], z4v = wz[q], n4v = wn[q];
#pragma unroll
                for (int i = 0; i < 4; i++) {
                    float4 h4 = ((const float4*)sH[i])[c];
                    aR[i] = fmaf(h4.x, r4v.x, fmaf(h4.y, r4v.y, fmaf(h4.z, r4v.z, fmaf(h4.w, r4v.w, aR[i]))));
                    aZ[i] = fmaf(h4.x, z4v.x, fmaf(h4.y, z4v.y, fmaf(h4.z, z4v.z, fmaf(h4.w, z4v.w, aZ[i]))));
                    aN[i] = fmaf(h4.x, n4v.x, fmaf(h4.y, n4v.y, fmaf(h4.z, n4v.z, fmaf(h4.w, n4v.w, aN[i]))));
                }
            }
#pragma unroll
            for (int off = 16; off; off >>= 1) {
#pragma unroll
                for (int i = 0; i < 4; i++) {
                    aR[i] += __shfl_xor_sync(0xffffffffu, aR[i], off);
                    aZ[i] += __shfl_xor_sync(0xffffffffu, aZ[i], off);
                    aN[i] += __shfl_xor_sync(0xffffffffu, aN[i], off);
                }
            }
            if (lane < 4 && myt >= 0) {
                float rv = sigmoidf_(ir + aR[lane]);
                float uv = sigmoidf_(iz + aZ[lane]);
                float nv = tanhf(inn + rv * (aN[lane] + bnj));
                float hin = sH[lane][j];
                store_state(myt, j, nv + uv * (hin - nv), out);
            }
            __syncthreads();
            r = rn;
        }
        grid_bar(barp, (++epoch) * SCAN_BLOCKS);
    }
}

// ---------------- launch ----------------
extern "C" void kernel_launch(void* const* d_in, const int* in_sizes, int n_in,
                              void* d_out, int out_size) {
    (void)in_sizes; (void)n_in;
    const float* x      = (const float*)d_in[0];
    const float* state  = (const float*)d_in[1];
    const int*   start  = (const int*)d_in[2];
    const float* pre_wm = (const float*)d_in[4];
    const float* pre_ws = (const float*)d_in[5];
    const float* pre_bm = (const float*)d_in[6];
    const float* pre_bs = (const float*)d_in[7];
    const float* wih    = (const float*)d_in[8];
    const float* whh    = (const float*)d_in[9];
    const float* gru_b  = (const float*)d_in[10];
    const float* gru_bn = (const float*)d_in[11];
    const float* p1_wm  = (const float*)d_in[12];
    const float* p1_ws  = (const float*)d_in[13];
    const float* p1_bm  = (const float*)d_in[14];
    const float* p1_bs  = (const float*)d_in[15];
    const float* p2_wm  = (const float*)d_in[16];
    const float* p2_ws  = (const float*)d_in[17];
    const float* p2_bm  = (const float*)d_in[18];
    const float* p2_bs  = (const float*)d_in[19];
    const float* p3_wm  = (const float*)d_in[20];
    const float* p3_ws  = (const float*)d_in[21];
    const float* p3_bm  = (const float*)d_in[22];
    const float* p3_bs  = (const float*)d_in[23];
    float* out = (float*)d_out;
    (void)out_size;

    unsigned nk[8][2];
    for (int i = 0; i < 8; i++) {
        unsigned a = 0u, b = (unsigned)i;
        tf_block(0u, 7u, a, b);
        nk[i][0] = a; nk[i][1] = b;
    }

    float *preB, *p1B, *p2B, *p3W, *p3B, *ig, *states, *y2;
    __half *xh, *xl, *preWh, *preWl, *wihh, *wihl, *whhh, *whhl, *p1Wh, *p1Wl, *p2Wh, *p2Wl;
    __half *zh, *zl, *sth, *stl, *y1h, *y1l;
    cudaGetSymbolAddress((void**)&preB, g_preB);
    cudaGetSymbolAddress((void**)&p1B, g_p1B);
    cudaGetSymbolAddress((void**)&p2B, g_p2B);
    cudaGetSymbolAddress((void**)&p3W, g_p3W);
    cudaGetSymbolAddress((void**)&p3B, g_p3B);
    cudaGetSymbolAddress((void**)&ig, g_ig);
    cudaGetSymbolAddress((void**)&states, g_states);
    cudaGetSymbolAddress((void**)&y2, g_y2);
    cudaGetSymbolAddress((void**)&xh, g_xh);
    cudaGetSymbolAddress((void**)&xl, g_xl);
    cudaGetSymbolAddress((void**)&preWh, g_preWh);
    cudaGetSymbolAddress((void**)&preWl, g_preWl);
    cudaGetSymbolAddress((void**)&wihh, g_wihh);
    cudaGetSymbolAddress((void**)&wihl, g_wihl);
    cudaGetSymbolAddress((void**)&whhh, g_whhh);
    cudaGetSymbolAddress((void**)&whhl, g_whhl);
    cudaGetSymbolAddress((void**)&p1Wh, g_p1Wh);
    cudaGetSymbolAddress((void**)&p1Wl, g_p1Wl);
    cudaGetSymbolAddress((void**)&p2Wh, g_p2Wh);
    cudaGetSymbolAddress((void**)&p2Wl, g_p2Wl);
    cudaGetSymbolAddress((void**)&zh, g_zh);
    cudaGetSymbolAddress((void**)&zl, g_zl);
    cudaGetSymbolAddress((void**)&sth, g_sth);
    cudaGetSymbolAddress((void**)&stl, g_stl);
    cudaGetSymbolAddress((void**)&y1h, g_y1h);
    cudaGetSymbolAddress((void**)&y1l, g_y1l);

    cudaFuncSetAttribute(mma_gemm_kernel, cudaFuncAttributeMaxDynamicSharedMemorySize,
                         MMA_SMEM_BYTES);
    cudaFuncSetAttribute(mma_ggemm_kernel, cudaFuncAttributeMaxDynamicSharedMemorySize,
                         MMA_SMEM_BYTES);

    static cudaStream_t sB = nullptr;
    static cudaEvent_t evFork, evPre, evWih, evWhh, evPrep, evP1, evP2;
    if (sB == nullptr) {
        cudaStreamCreateWithFlags(&sB, cudaStreamNonBlocking);
        cudaEventCreateWithFlags(&evFork, cudaEventDisableTiming);
        cudaEventCreateWithFlags(&evPre, cudaEventDisableTiming);
        cudaEventCreateWithFlags(&evWih, cudaEventDisableTiming);
        cudaEventCreateWithFlags(&evWhh, cudaEventDisableTiming);
        cudaEventCreateWithFlags(&evPrep, cudaEventDisableTiming);
        cudaEventCreateWithFlags(&evP1, cudaEventDisableTiming);
        cudaEventCreateWithFlags(&evP2, cudaEventDisableTiming);
    }

    cudaEventRecord(evFork, 0);
    cudaStreamWaitEvent(sB, evFork, 0);

    // main: x split
    conv_split_kernel<<<(T_STEPS * OBS / 4 + 255) / 256, 256>>>(x, xh, xl, T_STEPS * OBS / 4);
    // side: pre noise + small noise
    { int n = MLPD * OBS; gen_noisy_w_kernel<<<(n + 255) / 256, 256, 0, sB>>>(pre_wm, pre_ws, preWh, preWl, n, nk[0][0], nk[0][1]); }
    gen_small_kernel<<<(19472 + 255) / 256, 256, 0, sB>>>(
        p3_wm, p3_ws, p3W, nk[6][0], nk[6][1],
        pre_bm, pre_bs, preB, nk[1][0], nk[1][1],
        p1_bm, p1_bs, p1B, nk[3][0], nk[3][1],
        p2_bm, p2_bs, p2B, nk[5][0], nk[5][1],
        p3_bm, p3_bs, p3B, nk[7][0], nk[7][1]);
    cudaEventRecord(evPre, sB);

    // main: GEMM1
    cudaStreamWaitEvent(0, evPre, 0);
    mma_gemm_kernel<<<dim3(MLPD / 128, T_STEPS / 64), 256, MMA_SMEM_BYTES>>>(
        xh, xl, preWh, preWl, preB, nullptr, zh, zl, T_STEPS, MLPD, OBS, 1, 1);

    // side: wih split, whh split, prep (all overlap GEMM1/2)
    conv_split_kernel<<<(3 * HD * MLPD / 4 + 255) / 256, 256, 0, sB>>>(wih, wihh, wihl, 3 * HD * MLPD / 4);
    cudaEventRecord(evWih, sB);
    conv_split_kernel<<<(3 * HD * MLPD / 4 + 255) / 256, 256, 0, sB>>>(whh, whhh, whhl, 3 * HD * MLPD / 4);
    cudaEventRecord(evWhh, sB);
    prep_kernel<<<1, 1024, 0, sB>>>(start);
    cudaEventRecord(evPrep, sB);

    // main: GEMM2
    cudaStreamWaitEvent(0, evWih, 0);
    mma_gemm_kernel<<<dim3(3 * HD / 128, T_STEPS / 64), 256, MMA_SMEM_BYTES>>>(
        zh, zl, wihh, wihl, gru_b, ig, nullptr, nullptr, T_STEPS, 3 * HD, MLPD, 0, 0);

    // side: p1/p2 noise (overlaps GEMM2 + scan rounds)
    { int n = MLPD * HD;   gen_noisy_w_kernel<<<(n + 255) / 256, 256, 0, sB>>>(p1_wm, p1_ws, p1Wh, p1Wl, n, nk[2][0], nk[2][1]); }
    cudaEventRecord(evP1, sB);
    { int n = MLPD * MLPD; gen_noisy_w_kernel<<<(n + 255) / 256, 256, 0, sB>>>(p2_wm, p2_ws, p2Wh, p2Wl, n, nk[4][0], nk[4][1]); }
    cudaEventRecord(evP2, sB);

    // main: round 0
    cudaStreamWaitEvent(0, evPrep, 0);
    round0_kernel<<<SCAN_BLOCKS, 256>>>(whh, gru_bn, start, state, out);

    // main: split-K GEMM rounds 1..KGEMM
    cudaStreamWaitEvent(0, evWhh, 0);
    {
        const int ymax[KGEMM + 1] = {0, 16, 11, 8, 7};
        const int skv[KGEMM + 1]  = {0, 2, 4, 4, 4};
        const int rbnd[KGEMM + 1] = {0, 1024, 683, 512, 410};
        for (int k = 1; k <= KGEMM; k++) {
            mma_ggemm_kernel<<<dim3(3 * HD / 128, ymax[k], skv[k]), 256, MMA_SMEM_BYTES>>>(k);
            gate_kernel<<<(rbnd[k] * HD + 255) / 256, 256>>>(gru_bn, out, k, skv[k]);
        }
    }

    // main: cleanup scan for rounds > KGEMM
    cleanup_scan_kernel<<<SCAN_BLOCKS, 256>>>(whh, gru_bn, out, KGEMM + 1);

    // main: GEMM3
    cudaStreamWaitEvent(0, evP1, 0);
    mma_gemm_kernel<<<dim3(MLPD / 128, T_STEPS / 64), 256, MMA_SMEM_BYTES>>>(
        sth, stl, p1Wh, p1Wl, p1B, nullptr, y1h, y1l, T_STEPS, MLPD, HD, 1, 1);

    // main: GEMM4
    cudaStreamWaitEvent(0, evP2, 0);
    mma_gemm_kernel<<<dim3(MLPD / 128, T_STEPS / 64), 256, MMA_SMEM_BYTES>>>(
        y1h, y1l, p2Wh, p2Wl, p2B, y2, nullptr, nullptr, T_STEPS, MLPD, MLPD, 1, 0);

    // main: final layer -> d_out[0 : 2048*16]  (128 blocks, 1 output/thread)
    sgemm_p3_kernel<<<T_STEPS / 16, 256>>>(y2, p3W, p3B, out, ACTD, MLPD);
}